// round 9
// baseline (speedup 1.0000x reference)
#include <cuda_runtime.h>
#include <cuda_bf16.h>
#include <cstdint>
#include <cstddef>

#define BB 4
#define SS 512
#define EE 512
#define HIDD 2048
#define HH 8
#define DD 64
#define RFULL 201
#define RUSE 101
#define MR (BB*SS)   // 2048

// ---------------- fp32 scratch ----------------------------------------------
__device__ __align__(128) float g_q [MR*EE];
__device__ __align__(128) float g_ke[MR*EE];
__device__ __align__(128) float g_krt[RFULL*EE];
__device__ __align__(128) float g_t1[RFULL*HH];
__device__ __align__(128) float g_b0t[MR*HH];
__device__ __align__(128) float g_P[(size_t)MR*HH*RUSE];
__device__ __align__(128) float g_L[(size_t)BB*HH*SS*SS];
__device__ __align__(128) float g_v [MR*EE];

// ---------------- bf16 split scratch ----------------------------------------
__device__ __align__(128) __nv_bfloat16 g_xnh[MR*EE],   g_xnl[MR*EE];
__device__ __align__(128) __nv_bfloat16 g_xh [MR*HIDD], g_xl [MR*HIDD];
__device__ __align__(128) __nv_bfloat16 g_vnh[MR*EE],   g_vnl[MR*EE];
__device__ __align__(128) __nv_bfloat16 g_h1h[MR*HIDD], g_h1l[MR*HIDD];
__device__ __align__(128) __nv_bfloat16 g_reh[RFULL*EE + 64], g_rel_[RFULL*EE + 64];
__device__ __align__(128) __nv_bfloat16 g_qh [MR*EE], g_ql [MR*EE];
__device__ __align__(128) __nv_bfloat16 g_keh[MR*EE], g_kel[MR*EE];
__device__ __align__(128) __nv_bfloat16 g_kvh[MR*EE], g_kvl[MR*EE];
__device__ __align__(128) __nv_bfloat16 g_Sh[(size_t)BB*HH*SS*SS];
__device__ __align__(128) __nv_bfloat16 g_Sl[(size_t)BB*HH*SS*SS];
// weights, transposed to [N][K] and split; q/ke/kv concatenated to [1536][2048]
__device__ __align__(128) __nv_bfloat16 g_wb0h[HIDD*EE],    g_wb0l[HIDD*EE];
__device__ __align__(128) __nv_bfloat16 g_wqkvh[3*EE*HIDD], g_wqkvl[3*EE*HIDD];
__device__ __align__(128) __nv_bfloat16 g_wkrh[EE*EE],      g_wkrl[EE*EE];
__device__ __align__(128) __nv_bfloat16 g_w11h[HIDD*EE],    g_w11l[HIDD*EE];
__device__ __align__(128) __nv_bfloat16 g_w12h[EE*HIDD],    g_w12l[EE*HIDD];

// ---------------- PTX helpers -----------------------------------------------
__device__ __forceinline__ uint32_t s2u(const void* p){
    uint32_t a;
    asm("{ .reg .u64 t; cvta.to.shared.u64 t, %1; cvt.u32.u64 %0, t; }" : "=r"(a) : "l"(p));
    return a;
}
__device__ __forceinline__ void cpa16(uint32_t dst, const void* src, uint32_t sz){
    asm volatile("cp.async.cg.shared.global [%0], [%1], 16, %2;" :: "r"(dst), "l"(src), "r"(sz));
}
__device__ __forceinline__ void cpcommit(){ asm volatile("cp.async.commit_group;" ::: "memory"); }
__device__ __forceinline__ void cpwait0(){ asm volatile("cp.async.wait_group 0;" ::: "memory"); }
__device__ __forceinline__ void cpwait1(){ asm volatile("cp.async.wait_group 1;" ::: "memory"); }

__device__ __forceinline__ void ldsm4(uint32_t* r, uint32_t addr){
    asm volatile("ldmatrix.sync.aligned.m8n8.x4.shared.b16 {%0,%1,%2,%3}, [%4];"
        : "=r"(r[0]), "=r"(r[1]), "=r"(r[2]), "=r"(r[3]) : "r"(addr));
}
__device__ __forceinline__ void ldsm4t(uint32_t* r, uint32_t addr){
    asm volatile("ldmatrix.sync.aligned.m8n8.x4.trans.shared.b16 {%0,%1,%2,%3}, [%4];"
        : "=r"(r[0]), "=r"(r[1]), "=r"(r[2]), "=r"(r[3]) : "r"(addr));
}
__device__ __forceinline__ void mma16816(float* d, const uint32_t* a, const uint32_t* b){
    asm volatile("mma.sync.aligned.m16n8k16.row.col.f32.bf16.bf16.f32 "
        "{%0,%1,%2,%3}, {%4,%5,%6,%7}, {%8,%9}, {%0,%1,%2,%3};"
        : "+f"(d[0]), "+f"(d[1]), "+f"(d[2]), "+f"(d[3])
        : "r"(a[0]), "r"(a[1]), "r"(a[2]), "r"(a[3]), "r"(b[0]), "r"(b[1]));
}

// GEMM geometry: k-chunk 32, rows padded to 40 bf16 (80 B)
#define KC 32
#define GSTR 40
#define GROWB 80
#define TILE_B (128*GROWB)               // 10240
#define STAGE_B (4*TILE_B)               // 40960
#define GSMEM_BYTES (2*STAGE_B)          // 81920 -> 2 CTAs/SM

// attention tiles: 64x64 bf16, stride 72 (144 B rows)
#define ASTR 72
#define AROWB 144
#define ATILE_B (64*AROWB)               // 9216
#define ASTAGE_B (4*ATILE_B)             // 36864
#define ATT_SMEM (2*ASTAGE_B)            // 73728

// ---------------- GEMM chunk loader (128x128, KC=32) -------------------------
__device__ __forceinline__ void load_chunk(uint32_t stage, int tid,
    const __nv_bfloat16* __restrict__ Ah, const __nv_bfloat16* __restrict__ Al,
    const __nv_bfloat16* __restrict__ Bh, const __nv_bfloat16* __restrict__ Bl,
    int m0, int n0, int k0, int M, int K)
{
    #pragma unroll
    for (int t = 0; t < 4; t++){
        const __nv_bfloat16* g = (t==0)?Ah:(t==1)?Al:(t==2)?Bh:Bl;
        int row0 = (t < 2) ? m0 : n0;
        uint32_t tb = stage + t*TILE_B;
        #pragma unroll
        for (int i = 0; i < 2; i++){
            int s = i*256 + tid;           // 0..511
            int r = s >> 2, seg = s & 3;
            int gr = row0 + r;
            uint32_t sz = 16u;
            if (t < 2 && gr >= M){ sz = 0u; gr = M - 1; }
            cpa16(tb + (uint32_t)(r*GROWB + seg*16),
                  g + (size_t)gr*K + k0 + seg*8, sz);
        }
    }
    cpcommit();
}

// ---------------- 128x128 mainloop, 2 CTAs/SM --------------------------------
__device__ __forceinline__ void mainloop128(uint32_t sb, int tid, int lane, int warp,
    const __nv_bfloat16* Ah, const __nv_bfloat16* Al,
    const __nv_bfloat16* Bh, const __nv_bfloat16* Bl,
    int m0, int n0, int M, int K, float acc[4][4][4])
{
    int a_row  = (warp >> 2)*64 + (lane & 15);
    int a_col8 = (lane >> 4)*8;
    int b_row  = (warp & 3)*32 + (lane & 7) + ((lane & 16) ? 8 : 0);
    int b_col8 = ((lane & 8) ? 8 : 0);

    const int NC = K / KC;
    uint32_t st0 = sb, st1 = sb + STAGE_B;
    load_chunk(st0, tid, Ah, Al, Bh, Bl, m0, n0, 0, M, K);

    for (int c = 0; c < NC; c++){
        uint32_t cur = (c & 1) ? st1 : st0;
        if (c + 1 < NC)
            load_chunk((c & 1) ? st0 : st1, tid, Ah, Al, Bh, Bl, m0, n0, (c+1)*KC, M, K);
        if (c + 1 < NC) cpwait1(); else cpwait0();
        __syncthreads();

        uint32_t cAh = cur, cAl = cur + TILE_B, cBh = cur + 2*TILE_B, cBl = cur + 3*TILE_B;
        #pragma unroll
        for (int ks = 0; ks < 2; ks++){
            int k0 = ks*16;
            // staged fragment loads to cap register peak (~112):
            uint32_t ah[4][4], bx[2][4];
            #pragma unroll
            for (int mt = 0; mt < 4; mt++){
                uint32_t off = (uint32_t)((a_row + mt*16)*GSTR + k0 + a_col8)*2u;
                ldsm4(ah[mt], cAh + off);
            }
            #pragma unroll
            for (int p = 0; p < 2; p++){
                uint32_t off = (uint32_t)((b_row + p*16)*GSTR + k0 + b_col8)*2u;
                ldsm4(bx[p], cBh + off);
            }
            // pass 1: Ah*Bh
            #pragma unroll
            for (int mt = 0; mt < 4; mt++)
                #pragma unroll
                for (int nt = 0; nt < 4; nt++)
                    mma16816(acc[mt][nt], ah[mt], &bx[nt >> 1][(nt & 1)*2]);
            // pass 3 uses Bh too: load Al now, keep bx
            uint32_t al[4][4];
            #pragma unroll
            for (int mt = 0; mt < 4; mt++){
                uint32_t off = (uint32_t)((a_row + mt*16)*GSTR + k0 + a_col8)*2u;
                ldsm4(al[mt], cAl + off);
            }
            #pragma unroll
            for (int mt = 0; mt < 4; mt++)
                #pragma unroll
                for (int nt = 0; nt < 4; nt++)
                    mma16816(acc[mt][nt], al[mt], &bx[nt >> 1][(nt & 1)*2]);
            // pass 2: Ah*Bl — overwrite bx with Bl
            #pragma unroll
            for (int p = 0; p < 2; p++){
                uint32_t off = (uint32_t)((b_row + p*16)*GSTR + k0 + b_col8)*2u;
                ldsm4(bx[p], cBl + off);
            }
            #pragma unroll
            for (int mt = 0; mt < 4; mt++)
                #pragma unroll
                for (int nt = 0; nt < 4; nt++)
                    mma16816(acc[mt][nt], ah[mt], &bx[nt >> 1][(nt & 1)*2]);
        }
        __syncthreads();
    }
}

// EPI: 0 fp32+bias, 1 relu -> bf16 hi/lo, 2 fp32+bias+res
template<int EPI>
__global__ __launch_bounds__(256, 2)
void gemm128(const __nv_bfloat16* Ah, const __nv_bfloat16* Al,
             const __nv_bfloat16* Bh, const __nv_bfloat16* Bl,
             const float* __restrict__ bias, const float* __restrict__ res,
             float* __restrict__ Cf, __nv_bfloat16* __restrict__ Ch, __nv_bfloat16* __restrict__ Cl,
             int M, int N, int K)
{
    extern __shared__ char smem[];
    uint32_t sb = s2u(smem);
    int tid = threadIdx.x, lane = tid & 31, warp = tid >> 5;
    int m0 = blockIdx.y*128, n0 = blockIdx.x*128;
    float acc[4][4][4];
    #pragma unroll
    for (int a = 0; a < 4; a++)
        #pragma unroll
        for (int b = 0; b < 4; b++)
            #pragma unroll
            for (int c = 0; c < 4; c++) acc[a][b][c] = 0.f;

    mainloop128(sb, tid, lane, warp, Ah, Al, Bh, Bl, m0, n0, M, K, acc);

    int g = lane >> 2, tig = lane & 3;
    int wm = warp >> 2, wn = warp & 3;
    #pragma unroll
    for (int mt = 0; mt < 4; mt++)
        #pragma unroll
        for (int half = 0; half < 2; half++){
            int row = m0 + wm*64 + mt*16 + g + half*8;
            if (row >= M) continue;
            #pragma unroll
            for (int nt = 0; nt < 4; nt++){
                int col = n0 + wn*32 + nt*8 + tig*2;
                float v0 = acc[mt][nt][half*2 + 0] + bias[col];
                float v1 = acc[mt][nt][half*2 + 1] + bias[col + 1];
                size_t o = (size_t)row*N + col;
                if (EPI == 1){
                    v0 = fmaxf(v0, 0.f); v1 = fmaxf(v1, 0.f);
                    __nv_bfloat16 h0 = __float2bfloat16_rn(v0);
                    __nv_bfloat16 h1 = __float2bfloat16_rn(v1);
                    __nv_bfloat16 l0 = __float2bfloat16_rn(v0 - __bfloat162float(h0));
                    __nv_bfloat16 l1 = __float2bfloat16_rn(v1 - __bfloat162float(h1));
                    *(uint32_t*)((char*)Ch + o*2) =
                        (uint32_t)__bfloat16_as_ushort(h0) | ((uint32_t)__bfloat16_as_ushort(h1) << 16);
                    *(uint32_t*)((char*)Cl + o*2) =
                        (uint32_t)__bfloat16_as_ushort(l0) | ((uint32_t)__bfloat16_as_ushort(l1) << 16);
                } else {
                    if (EPI == 2){
                        float2 rv = *(const float2*)&res[o];
                        v0 += rv.x; v1 += rv.y;
                    }
                    *(float2*)&Cf[o] = make_float2(v0, v1);
                }
            }
        }
}

// merged qkv (B = [1536][2048]); route outputs by n0>>9
__global__ __launch_bounds__(256, 2)
void gemm_qkv(const __nv_bfloat16* Ah, const __nv_bfloat16* Al,
              const __nv_bfloat16* Bh, const __nv_bfloat16* Bl,
              const float* b0, const float* b1, const float* b2,
              float* f0, float* f1,
              __nv_bfloat16* c0h, __nv_bfloat16* c0l,
              __nv_bfloat16* c1h, __nv_bfloat16* c1l,
              __nv_bfloat16* c2h, __nv_bfloat16* c2l,
              int M, int K)
{
    extern __shared__ char smem[];
    uint32_t sb = s2u(smem);
    int tid = threadIdx.x, lane = tid & 31, warp = tid >> 5;
    int m0 = blockIdx.y*128, n0 = blockIdx.x*128;
    float acc[4][4][4];
    #pragma unroll
    for (int a = 0; a < 4; a++)
        #pragma unroll
        for (int b = 0; b < 4; b++)
            #pragma unroll
            for (int c = 0; c < 4; c++) acc[a][b][c] = 0.f;

    mainloop128(sb, tid, lane, warp, Ah, Al, Bh, Bl, m0, n0, M, K, acc);

    int z = n0 >> 9;
    const float* bias = (z==0)?b0:(z==1)?b1:b2;
    float* Cf = (z==0)?f0:(z==1)?f1:nullptr;
    __nv_bfloat16* Ch = (z==0)?c0h:(z==1)?c1h:c2h;
    __nv_bfloat16* Cl = (z==0)?c0l:(z==1)?c1l:c2l;
    int n0l = n0 & 511;

    int g = lane >> 2, tig = lane & 3;
    int wm = warp >> 2, wn = warp & 3;
    #pragma unroll
    for (int mt = 0; mt < 4; mt++)
        #pragma unroll
        for (int half = 0; half < 2; half++){
            int row = m0 + wm*64 + mt*16 + g + half*8;
            #pragma unroll
            for (int nt = 0; nt < 4; nt++){
                int col = n0l + wn*32 + nt*8 + tig*2;
                float v0 = acc[mt][nt][half*2 + 0] + bias[col];
                float v1 = acc[mt][nt][half*2 + 1] + bias[col + 1];
                size_t o = (size_t)row*512 + col;
                if (Cf) *(float2*)&Cf[o] = make_float2(v0, v1);
                __nv_bfloat16 h0 = __float2bfloat16_rn(v0);
                __nv_bfloat16 h1 = __float2bfloat16_rn(v1);
                __nv_bfloat16 l0 = __float2bfloat16_rn(v0 - __bfloat162float(h0));
                __nv_bfloat16 l1 = __float2bfloat16_rn(v1 - __bfloat162float(h1));
                *(uint32_t*)((char*)Ch + o*2) =
                    (uint32_t)__bfloat16_as_ushort(h0) | ((uint32_t)__bfloat16_as_ushort(h1) << 16);
                *(uint32_t*)((char*)Cl + o*2) =
                    (uint32_t)__bfloat16_as_ushort(l0) | ((uint32_t)__bfloat16_as_ushort(l1) << 16);
            }
        }
}

// ---------------- logits via mma: causal 64x64 tiles ------------------------
__global__ __launch_bounds__(128) void logits_mma(
    const __nv_bfloat16* __restrict__ qh, const __nv_bfloat16* __restrict__ ql,
    const __nv_bfloat16* __restrict__ keh, const __nv_bfloat16* __restrict__ kel,
    const float* __restrict__ P, const float* __restrict__ b0t,
    float* __restrict__ L)
{
    __shared__ char lsm[ASTAGE_B];
    uint32_t sb = s2u(lsm);
    int tid = threadIdx.x, lane = tid & 31, warp = tid >> 5;
    int tri = blockIdx.x;
    int it = 0;
    while ((it + 1)*(it + 2)/2 <= tri) it++;
    int jt = tri - it*(it + 1)/2;
    int bh = blockIdx.y, b = bh >> 3, h = bh & 7;
    int i0 = it*64, j0 = jt*64;

    #pragma unroll
    for (int t = 0; t < 4; t++){
        const __nv_bfloat16* g = (t==0)?qh:(t==1)?ql:(t==2)?keh:kel;
        int row0 = (t < 2) ? i0 : j0;
        uint32_t tb = sb + t*ATILE_B;
        #pragma unroll
        for (int i = 0; i < 4; i++){
            int s = i*128 + tid;
            int r = s >> 3, seg = s & 7;
            cpa16(tb + (uint32_t)(r*AROWB + seg*16),
                  g + ((size_t)(b*SS + row0 + r))*EE + h*DD + seg*8, 16u);
        }
    }
    cpcommit(); cpwait0();
    __syncthreads();

    int wm = warp >> 1, wn = warp & 1;
    int a_row  = wm*32 + (lane & 15);
    int a_col8 = (lane >> 4)*8;
    int b_row  = wn*32 + (lane & 7) + ((lane & 16) ? 8 : 0);
    int b_col8 = ((lane & 8) ? 8 : 0);

    uint32_t cAh = sb, cAl = sb + ATILE_B, cBh = sb + 2*ATILE_B, cBl = sb + 3*ATILE_B;
    float acc[2][4][4];
    #pragma unroll
    for (int a = 0; a < 2; a++)
        #pragma unroll
        for (int bb2 = 0; bb2 < 4; bb2++)
            #pragma unroll
            for (int c = 0; c < 4; c++) acc[a][bb2][c] = 0.f;

    #pragma unroll
    for (int ks = 0; ks < 4; ks++){
        int k0 = ks*16;
        uint32_t ah[2][4], al[2][4], bhf[2][4], blf[2][4];
        #pragma unroll
        for (int mt = 0; mt < 2; mt++){
            uint32_t off = (uint32_t)((a_row + mt*16)*ASTR + k0 + a_col8)*2u;
            ldsm4(ah[mt], cAh + off);
            ldsm4(al[mt], cAl + off);
        }
        #pragma unroll
        for (int p = 0; p < 2; p++){
            uint32_t off = (uint32_t)((b_row + p*16)*ASTR + k0 + b_col8)*2u;
            ldsm4(bhf[p], cBh + off);
            ldsm4(blf[p], cBl + off);
        }
        #pragma unroll
        for (int mt = 0; mt < 2; mt++)
            #pragma unroll
            for (int nt = 0; nt < 4; nt++)
                mma16816(acc[mt][nt], ah[mt], &bhf[nt >> 1][(nt & 1)*2]);
        #pragma unroll
        for (int mt = 0; mt < 2; mt++)
            #pragma unroll
            for (int nt = 0; nt < 4; nt++)
                mma16816(acc[mt][nt], ah[mt], &blf[nt >> 1][(nt & 1)*2]);
        #pragma unroll
        for (int mt = 0; mt < 2; mt++)
            #pragma unroll
            for (int nt = 0; nt < 4; nt++)
                mma16816(acc[mt][nt], al[mt], &bhf[nt >> 1][(nt & 1)*2]);
    }

    int g = lane >> 2, tig = lane & 3;
    #pragma unroll
    for (int mt = 0; mt < 2; mt++)
        #pragma unroll
        for (int half = 0; half < 2; half++){
            int gi = i0 + wm*32 + mt*16 + g + half*8;
            const float* Pr = P + ((size_t)(b*SS + gi)*HH + h)*RUSE;
            float* Lr = L + ((size_t)bh*SS + gi)*SS;
            #pragma unroll
            for (int nt = 0; nt < 4; nt++){
                int gj = j0 + wn*32 + nt*8 + tig*2;
                #pragma unroll
                for (int e = 0; e < 2; e++){
                    int j = gj + e;
                    if (j > gi) continue;
                    int off = j - gi;
                    if (off < -100) off = -100;
                    Lr[j] = acc[mt][nt][half*2 + e]*0.125f + Pr[off + 100]
                          + b0t[(size_t)(b*SS + j)*HH + h];
                }
            }
        }
}

// ---------------- softmax: fp32 in, bf16 hi/lo out --------------------------
__global__ void softmax_kernel(const float* __restrict__ L,
                               __nv_bfloat16* __restrict__ Ph,
                               __nv_bfloat16* __restrict__ Pl)
{
    int i = blockIdx.x;
    size_t ro = ((size_t)blockIdx.y*SS + i)*SS;
    const float* row = L + ro;
    int n = i + 1;
    int tid = threadIdx.x;
    float v[4];
    float mx = -1e30f;
    #pragma unroll
    for (int l = 0; l < 4; l++){
        int j = tid + l*128;
        v[l] = (j < n) ? row[j] : -1e30f;
        mx = fmaxf(mx, v[l]);
    }
    #pragma unroll
    for (int o = 16; o > 0; o >>= 1) mx = fmaxf(mx, __shfl_xor_sync(0xffffffffu, mx, o));
    __shared__ float smx[4], ssum[4];
    if ((tid & 31) == 0) smx[tid>>5] = mx;
    __syncthreads();
    mx = fmaxf(fmaxf(smx[0], smx[1]), fmaxf(smx[2], smx[3]));
    float s = 0.f;
    #pragma unroll
    for (int l = 0; l < 4; l++){
        int j = tid + l*128;
        if (j < n){ v[l] = __expf(v[l] - mx); s += v[l]; } else v[l] = 0.f;
    }
    #pragma unroll
    for (int o = 16; o > 0; o >>= 1) s += __shfl_xor_sync(0xffffffffu, s, o);
    if ((tid & 31) == 0) ssum[tid>>5] = s;
    __syncthreads();
    s = ssum[0] + ssum[1] + ssum[2] + ssum[3];
    float inv = 1.f / s;
    #pragma unroll
    for (int l = 0; l < 4; l++){
        int j = tid + l*128;
        float p = (j < n) ? v[l]*inv : 0.f;
        __nv_bfloat16 h = __float2bfloat16_rn(p);
        Ph[ro + j] = h;
        Pl[ro + j] = __float2bfloat16_rn(p - __bfloat162float(h));
    }
}

// ---------------- att via mma ------------------------------------------------
__device__ __forceinline__ void load_att_chunk(uint32_t stage, int tid,
    const __nv_bfloat16* __restrict__ Ph, const __nv_bfloat16* __restrict__ Pl,
    const __nv_bfloat16* __restrict__ kvh, const __nv_bfloat16* __restrict__ kvl,
    int bh, int b, int h, int i0, int jt)
{
    int j0 = jt*64;
    #pragma unroll
    for (int t = 0; t < 2; t++){
        const __nv_bfloat16* g = t ? Pl : Ph;
        uint32_t tb = stage + t*ATILE_B;
        #pragma unroll
        for (int i = 0; i < 4; i++){
            int s = i*128 + tid;
            int r = s >> 3, seg = s & 7;
            cpa16(tb + (uint32_t)(r*AROWB + seg*16),
                  g + ((size_t)bh*SS + i0 + r)*SS + j0 + seg*8, 16u);
        }
    }
    #pragma unroll
    for (int t = 0; t < 2; t++){
        const __nv_bfloat16* g = t ? kvl : kvh;
        uint32_t tb = stage + (2 + t)*ATILE_B;
        #pragma unroll
        for (int i = 0; i < 4; i++){
            int s = i*128 + tid;
            int r = s >> 3, seg = s & 7;
            cpa16(tb + (uint32_t)(r*AROWB + seg*16),
                  g + ((size_t)(b*SS + j0 + r))*EE + h*DD + seg*8, 16u);
        }
    }
    cpcommit();
}

__global__ __launch_bounds__(128) void att_mma(
    const __nv_bfloat16* __restrict__ Ph, const __nv_bfloat16* __restrict__ Pl,
    const __nv_bfloat16* __restrict__ kvh, const __nv_bfloat16* __restrict__ kvl,
    const float* __restrict__ vals, float* __restrict__ V)
{
    extern __shared__ char smem[];
    uint32_t sb = s2u(smem);
    int tid = threadIdx.x, lane = tid & 31, warp = tid >> 5;
    int it = blockIdx.x, bh = blockIdx.y, b = bh >> 3, h = bh & 7;
    int i0 = it*64;
    int NCH = it + 1;

    int wm = warp >> 1, wn = warp & 1;
    int a_row  = wm*32 + (lane & 15);
    int a_col8 = (lane >> 4)*8;
    int bt_row = lane & 15;
    int bt_col = wn*32 + ((lane & 16) ? 8 : 0);

    float acc[2][4][4];
    #pragma unroll
    for (int a = 0; a < 2; a++)
        #pragma unroll
        for (int bb2 = 0; bb2 < 4; bb2++)
            #pragma unroll
            for (int c = 0; c < 4; c++) acc[a][bb2][c] = 0.f;

    uint32_t st0 = sb, st1 = sb + ASTAGE_B;
    load_att_chunk(st0, tid, Ph, Pl, kvh, kvl, bh, b, h, i0, 0);

    for (int c = 0; c < NCH; c++){
        uint32_t cur = (c & 1) ? st1 : st0;
        if (c + 1 < NCH)
            load_att_chunk((c & 1) ? st0 : st1, tid, Ph, Pl, kvh, kvl, bh, b, h, i0, c + 1);
        if (c + 1 < NCH) cpwait1(); else cpwait0();
        __syncthreads();

        uint32_t cSh = cur, cSl = cur + ATILE_B, cKh = cur + 2*ATILE_B, cKl = cur + 3*ATILE_B;
        #pragma unroll
        for (int ks = 0; ks < 4; ks++){
            int k0 = ks*16;
            uint32_t ah[2][4], al[2][4], bhf[2][4], blf[2][4];
            #pragma unroll
            for (int mt = 0; mt < 2; mt++){
                uint32_t off = (uint32_t)((a_row + mt*16)*ASTR + k0 + a_col8)*2u;
                ldsm4(ah[mt], cSh + off);
                ldsm4(al[mt], cSl + off);
            }
            #pragma unroll
            for (int grp = 0; grp < 2; grp++){
                uint32_t off = (uint32_t)((k0 + bt_row)*ASTR + bt_col + grp*16)*2u;
                ldsm4t(bhf[grp], cKh + off);
                ldsm4t(blf[grp], cKl + off);
            }
            #pragma unroll
            for (int mt = 0; mt < 2; mt++)
                #pragma unroll
                for (int nt = 0; nt < 4; nt++)
                    mma16816(acc[mt][nt], ah[mt], &bhf[nt >> 1][(nt & 1)*2]);
            #pragma unroll
            for (int mt = 0; mt < 2; mt++)
                #pragma unroll
                for (int nt = 0; nt < 4; nt++)
                    mma16816(acc[mt][nt], ah[mt], &blf[nt >> 1][(nt & 1)*2]);
            #pragma unroll
            for (int mt = 0; mt < 2; mt++)
                #pragma unroll
                for (int nt = 0; nt < 4; nt++)
                    mma16816(acc[mt][nt], al[mt], &bhf[nt >> 1][(nt & 1)*2]);
        }
        __syncthreads();
    }

    int g = lane >> 2, tig = lane & 3;
    #pragma unroll
    for (int mt = 0; mt < 2; mt++)
        #pragma unroll
        for (int half = 0; half < 2; half++){
            int gi = i0 + wm*32 + mt*16 + g + half*8;
            #pragma unroll
            for (int nt = 0; nt < 4; nt++){
                int gd = wn*32 + nt*8 + tig*2;
                size_t o = ((size_t)(b*SS + gi))*EE + h*DD + gd;
                float2 rv = *(const float2*)&vals[o];
                *(float2*)&V[o] = make_float2(acc[mt][nt][half*2 + 0] + rv.x,
                                              acc[mt][nt][half*2 + 1] + rv.y);
            }
        }
}

// ---------------- fused weight conversion -----------------------------------
struct WTab {
    const float* W[7];
    __nv_bfloat16* Th[7];
    __nv_bfloat16* Tl[7];
    int K[7];
    int N[7];
    int off[8];
};

__global__ void convWT_all(WTab tab)
{
    __shared__ float t[32][33];
    int bid = blockIdx.x;
    int e = 0;
    #pragma unroll
    for (int i = 1; i < 7; i++) if (bid >= tab.off[i]) e = i;
    int local = bid - tab.off[e];
    const float* W = tab.W[e];
    __nv_bfloat16* Th = tab.Th[e];
    __nv_bfloat16* Tl = tab.Tl[e];
    int K = tab.K[e], N = tab.N[e];
    int ntiles = N >> 5;
    int kt = local / ntiles, ct = local - kt*ntiles;
    int by = kt*32, bx = ct*32;
    int lx = threadIdx.x & 31, ly = threadIdx.x >> 5;
    #pragma unroll
    for (int i = 0; i < 32; i += 8)
        t[ly + i][lx] = W[(size_t)(by + ly + i)*N + bx + lx];
    __syncthreads();
    #pragma unroll
    for (int i = 0; i < 32; i += 8){
        int n = bx + ly + i, k = by + lx;
        float x = t[lx][ly + i];
        __nv_bfloat16 h = __float2bfloat16_rn(x);
        Th[(size_t)n*K + k] = h;
        Tl[(size_t)n*K + k] = __float2bfloat16_rn(x - __bfloat162float(h));
    }
}

__global__ void convA(const float* __restrict__ X, __nv_bfloat16* __restrict__ H,
                      __nv_bfloat16* __restrict__ L, int n)
{
    int i = blockIdx.x*256 + threadIdx.x;
    if (i < n){
        float x = X[i];
        __nv_bfloat16 h = __float2bfloat16_rn(x);
        H[i] = h;
        L[i] = __float2bfloat16_rn(x - __bfloat162float(h));
    }
}

// ---------------- LayerNorm -> bf16 hi/lo -----------------------------------
__global__ void ln_bf16(const float* __restrict__ X, const float* __restrict__ g,
                        const float* __restrict__ bt,
                        __nv_bfloat16* __restrict__ Yh, __nv_bfloat16* __restrict__ Yl)
{
    int row = blockIdx.x;
    int tid = threadIdx.x;
    const float* x = X + (size_t)row*EE;
    float a = x[tid], c = x[tid + 256];
    float s  = a + c;
    float s2 = a*a + c*c;
    #pragma unroll
    for (int o = 16; o > 0; o >>= 1){
        s  += __shfl_xor_sync(0xffffffffu, s,  o);
        s2 += __shfl_xor_sync(0xffffffffu, s2, o);
    }
    __shared__ float sa[8], sbm[8];
    if ((tid & 31) == 0){ sa[tid>>5] = s; sbm[tid>>5] = s2; }
    __syncthreads();
    float ts = 0.f, ts2 = 0.f;
    #pragma unroll
    for (int w = 0; w < 8; w++){ ts += sa[w]; ts2 += sbm[w]; }
    float mean = ts * (1.f/512.f);
    float var  = ts2 * (1.f/512.f) - mean*mean;
    float r = rsqrtf(var + 1e-3f);
    float y0 = (a - mean)*r*g[tid]       + bt[tid];
    float y1 = (c - mean)*r*g[tid + 256] + bt[tid + 256];
    __nv_bfloat16 h0 = __float2bfloat16_rn(y0);
    __nv_bfloat16 h1 = __float2bfloat16_rn(y1);
    Yh[(size_t)row*EE + tid]       = h0;
    Yh[(size_t)row*EE + tid + 256] = h1;
    Yl[(size_t)row*EE + tid]       = __float2bfloat16_rn(y0 - __bfloat162float(h0));
    Yl[(size_t)row*EE + tid + 256] = __float2bfloat16_rn(y1 - __bfloat162float(h1));
}

// ---------------- tiny N=8 projection ---------------------------------------
__global__ void proj8(const float* __restrict__ X, const float* __restrict__ Wp,
                      const float* __restrict__ bp, float* __restrict__ Y)
{
    int row = blockIdx.x;
    int tid = threadIdx.x;
    int h = tid & 7, seg = tid >> 3;
    const float* x = X + (size_t)row*EE;
    float s = 0.f;
    #pragma unroll
    for (int k = 0; k < 16; k++){
        int kk = seg*16 + k;
        s += x[kk] * Wp[kk*HH + h];
    }
    __shared__ float sm[256];
    sm[tid] = s;
    __syncthreads();
    if (tid < 8){
        float acc = bp[tid];
        #pragma unroll
        for (int sg = 0; sg < 32; sg++) acc += sm[sg*8 + tid];
        Y[(size_t)row*HH + tid] = acc;
    }
}

// ---------------- P[m,h,r] --------------------------------------------------
__global__ __launch_bounds__(128) void pkernel(
    const float* __restrict__ q, const float* __restrict__ krt,
    const float* __restrict__ t1, float* __restrict__ P)
{
    int h = blockIdx.y;
    int m = blockIdx.x * 128 + threadIdx.x;
    float qr[64];
    const float4* qp = (const float4*)(q + (size_t)m*EE + h*DD);
    #pragma unroll
    for (int t = 0; t < 16; t++){
        float4 v = qp[t];
        qr[t*4+0]=v.x; qr[t*4+1]=v.y; qr[t*4+2]=v.z; qr[t*4+3]=v.w;
    }
    float* Pp = P + ((size_t)m*HH + h)*RUSE;
    const float* kbase = krt + h*DD;
    for (int r = 0; r < RUSE; r++){
        const float4* kp = (const float4*)(kbase + (size_t)r*EE);
        float acc = 0.f;
        #pragma unroll
        for (int t = 0; t < 16; t++){
            float4 k4 = __ldg(&kp[t]);
            acc += qr[t*4+0]*k4.x + qr[t*4+1]*k4.y + qr[t*4+2]*k4.z + qr[t*4+3]*k4.w;
        }
        Pp[r] = acc + t1[r*HH + h];
    }
}

// ---------------- launch ----------------------------------------------------
extern "C" void kernel_launch(void* const* d_in, const int* in_sizes, int n_in,
                              void* d_out, int out_size)
{
    const float* values  = (const float*)d_in[0];
    const float* rel_enc = (const float*)d_in[2];
    const float* ln0_g   = (const float*)d_in[3];
    const float* ln0_b   = (const float*)d_in[4];
    const float* w_b0    = (const float*)d_in[5];
    const float* b_b0    = (const float*)d_in[6];
    const float* wq      = (const float*)d_in[7];
    const float* bq      = (const float*)d_in[8];
    const float* wke     = (const float*)d_in[9];
    const float* bke     = (const float*)d_in[10];
    const float* wkv     = (const float*)d_in[11];
    const float* bkv     = (const float*)d_in[12];
    const float* wkr     = (const float*)d_in[13];
    const float* bkr     = (const float*)d_in[14];
    const float* wab0    = (const float*)d_in[15];
    const float* bab0    = (const float*)d_in[16];
    const float* wab1    = (const float*)d_in[17];
    const float* bab1    = (const float*)d_in[18];
    const float* ln1_g   = (const float*)d_in[19];
    const float* ln1_b   = (const float*)d_in[20];
    const float* w11     = (const float*)d_in[21];
    const float* b11     = (const float*)d_in[22];
    const float* w12     = (const float*)d_in[23];
    const float* b12     = (const float*)d_in[24];
    float* out = (float*)d_out;

    float *p_q,*p_ke,*p_krt,*p_t1,*p_b0t,*p_P,*p_L,*p_v;
    cudaGetSymbolAddress((void**)&p_q,   g_q);
    cudaGetSymbolAddress((void**)&p_ke,  g_ke);
    cudaGetSymbolAddress((void**)&p_krt, g_krt);
    cudaGetSymbolAddress((void**)&p_t1,  g_t1);
    cudaGetSymbolAddress((void**)&p_b0t, g_b0t);
    cudaGetSymbolAddress((void**)&p_P,   g_P);
    cudaGetSymbolAddress((void**)&p_L,   g_L);
    cudaGetSymbolAddress((void**)&p_v,   g_v);

    __nv_bfloat16 *xnh,*xnl,*xh,*xl,*vnh,*vnl,*h1h,*h1l,*reh,*rel;
    __nv_bfloat16 *qh,*ql,*keh,*kel,*kvh,*kvl,*Sh,*Sl;
    __nv_bfloat16 *wb0h,*wb0l,*wqkvh,*wqkvl,*wkrh,*wkrl,*w11h,*w11l,*w12h,*w12l;
    cudaGetSymbolAddress((void**)&xnh, g_xnh); cudaGetSymbolAddress((void**)&xnl, g_xnl);
    cudaGetSymbolAddress((void**)&xh,  g_xh);  cudaGetSymbolAddress((void**)&xl,  g_xl);
    cudaGetSymbolAddress((void**)&vnh, g_vnh); cudaGetSymbolAddress((void**)&vnl, g_vnl);
    cudaGetSymbolAddress((void**)&h1h, g_h1h); cudaGetSymbolAddress((void**)&h1l, g_h1l);
    cudaGetSymbolAddress((void**)&reh, g_reh); cudaGetSymbolAddress((void**)&rel, g_rel_);
    cudaGetSymbolAddress((void**)&qh,  g_qh);  cudaGetSymbolAddress((void**)&ql,  g_ql);
    cudaGetSymbolAddress((void**)&keh, g_keh); cudaGetSymbolAddress((void**)&kel, g_kel);
    cudaGetSymbolAddress((void**)&kvh, g_kvh); cudaGetSymbolAddress((void**)&kvl, g_kvl);
    cudaGetSymbolAddress((void**)&Sh,  g_Sh);  cudaGetSymbolAddress((void**)&Sl,  g_Sl);
    cudaGetSymbolAddress((void**)&wb0h, g_wb0h);   cudaGetSymbolAddress((void**)&wb0l, g_wb0l);
    cudaGetSymbolAddress((void**)&wqkvh, g_wqkvh); cudaGetSymbolAddress((void**)&wqkvl, g_wqkvl);
    cudaGetSymbolAddress((void**)&wkrh, g_wkrh);   cudaGetSymbolAddress((void**)&wkrl, g_wkrl);
    cudaGetSymbolAddress((void**)&w11h, g_w11h);   cudaGetSymbolAddress((void**)&w11l, g_w11l);
    cudaGetSymbolAddress((void**)&w12h, g_w12h);   cudaGetSymbolAddress((void**)&w12l, g_w12l);

    cudaFuncSetAttribute(gemm128<0>, cudaFuncAttributeMaxDynamicSharedMemorySize, GSMEM_BYTES);
    cudaFuncSetAttribute(gemm128<1>, cudaFuncAttributeMaxDynamicSharedMemorySize, GSMEM_BYTES);
    cudaFuncSetAttribute(gemm128<2>, cudaFuncAttributeMaxDynamicSharedMemorySize, GSMEM_BYTES);
    cudaFuncSetAttribute(gemm_qkv,   cudaFuncAttributeMaxDynamicSharedMemorySize, GSMEM_BYTES);
    cudaFuncSetAttribute(att_mma,    cudaFuncAttributeMaxDynamicSharedMemorySize, ATT_SMEM);

    WTab tab;
    tab.W[0]=w_b0; tab.Th[0]=wb0h;              tab.Tl[0]=wb0l;              tab.K[0]=EE;   tab.N[0]=HIDD;
    tab.W[1]=wq;   tab.Th[1]=wqkvh;             tab.Tl[1]=wqkvl;             tab.K[1]=HIDD; tab.N[1]=EE;
    tab.W[2]=wke;  tab.Th[2]=wqkvh + 512*HIDD;  tab.Tl[2]=wqkvl + 512*HIDD;  tab.K[2]=HIDD; tab.N[2]=EE;
    tab.W[3]=wkv;  tab.Th[3]=wqkvh + 1024*HIDD; tab.Tl[3]=wqkvl + 1024*HIDD; tab.K[3]=HIDD; tab.N[3]=EE;
    tab.W[4]=wkr;  tab.Th[4]=wkrh;              tab.Tl[4]=wkrl;              tab.K[4]=EE;   tab.N[4]=EE;
    tab.W[5]=w11;  tab.Th[5]=w11h;              tab.Tl[5]=w11l;              tab.K[5]=EE;   tab.N[5]=HIDD;
    tab.W[6]=w12;  tab.Th[6]=w12h;              tab.Tl[6]=w12l;              tab.K[6]=HIDD; tab.N[6]=EE;
    int total = 0;
    for (int i = 0; i < 7; i++){
        tab.off[i] = total;
        total += (tab.K[i]/32) * (tab.N[i]/32);
    }
    tab.off[7] = total;
    convWT_all<<<total, 256>>>(tab);
    convA<<<(RFULL*EE + 255)/256, 256>>>(rel_enc, reh, rel, RFULL*EE);

    // 1) LN0
    ln_bf16<<<MR, 256>>>(values, ln0_g, ln0_b, xnh, xnl);
    // 2) x = relu(xn @ w_b0 + b_b0)   [256 blocks, 2 CTA/SM]
    gemm128<1><<<dim3(HIDD/128, MR/128), 256, GSMEM_BYTES>>>(
        xnh, xnl, wb0h, wb0l, b_b0, nullptr, nullptr, xh, xl, MR, HIDD, EE);
    // 3) merged q/ke/kv               [192 blocks]
    gemm_qkv<<<dim3(12, MR/128), 256, GSMEM_BYTES>>>(
        xh, xl, wqkvh, wqkvl, bq, bke, bkv,
        p_q, p_ke, qh, ql, keh, kel, kvh, kvl, MR, HIDD);
    // 4) kr_table
    gemm128<0><<<dim3(EE/128, 2), 256, GSMEM_BYTES>>>(
        reh, rel, wkrh, wkrl, bkr, nullptr, p_krt, nullptr, nullptr, RFULL, EE, EE);
    // 5) t1 / bias0
    proj8<<<RFULL, 256>>>(p_krt, wab1, bab1, p_t1);
    proj8<<<MR, 256>>>(p_ke, wab0, bab0, p_b0t);
    // 6) P
    pkernel<<<dim3(MR/128, HH), 128>>>(p_q, p_krt, p_t1, p_P);
    // 7) logits
    logits_mma<<<dim3(36, BB*HH), 128>>>(qh, ql, keh, kel, p_P, p_b0t, p_L);
    // 8) softmax
    softmax_kernel<<<dim3(SS, BB*HH), 128>>>(p_L, Sh, Sl);
    // 9) att + residual
    att_mma<<<dim3(8, BB*HH), 128, ATT_SMEM>>>(Sh, Sl, kvh, kvl, values, p_v);
    // 10) LN1
    ln_bf16<<<MR, 256>>>(p_v, ln1_g, ln1_b, vnh, vnl);
    // 11) h1 = relu(vn @ w11 + b11)
    gemm128<1><<<dim3(HIDD/128, MR/128), 256, GSMEM_BYTES>>>(
        vnh, vnl, w11h, w11l, b11, nullptr, nullptr, h1h, h1l, MR, HIDD, EE);
    // 12) out = v + h1 @ w12 + b12
    gemm128<2><<<dim3(EE/128, MR/128), 256, GSMEM_BYTES>>>(
        h1h, h1l, w12h, w12l, b12, p_v, out, nullptr, nullptr, MR, EE, HIDD);
}

// round 10
// speedup vs baseline: 1.3450x; 1.3450x over previous
#include <cuda_runtime.h>
#include <cuda_fp16.h>
#include <cstdint>
#include <cstddef>

#define BB 4
#define SS 512
#define EE 512
#define HIDD 2048
#define HH 8
#define DD 64
#define RFULL 201
#define RUSE 101
#define MR (BB*SS)   // 2048

// ---------------- fp32 scratch ----------------------------------------------
__device__ __align__(128) float g_q [MR*EE];
__device__ __align__(128) float g_ke[MR*EE];
__device__ __align__(128) float g_krt[RFULL*EE];
__device__ __align__(128) float g_t1[RFULL*HH];
__device__ __align__(128) float g_b0t[MR*HH];
__device__ __align__(128) float g_P[(size_t)MR*HH*RUSE];
__device__ __align__(128) float g_L[(size_t)BB*HH*SS*SS];
__device__ __align__(128) float g_v [MR*EE];

// ---------------- fp16 split scratch ----------------------------------------
__device__ __align__(128) __half g_xnh[MR*EE],   g_xnl[MR*EE];
__device__ __align__(128) __half g_xh [MR*HIDD], g_xl [MR*HIDD];
__device__ __align__(128) __half g_vnh[MR*EE],   g_vnl[MR*EE];
__device__ __align__(128) __half g_h1h[MR*HIDD], g_h1l[MR*HIDD];
__device__ __align__(128) __half g_reh[RFULL*EE + 64], g_rel_[RFULL*EE + 64];
__device__ __align__(128) __half g_qh [MR*EE], g_ql [MR*EE];
__device__ __align__(128) __half g_keh[MR*EE], g_kel[MR*EE];
__device__ __align__(128) __half g_kvh[MR*EE], g_kvl[MR*EE];
__device__ __align__(128) __half g_Sh[(size_t)BB*HH*SS*SS];
__device__ __align__(128) __half g_Sl[(size_t)BB*HH*SS*SS];
// weights, transposed to [N][K], single fp16 (B-side of 2-pass split)
__device__ __align__(128) __half g_wb0h[HIDD*EE];
__device__ __align__(128) __half g_wqkvh[3*EE*HIDD];
__device__ __align__(128) __half g_wkrh[EE*EE];
__device__ __align__(128) __half g_w11h[HIDD*EE];
__device__ __align__(128) __half g_w12h[EE*HIDD];

// ---------------- PTX helpers -----------------------------------------------
__device__ __forceinline__ uint32_t s2u(const void* p){
    uint32_t a;
    asm("{ .reg .u64 t; cvta.to.shared.u64 t, %1; cvt.u32.u64 %0, t; }" : "=r"(a) : "l"(p));
    return a;
}
__device__ __forceinline__ void cpa16(uint32_t dst, const void* src, uint32_t sz){
    asm volatile("cp.async.cg.shared.global [%0], [%1], 16, %2;" :: "r"(dst), "l"(src), "r"(sz));
}
__device__ __forceinline__ void cpcommit(){ asm volatile("cp.async.commit_group;" ::: "memory"); }
__device__ __forceinline__ void cpwait0(){ asm volatile("cp.async.wait_group 0;" ::: "memory"); }
__device__ __forceinline__ void cpwait1(){ asm volatile("cp.async.wait_group 1;" ::: "memory"); }

__device__ __forceinline__ void ldsm4(uint32_t* r, uint32_t addr){
    asm volatile("ldmatrix.sync.aligned.m8n8.x4.shared.b16 {%0,%1,%2,%3}, [%4];"
        : "=r"(r[0]), "=r"(r[1]), "=r"(r[2]), "=r"(r[3]) : "r"(addr));
}
__device__ __forceinline__ void ldsm4t(uint32_t* r, uint32_t addr){
    asm volatile("ldmatrix.sync.aligned.m8n8.x4.trans.shared.b16 {%0,%1,%2,%3}, [%4];"
        : "=r"(r[0]), "=r"(r[1]), "=r"(r[2]), "=r"(r[3]) : "r"(addr));
}
__device__ __forceinline__ void mma16816(float* d, const uint32_t* a, const uint32_t* b){
    asm volatile("mma.sync.aligned.m16n8k16.row.col.f32.f16.f16.f32 "
        "{%0,%1,%2,%3}, {%4,%5,%6,%7}, {%8,%9}, {%0,%1,%2,%3};"
        : "+f"(d[0]), "+f"(d[1]), "+f"(d[2]), "+f"(d[3])
        : "r"(a[0]), "r"(a[1]), "r"(a[2]), "r"(a[3]), "r"(b[0]), "r"(b[1]));
}
__device__ __forceinline__ uint32_t packh(__half a, __half b){
    return (uint32_t)__half_as_ushort(a) | ((uint32_t)__half_as_ushort(b) << 16);
}

// geometry: k-chunk 64, rows padded to 72 halves (144 B)
#define KC 64
#define KSTRIDE 72
#define ROWB 144
#define TILE_B (128*ROWB)                // 18432 (128-row tile)
#define STAGE_B (3*TILE_B)               // 55296 (Ah, Al, Bh)
#define GSMEM_BYTES (2*STAGE_B)          // 110592 (128x128)

#define TILE_A2 (128*ROWB)               // 18432
#define TILE_B2 (256*ROWB)               // 36864
#define STAGE_B2 (2*TILE_A2 + TILE_B2)   // 73728
#define GSMEM2_BYTES (2*STAGE_B2)        // 147456 (128x256)

// attention tiles: 64x64 fp16, stride 72
#define ATILE_B (64*ROWB)                // 9216
#define ASTAGE_B (3*ATILE_B)             // 27648 (Ah, Al, Bh)
#define ATT_SMEM (2*ASTAGE_B)            // 55296

// ---------------- loaders ----------------------------------------------------
__device__ __forceinline__ void load_chunk128(uint32_t stage, int tid,
    const __half* __restrict__ Ah, const __half* __restrict__ Al,
    const __half* __restrict__ Bh,
    int m0, int n0, int k0, int M, int K)
{
    #pragma unroll
    for (int t = 0; t < 3; t++){
        const __half* g = (t==0)?Ah:(t==1)?Al:Bh;
        int row0 = (t < 2) ? m0 : n0;
        uint32_t tb = stage + t*TILE_B;
        #pragma unroll
        for (int i = 0; i < 4; i++){
            int s = i*256 + tid;          // 0..1023
            int r = s >> 3, seg = s & 7;
            int gr = row0 + r;
            uint32_t sz = 16u;
            if (t < 2 && gr >= M){ sz = 0u; gr = M - 1; }
            cpa16(tb + (uint32_t)(r*ROWB + seg*16),
                  g + (size_t)gr*K + k0 + seg*8, sz);
        }
    }
    cpcommit();
}

__device__ __forceinline__ void load_chunk_big(uint32_t stage, int tid,
    const __half* __restrict__ Ah, const __half* __restrict__ Al,
    const __half* __restrict__ Bh,
    int m0, int n0, int k0, int K)
{
    #pragma unroll
    for (int t = 0; t < 2; t++){
        const __half* g = t ? Al : Ah;
        uint32_t tb = stage + t*TILE_A2;
        #pragma unroll
        for (int i = 0; i < 4; i++){
            int s = i*256 + tid;
            int r = s >> 3, seg = s & 7;
            cpa16(tb + (uint32_t)(r*ROWB + seg*16),
                  g + (size_t)(m0 + r)*K + k0 + seg*8, 16u);
        }
    }
    {
        uint32_t tb = stage + 2*TILE_A2;
        #pragma unroll
        for (int i = 0; i < 8; i++){
            int s = i*256 + tid;          // 0..2047
            int r = s >> 3, seg = s & 7;
            cpa16(tb + (uint32_t)(r*ROWB + seg*16),
                  Bh + (size_t)(n0 + r)*K + k0 + seg*8, 16u);
        }
    }
    cpcommit();
}

// ---------------- 128x128 mainloop (2-pass fp16) -----------------------------
__device__ __forceinline__ void mainloop128(uint32_t sb, int tid, int lane, int warp,
    const __half* Ah, const __half* Al, const __half* Bh,
    int m0, int n0, int M, int K, float acc[4][4][4])
{
    int a_row  = (warp >> 2)*64 + (lane & 15);
    int a_col8 = (lane >> 4)*8;
    int b_row  = (warp & 3)*32 + (lane & 7) + ((lane & 16) ? 8 : 0);
    int b_col8 = ((lane & 8) ? 8 : 0);

    const int NC = K / KC;
    uint32_t st0 = sb, st1 = sb + STAGE_B;
    load_chunk128(st0, tid, Ah, Al, Bh, m0, n0, 0, M, K);

    for (int c = 0; c < NC; c++){
        uint32_t cur = (c & 1) ? st1 : st0;
        if (c + 1 < NC)
            load_chunk128((c & 1) ? st0 : st1, tid, Ah, Al, Bh, m0, n0, (c+1)*KC, M, K);
        if (c + 1 < NC) cpwait1(); else cpwait0();
        __syncthreads();

        uint32_t cAh = cur, cAl = cur + TILE_B, cBh = cur + 2*TILE_B;
        #pragma unroll
        for (int ks = 0; ks < 4; ks++){
            int k0 = ks*16;
            uint32_t ah[4][4], al[4][4], bh[2][4];
            #pragma unroll
            for (int mt = 0; mt < 4; mt++){
                uint32_t off = (uint32_t)((a_row + mt*16)*KSTRIDE + k0 + a_col8)*2u;
                ldsm4(ah[mt], cAh + off);
                ldsm4(al[mt], cAl + off);
            }
            #pragma unroll
            for (int p = 0; p < 2; p++){
                uint32_t off = (uint32_t)((b_row + p*16)*KSTRIDE + k0 + b_col8)*2u;
                ldsm4(bh[p], cBh + off);
            }
            // pass 1: Ah*Bh
            #pragma unroll
            for (int mt = 0; mt < 4; mt++)
                #pragma unroll
                for (int nt = 0; nt < 4; nt++)
                    mma16816(acc[mt][nt], ah[mt], &bh[nt >> 1][(nt & 1)*2]);
            // pass 2: Al*Bh
            #pragma unroll
            for (int mt = 0; mt < 4; mt++)
                #pragma unroll
                for (int nt = 0; nt < 4; nt++)
                    mma16816(acc[mt][nt], al[mt], &bh[nt >> 1][(nt & 1)*2]);
        }
        __syncthreads();
    }
}

// EPI: 0 fp32+bias, 2 fp32+bias+res
template<int EPI>
__global__ __launch_bounds__(256, 1)
void gemm128(const __half* Ah, const __half* Al, const __half* Bh,
             const float* __restrict__ bias, const float* __restrict__ res,
             float* __restrict__ Cf, int M, int N, int K)
{
    extern __shared__ char smem[];
    uint32_t sb = s2u(smem);
    int tid = threadIdx.x, lane = tid & 31, warp = tid >> 5;
    int m0 = blockIdx.y*128, n0 = blockIdx.x*128;
    float acc[4][4][4];
    #pragma unroll
    for (int a = 0; a < 4; a++)
        #pragma unroll
        for (int b = 0; b < 4; b++)
            #pragma unroll
            for (int c = 0; c < 4; c++) acc[a][b][c] = 0.f;

    mainloop128(sb, tid, lane, warp, Ah, Al, Bh, m0, n0, M, K, acc);

    int g = lane >> 2, tig = lane & 3;
    int wm = warp >> 2, wn = warp & 3;
    #pragma unroll
    for (int mt = 0; mt < 4; mt++)
        #pragma unroll
        for (int half = 0; half < 2; half++){
            int row = m0 + wm*64 + mt*16 + g + half*8;
            if (row >= M) continue;
            #pragma unroll
            for (int nt = 0; nt < 4; nt++){
                int col = n0 + wn*32 + nt*8 + tig*2;
                float v0 = acc[mt][nt][half*2 + 0] + bias[col];
                float v1 = acc[mt][nt][half*2 + 1] + bias[col + 1];
                size_t o = (size_t)row*N + col;
                if (EPI == 2){
                    float2 rv = *(const float2*)&res[o];
                    v0 += rv.x; v1 += rv.y;
                }
                *(float2*)&Cf[o] = make_float2(v0, v1);
            }
        }
}

// ---------------- 128x256 mainloop (2-pass fp16) -----------------------------
__device__ __forceinline__ void mainloop_big(uint32_t sb, int tid, int lane, int warp,
    const __half* Ah, const __half* Al, const __half* Bh,
    int m0, int n0, int K, float acc[4][8][4])
{
    int a_row  = (warp >> 2)*64 + (lane & 15);
    int a_col8 = (lane >> 4)*8;
    int b_rowb = (warp & 3)*64 + (lane & 7) + ((lane & 16) ? 8 : 0);
    int b_col8 = ((lane & 8) ? 8 : 0);

    const int NC = K / KC;
    uint32_t st0 = sb, st1 = sb + STAGE_B2;
    load_chunk_big(st0, tid, Ah, Al, Bh, m0, n0, 0, K);

    for (int c = 0; c < NC; c++){
        uint32_t cur = (c & 1) ? st1 : st0;
        if (c + 1 < NC)
            load_chunk_big((c & 1) ? st0 : st1, tid, Ah, Al, Bh, m0, n0, (c+1)*KC, K);
        if (c + 1 < NC) cpwait1(); else cpwait0();
        __syncthreads();

        uint32_t cAh = cur, cAl = cur + TILE_A2, cBh = cur + 2*TILE_A2;
        #pragma unroll
        for (int ks = 0; ks < 4; ks++){
            int k0 = ks*16;
            uint32_t ah[4][4], al[4][4];
            #pragma unroll
            for (int mt = 0; mt < 4; mt++){
                uint32_t off = (uint32_t)((a_row + mt*16)*KSTRIDE + k0 + a_col8)*2u;
                ldsm4(ah[mt], cAh + off);
                ldsm4(al[mt], cAl + off);
            }
            #pragma unroll
            for (int h2 = 0; h2 < 2; h2++){
                uint32_t bh[2][4];
                #pragma unroll
                for (int p = 0; p < 2; p++){
                    uint32_t off = (uint32_t)((b_rowb + (h2*2 + p)*16)*KSTRIDE + k0 + b_col8)*2u;
                    ldsm4(bh[p], cBh + off);
                }
                #pragma unroll
                for (int mt = 0; mt < 4; mt++)
                    #pragma unroll
                    for (int j = 0; j < 4; j++)
                        mma16816(acc[mt][h2*4 + j], ah[mt], &bh[j >> 1][(j & 1)*2]);
                #pragma unroll
                for (int mt = 0; mt < 4; mt++)
                    #pragma unroll
                    for (int j = 0; j < 4; j++)
                        mma16816(acc[mt][h2*4 + j], al[mt], &bh[j >> 1][(j & 1)*2]);
            }
        }
        __syncthreads();
    }
}

// relu -> fp16 hi/lo
__global__ __launch_bounds__(256, 1)
void gemm_big_relu(const __half* Ah, const __half* Al, const __half* Bh,
                   const float* __restrict__ bias,
                   __half* __restrict__ Ch, __half* __restrict__ Cl,
                   int M, int N, int K)
{
    extern __shared__ char smem[];
    uint32_t sb = s2u(smem);
    int tid = threadIdx.x, lane = tid & 31, warp = tid >> 5;
    int m0 = blockIdx.y*128, n0 = blockIdx.x*256;
    float acc[4][8][4];
    #pragma unroll
    for (int a = 0; a < 4; a++)
        #pragma unroll
        for (int b = 0; b < 8; b++)
            #pragma unroll
            for (int c = 0; c < 4; c++) acc[a][b][c] = 0.f;

    mainloop_big(sb, tid, lane, warp, Ah, Al, Bh, m0, n0, K, acc);

    int g = lane >> 2, tig = lane & 3;
    int wm = warp >> 2, wn = warp & 3;
    #pragma unroll
    for (int mt = 0; mt < 4; mt++)
        #pragma unroll
        for (int half = 0; half < 2; half++){
            int row = m0 + wm*64 + mt*16 + g + half*8;
            #pragma unroll
            for (int nt8 = 0; nt8 < 8; nt8++){
                int col = n0 + wn*64 + nt8*8 + tig*2;
                float v0 = fmaxf(acc[mt][nt8][half*2 + 0] + bias[col],     0.f);
                float v1 = fmaxf(acc[mt][nt8][half*2 + 1] + bias[col + 1], 0.f);
                size_t o = (size_t)row*N + col;
                __half h0 = __float2half_rn(v0);
                __half h1 = __float2half_rn(v1);
                __half l0 = __float2half_rn(v0 - __half2float(h0));
                __half l1 = __float2half_rn(v1 - __half2float(h1));
                *(uint32_t*)((char*)Ch + o*2) = packh(h0, h1);
                *(uint32_t*)((char*)Cl + o*2) = packh(l0, l1);
            }
        }
}

// merged qkv: B = concatenated [1536][2048], outputs routed by n0>>9
__global__ __launch_bounds__(256, 1)
void gemm_qkv_big(const __half* Ah, const __half* Al, const __half* Bh,
                  const float* b0, const float* b1, const float* b2,
                  float* f0, float* f1,
                  __half* c0h, __half* c0l,
                  __half* c1h, __half* c1l,
                  __half* c2h, __half* c2l,
                  int M, int K)
{
    extern __shared__ char smem[];
    uint32_t sb = s2u(smem);
    int tid = threadIdx.x, lane = tid & 31, warp = tid >> 5;
    int m0 = blockIdx.y*128, n0 = blockIdx.x*256;
    float acc[4][8][4];
    #pragma unroll
    for (int a = 0; a < 4; a++)
        #pragma unroll
        for (int b = 0; b < 8; b++)
            #pragma unroll
            for (int c = 0; c < 4; c++) acc[a][b][c] = 0.f;

    mainloop_big(sb, tid, lane, warp, Ah, Al, Bh, m0, n0, K, acc);

    int z = n0 >> 9;
    const float* bias = (z==0)?b0:(z==1)?b1:b2;
    float* Cf = (z==0)?f0:(z==1)?f1:nullptr;
    __half* Ch = (z==0)?c0h:(z==1)?c1h:c2h;
    __half* Cl = (z==0)?c0l:(z==1)?c1l:c2l;
    int n0l = n0 & 511;

    int g = lane >> 2, tig = lane & 3;
    int wm = warp >> 2, wn = warp & 3;
    #pragma unroll
    for (int mt = 0; mt < 4; mt++)
        #pragma unroll
        for (int half = 0; half < 2; half++){
            int row = m0 + wm*64 + mt*16 + g + half*8;
            #pragma unroll
            for (int nt8 = 0; nt8 < 8; nt8++){
                int col = n0l + wn*64 + nt8*8 + tig*2;
                float v0 = acc[mt][nt8][half*2 + 0] + bias[col];
                float v1 = acc[mt][nt8][half*2 + 1] + bias[col + 1];
                size_t o = (size_t)row*512 + col;
                if (Cf) *(float2*)&Cf[o] = make_float2(v0, v1);
                __half h0 = __float2half_rn(v0);
                __half h1 = __float2half_rn(v1);
                __half l0 = __float2half_rn(v0 - __half2float(h0));
                __half l1 = __float2half_rn(v1 - __half2float(h1));
                *(uint32_t*)((char*)Ch + o*2) = packh(h0, h1);
                *(uint32_t*)((char*)Cl + o*2) = packh(l0, l1);
            }
        }
}

// ---------------- logits via mma: causal 64x64 tiles ------------------------
__global__ __launch_bounds__(128) void logits_mma(
    const __half* __restrict__ qh, const __half* __restrict__ ql,
    const __half* __restrict__ keh,
    const float* __restrict__ P, const float* __restrict__ b0t,
    float* __restrict__ L)
{
    __shared__ char lsm[ASTAGE_B];
    uint32_t sb = s2u(lsm);
    int tid = threadIdx.x, lane = tid & 31, warp = tid >> 5;
    int tri = blockIdx.x;
    int it = 0;
    while ((it + 1)*(it + 2)/2 <= tri) it++;
    int jt = tri - it*(it + 1)/2;
    int bh = blockIdx.y, b = bh >> 3, h = bh & 7;
    int i0 = it*64, j0 = jt*64;

    #pragma unroll
    for (int t = 0; t < 3; t++){
        const __half* g = (t==0)?qh:(t==1)?ql:keh;
        int row0 = (t < 2) ? i0 : j0;
        uint32_t tb = sb + t*ATILE_B;
        #pragma unroll
        for (int i = 0; i < 4; i++){
            int s = i*128 + tid;
            int r = s >> 3, seg = s & 7;
            cpa16(tb + (uint32_t)(r*ROWB + seg*16),
                  g + ((size_t)(b*SS + row0 + r))*EE + h*DD + seg*8, 16u);
        }
    }
    cpcommit(); cpwait0();
    __syncthreads();

    int wm = warp >> 1, wn = warp & 1;
    int a_row  = wm*32 + (lane & 15);
    int a_col8 = (lane >> 4)*8;
    int b_row  = wn*32 + (lane & 7) + ((lane & 16) ? 8 : 0);
    int b_col8 = ((lane & 8) ? 8 : 0);

    uint32_t cAh = sb, cAl = sb + ATILE_B, cBh = sb + 2*ATILE_B;
    float acc[2][4][4];
    #pragma unroll
    for (int a = 0; a < 2; a++)
        #pragma unroll
        for (int bb2 = 0; bb2 < 4; bb2++)
            #pragma unroll
            for (int c = 0; c < 4; c++) acc[a][bb2][c] = 0.f;

    #pragma unroll
    for (int ks = 0; ks < 4; ks++){
        int k0 = ks*16;
        uint32_t ah[2][4], al[2][4], bhf[2][4];
        #pragma unroll
        for (int mt = 0; mt < 2; mt++){
            uint32_t off = (uint32_t)((a_row + mt*16)*KSTRIDE + k0 + a_col8)*2u;
            ldsm4(ah[mt], cAh + off);
            ldsm4(al[mt], cAl + off);
        }
        #pragma unroll
        for (int p = 0; p < 2; p++){
            uint32_t off = (uint32_t)((b_row + p*16)*KSTRIDE + k0 + b_col8)*2u;
            ldsm4(bhf[p], cBh + off);
        }
        #pragma unroll
        for (int mt = 0; mt < 2; mt++)
            #pragma unroll
            for (int nt = 0; nt < 4; nt++)
                mma16816(acc[mt][nt], ah[mt], &bhf[nt >> 1][(nt & 1)*2]);
        #pragma unroll
        for (int mt = 0; mt < 2; mt++)
            #pragma unroll
            for (int nt = 0; nt < 4; nt++)
                mma16816(acc[mt][nt], al[mt], &bhf[nt >> 1][(nt & 1)*2]);
    }

    int g = lane >> 2, tig = lane & 3;
    #pragma unroll
    for (int mt = 0; mt < 2; mt++)
        #pragma unroll
        for (int half = 0; half < 2; half++){
            int gi = i0 + wm*32 + mt*16 + g + half*8;
            const float* Pr = P + ((size_t)(b*SS + gi)*HH + h)*RUSE;
            float* Lr = L + ((size_t)bh*SS + gi)*SS;
            #pragma unroll
            for (int nt = 0; nt < 4; nt++){
                int gj = j0 + wn*32 + nt*8 + tig*2;
                #pragma unroll
                for (int e = 0; e < 2; e++){
                    int j = gj + e;
                    if (j > gi) continue;
                    int off = j - gi;
                    if (off < -100) off = -100;
                    Lr[j] = acc[mt][nt][half*2 + e]*0.125f + Pr[off + 100]
                          + b0t[(size_t)(b*SS + j)*HH + h];
                }
            }
        }
}

// ---------------- softmax: fp32 in, fp16 hi/lo out --------------------------
__global__ void softmax_kernel(const float* __restrict__ L,
                               __half* __restrict__ Ph,
                               __half* __restrict__ Pl)
{
    int i = blockIdx.x;
    size_t ro = ((size_t)blockIdx.y*SS + i)*SS;
    const float* row = L + ro;
    int n = i + 1;
    int tid = threadIdx.x;
    float v[4];
    float mx = -1e30f;
    #pragma unroll
    for (int l = 0; l < 4; l++){
        int j = tid + l*128;
        v[l] = (j < n) ? row[j] : -1e30f;
        mx = fmaxf(mx, v[l]);
    }
    #pragma unroll
    for (int o = 16; o > 0; o >>= 1) mx = fmaxf(mx, __shfl_xor_sync(0xffffffffu, mx, o));
    __shared__ float smx[4], ssum[4];
    if ((tid & 31) == 0) smx[tid>>5] = mx;
    __syncthreads();
    mx = fmaxf(fmaxf(smx[0], smx[1]), fmaxf(smx[2], smx[3]));
    float s = 0.f;
    #pragma unroll
    for (int l = 0; l < 4; l++){
        int j = tid + l*128;
        if (j < n){ v[l] = __expf(v[l] - mx); s += v[l]; } else v[l] = 0.f;
    }
    #pragma unroll
    for (int o = 16; o > 0; o >>= 1) s += __shfl_xor_sync(0xffffffffu, s, o);
    if ((tid & 31) == 0) ssum[tid>>5] = s;
    __syncthreads();
    s = ssum[0] + ssum[1] + ssum[2] + ssum[3];
    float inv = 1.f / s;
    #pragma unroll
    for (int l = 0; l < 4; l++){
        int j = tid + l*128;
        float p = (j < n) ? v[l]*inv : 0.f;
        __half h = __float2half_rn(p);
        Ph[ro + j] = h;
        Pl[ro + j] = __float2half_rn(p - __half2float(h));
    }
}

// ---------------- att via mma ------------------------------------------------
__device__ __forceinline__ void load_att_chunk(uint32_t stage, int tid,
    const __half* __restrict__ Ph, const __half* __restrict__ Pl,
    const __half* __restrict__ kvh,
    int bh, int b, int h, int i0, int jt)
{
    int j0 = jt*64;
    #pragma unroll
    for (int t = 0; t < 2; t++){
        const __half* g = t ? Pl : Ph;
        uint32_t tb = stage + t*ATILE_B;
        #pragma unroll
        for (int i = 0; i < 4; i++){
            int s = i*128 + tid;
            int r = s >> 3, seg = s & 7;
            cpa16(tb + (uint32_t)(r*ROWB + seg*16),
                  g + ((size_t)bh*SS + i0 + r)*SS + j0 + seg*8, 16u);
        }
    }
    {
        uint32_t tb = stage + 2*ATILE_B;
        #pragma unroll
        for (int i = 0; i < 4; i++){
            int s = i*128 + tid;
            int r = s >> 3, seg = s & 7;
            cpa16(tb + (uint32_t)(r*ROWB + seg*16),
                  kvh + ((size_t)(b*SS + j0 + r))*EE + h*DD + seg*8, 16u);
        }
    }
    cpcommit();
}

__global__ __launch_bounds__(128) void att_mma(
    const __half* __restrict__ Ph, const __half* __restrict__ Pl,
    const __half* __restrict__ kvh,
    const float* __restrict__ vals, float* __restrict__ V)
{
    extern __shared__ char smem[];
    uint32_t sb = s2u(smem);
    int tid = threadIdx.x, lane = tid & 31, warp = tid >> 5;
    int it = blockIdx.x, bh = blockIdx.y, b = bh >> 3, h = bh & 7;
    int i0 = it*64;
    int NCH = it + 1;

    int wm = warp >> 1, wn = warp & 1;
    int a_row  = wm*32 + (lane & 15);
    int a_col8 = (lane >> 4)*8;
    int bt_row = lane & 15;
    int bt_col = wn*32 + ((lane & 16) ? 8 : 0);

    float acc[2][4][4];
    #pragma unroll
    for (int a = 0; a < 2; a++)
        #pragma unroll
        for (int bb2 = 0; bb2 < 4; bb2++)
            #pragma unroll
            for (int c = 0; c < 4; c++) acc[a][bb2][c] = 0.f;

    uint32_t st0 = sb, st1 = sb + ASTAGE_B;
    load_att_chunk(st0, tid, Ph, Pl, kvh, bh, b, h, i0, 0);

    for (int c = 0; c < NCH; c++){
        uint32_t cur = (c & 1) ? st1 : st0;
        if (c + 1 < NCH)
            load_att_chunk((c & 1) ? st0 : st1, tid, Ph, Pl, kvh, bh, b, h, i0, c + 1);
        if (c + 1 < NCH) cpwait1(); else cpwait0();
        __syncthreads();

        uint32_t cSh = cur, cSl = cur + ATILE_B, cKh = cur + 2*ATILE_B;
        #pragma unroll
        for (int ks = 0; ks < 4; ks++){
            int k0 = ks*16;
            uint32_t ah[2][4], al[2][4], bhf[2][4];
            #pragma unroll
            for (int mt = 0; mt < 2; mt++){
                uint32_t off = (uint32_t)((a_row + mt*16)*KSTRIDE + k0 + a_col8)*2u;
                ldsm4(ah[mt], cSh + off);
                ldsm4(al[mt], cSl + off);
            }
            #pragma unroll
            for (int grp = 0; grp < 2; grp++){
                uint32_t off = (uint32_t)((k0 + bt_row)*KSTRIDE + bt_col + grp*16)*2u;
                ldsm4t(bhf[grp], cKh + off);
            }
            #pragma unroll
            for (int mt = 0; mt < 2; mt++)
                #pragma unroll
                for (int nt = 0; nt < 4; nt++)
                    mma16816(acc[mt][nt], ah[mt], &bhf[nt >> 1][(nt & 1)*2]);
            #pragma unroll
            for (int mt = 0; mt < 2; mt++)
                #pragma unroll
                for (int nt = 0; nt < 4; nt++)
                    mma16816(acc[mt][nt], al[mt], &bhf[nt >> 1][(nt & 1)*2]);
        }
        __syncthreads();
    }

    int g = lane >> 2, tig = lane & 3;
    #pragma unroll
    for (int mt = 0; mt < 2; mt++)
        #pragma unroll
        for (int half = 0; half < 2; half++){
            int gi = i0 + wm*32 + mt*16 + g + half*8;
            #pragma unroll
            for (int nt = 0; nt < 4; nt++){
                int gd = wn*32 + nt*8 + tig*2;
                size_t o = ((size_t)(b*SS + gi))*EE + h*DD + gd;
                float2 rv = *(const float2*)&vals[o];
                *(float2*)&V[o] = make_float2(acc[mt][nt][half*2 + 0] + rv.x,
                                              acc[mt][nt][half*2 + 1] + rv.y);
            }
        }
}

// ---------------- fused weight conversion (single fp16) ----------------------
struct WTab {
    const float* W[7];
    __half* Th[7];
    int K[7];
    int N[7];
    int off[8];
};

__global__ void convWT_all(WTab tab)
{
    __shared__ float t[32][33];
    int bid = blockIdx.x;
    int e = 0;
    #pragma unroll
    for (int i = 1; i < 7; i++) if (bid >= tab.off[i]) e = i;
    int local = bid - tab.off[e];
    const float* W = tab.W[e];
    __half* Th = tab.Th[e];
    int K = tab.K[e], N = tab.N[e];
    int ntiles = N >> 5;
    int kt = local / ntiles, ct = local - kt*ntiles;
    int by = kt*32, bx = ct*32;
    int lx = threadIdx.x & 31, ly = threadIdx.x >> 5;
    #pragma unroll
    for (int i = 0; i < 32; i += 8)
        t[ly + i][lx] = W[(size_t)(by + ly + i)*N + bx + lx];
    __syncthreads();
    #pragma unroll
    for (int i = 0; i < 32; i += 8){
        int n = bx + ly + i, k = by + lx;
        Th[(size_t)n*K + k] = __float2half_rn(t[lx][ly + i]);
    }
}

__global__ void convA(const float* __restrict__ X, __half* __restrict__ H,
                      __half* __restrict__ L, int n)
{
    int i = blockIdx.x*256 + threadIdx.x;
    if (i < n){
        float x = X[i];
        __half h = __float2half_rn(x);
        H[i] = h;
        L[i] = __float2half_rn(x - __half2float(h));
    }
}

// ---------------- LayerNorm -> fp16 hi/lo -----------------------------------
__global__ void ln_f16(const float* __restrict__ X, const float* __restrict__ g,
                       const float* __restrict__ bt,
                       __half* __restrict__ Yh, __half* __restrict__ Yl)
{
    int row = blockIdx.x;
    int tid = threadIdx.x;
    const float* x = X + (size_t)row*EE;
    float a = x[tid], c = x[tid + 256];
    float s  = a + c;
    float s2 = a*a + c*c;
    #pragma unroll
    for (int o = 16; o > 0; o >>= 1){
        s  += __shfl_xor_sync(0xffffffffu, s,  o);
        s2 += __shfl_xor_sync(0xffffffffu, s2, o);
    }
    __shared__ float sa[8], sbm[8];
    if ((tid & 31) == 0){ sa[tid>>5] = s; sbm[tid>>5] = s2; }
    __syncthreads();
    float ts = 0.f, ts2 = 0.f;
    #pragma unroll
    for (int w = 0; w < 8; w++){ ts += sa[w]; ts2 += sbm[w]; }
    float mean = ts * (1.f/512.f);
    float var  = ts2 * (1.f/512.f) - mean*mean;
    float r = rsqrtf(var + 1e-3f);
    float y0 = (a - mean)*r*g[tid]       + bt[tid];
    float y1 = (c - mean)*r*g[tid + 256] + bt[tid + 256];
    __half h0 = __float2half_rn(y0);
    __half h1 = __float2half_rn(y1);
    Yh[(size_t)row*EE + tid]       = h0;
    Yh[(size_t)row*EE + tid + 256] = h1;
    Yl[(size_t)row*EE + tid]       = __float2half_rn(y0 - __half2float(h0));
    Yl[(size_t)row*EE + tid + 256] = __float2half_rn(y1 - __half2float(h1));
}

// ---------------- tiny N=8 projection ---------------------------------------
__global__ void proj8(const float* __restrict__ X, const float* __restrict__ Wp,
                      const float* __restrict__ bp, float* __restrict__ Y)
{
    int row = blockIdx.x;
    int tid = threadIdx.x;
    int h = tid & 7, seg = tid >> 3;
    const float* x = X + (size_t)row*EE;
    float s = 0.f;
    #pragma unroll
    for (int k = 0; k < 16; k++){
        int kk = seg*16 + k;
        s += x[kk] * Wp[kk*HH + h];
    }
    __shared__ float sm[256];
    sm[tid] = s;
    __syncthreads();
    if (tid < 8){
        float acc = bp[tid];
        #pragma unroll
        for (int sg = 0; sg < 32; sg++) acc += sm[sg*8 + tid];
        Y[(size_t)row*HH + tid] = acc;
    }
}

// ---------------- P[m,h,r] --------------------------------------------------
__global__ __launch_bounds__(128) void pkernel(
    const float* __restrict__ q, const float* __restrict__ krt,
    const float* __restrict__ t1, float* __restrict__ P)
{
    int h = blockIdx.y;
    int m = blockIdx.x * 128 + threadIdx.x;
    float qr[64];
    const float4* qp = (const float4*)(q + (size_t)m*EE + h*DD);
    #pragma unroll
    for (int t = 0; t < 16; t++){
        float4 v = qp[t];
        qr[t*4+0]=v.x; qr[t*4+1]=v.y; qr[t*4+2]=v.z; qr[t*4+3]=v.w;
    }
    float* Pp = P + ((size_t)m*HH + h)*RUSE;
    const float* kbase = krt + h*DD;
    for (int r = 0; r < RUSE; r++){
        const float4* kp = (const float4*)(kbase + (size_t)r*EE);
        float acc = 0.f;
        #pragma unroll
        for (int t = 0; t < 16; t++){
            float4 k4 = __ldg(&kp[t]);
            acc += qr[t*4+0]*k4.x + qr[t*4+1]*k4.y + qr[t*4+2]*k4.z + qr[t*4+3]*k4.w;
        }
        Pp[r] = acc + t1[r*HH + h];
    }
}

// ---------------- launch ----------------------------------------------------
extern "C" void kernel_launch(void* const* d_in, const int* in_sizes, int n_in,
                              void* d_out, int out_size)
{
    const float* values  = (const float*)d_in[0];
    const float* rel_enc = (const float*)d_in[2];
    const float* ln0_g   = (const float*)d_in[3];
    const float* ln0_b   = (const float*)d_in[4];
    const float* w_b0    = (const float*)d_in[5];
    const float* b_b0    = (const float*)d_in[6];
    const float* wq      = (const float*)d_in[7];
    const float* bq      = (const float*)d_in[8];
    const float* wke     = (const float*)d_in[9];
    const float* bke     = (const float*)d_in[10];
    const float* wkv     = (const float*)d_in[11];
    const float* bkv     = (const float*)d_in[12];
    const float* wkr     = (const float*)d_in[13];
    const float* bkr     = (const float*)d_in[14];
    const float* wab0    = (const float*)d_in[15];
    const float* bab0    = (const float*)d_in[16];
    const float* wab1    = (const float*)d_in[17];
    const float* bab1    = (const float*)d_in[18];
    const float* ln1_g   = (const float*)d_in[19];
    const float* ln1_b   = (const float*)d_in[20];
    const float* w11     = (const float*)d_in[21];
    const float* b11     = (const float*)d_in[22];
    const float* w12     = (const float*)d_in[23];
    const float* b12     = (const float*)d_in[24];
    float* out = (float*)d_out;

    float *p_q,*p_ke,*p_krt,*p_t1,*p_b0t,*p_P,*p_L,*p_v;
    cudaGetSymbolAddress((void**)&p_q,   g_q);
    cudaGetSymbolAddress((void**)&p_ke,  g_ke);
    cudaGetSymbolAddress((void**)&p_krt, g_krt);
    cudaGetSymbolAddress((void**)&p_t1,  g_t1);
    cudaGetSymbolAddress((void**)&p_b0t, g_b0t);
    cudaGetSymbolAddress((void**)&p_P,   g_P);
    cudaGetSymbolAddress((void**)&p_L,   g_L);
    cudaGetSymbolAddress((void**)&p_v,   g_v);

    __half *xnh,*xnl,*xh,*xl,*vnh,*vnl,*h1h,*h1l,*reh,*rel;
    __half *qh,*ql,*keh,*kel,*kvh,*kvl,*Sh,*Sl;
    __half *wb0h,*wqkvh,*wkrh,*w11h,*w12h;
    cudaGetSymbolAddress((void**)&xnh, g_xnh); cudaGetSymbolAddress((void**)&xnl, g_xnl);
    cudaGetSymbolAddress((void**)&xh,  g_xh);  cudaGetSymbolAddress((void**)&xl,  g_xl);
    cudaGetSymbolAddress((void**)&vnh, g_vnh); cudaGetSymbolAddress((void**)&vnl, g_vnl);
    cudaGetSymbolAddress((void**)&h1h, g_h1h); cudaGetSymbolAddress((void**)&h1l, g_h1l);
    cudaGetSymbolAddress((void**)&reh, g_reh); cudaGetSymbolAddress((void**)&rel, g_rel_);
    cudaGetSymbolAddress((void**)&qh,  g_qh);  cudaGetSymbolAddress((void**)&ql,  g_ql);
    cudaGetSymbolAddress((void**)&keh, g_keh); cudaGetSymbolAddress((void**)&kel, g_kel);
    cudaGetSymbolAddress((void**)&kvh, g_kvh); cudaGetSymbolAddress((void**)&kvl, g_kvl);
    cudaGetSymbolAddress((void**)&Sh,  g_Sh);  cudaGetSymbolAddress((void**)&Sl,  g_Sl);
    cudaGetSymbolAddress((void**)&wb0h, g_wb0h);
    cudaGetSymbolAddress((void**)&wqkvh, g_wqkvh);
    cudaGetSymbolAddress((void**)&wkrh, g_wkrh);
    cudaGetSymbolAddress((void**)&w11h, g_w11h);
    cudaGetSymbolAddress((void**)&w12h, g_w12h);

    cudaFuncSetAttribute(gemm128<0>,    cudaFuncAttributeMaxDynamicSharedMemorySize, GSMEM_BYTES);
    cudaFuncSetAttribute(gemm128<2>,    cudaFuncAttributeMaxDynamicSharedMemorySize, GSMEM_BYTES);
    cudaFuncSetAttribute(gemm_big_relu, cudaFuncAttributeMaxDynamicSharedMemorySize, GSMEM2_BYTES);
    cudaFuncSetAttribute(gemm_qkv_big,  cudaFuncAttributeMaxDynamicSharedMemorySize, GSMEM2_BYTES);
    cudaFuncSetAttribute(att_mma,       cudaFuncAttributeMaxDynamicSharedMemorySize, ATT_SMEM);

    WTab tab;
    tab.W[0]=w_b0; tab.Th[0]=wb0h;              tab.K[0]=EE;   tab.N[0]=HIDD;
    tab.W[1]=wq;   tab.Th[1]=wqkvh;             tab.K[1]=HIDD; tab.N[1]=EE;
    tab.W[2]=wke;  tab.Th[2]=wqkvh + 512*HIDD;  tab.K[2]=HIDD; tab.N[2]=EE;
    tab.W[3]=wkv;  tab.Th[3]=wqkvh + 1024*HIDD; tab.K[3]=HIDD; tab.N[3]=EE;
    tab.W[4]=wkr;  tab.Th[4]=wkrh;              tab.K[4]=EE;   tab.N[4]=EE;
    tab.W[5]=w11;  tab.Th[5]=w11h;              tab.K[5]=EE;   tab.N[5]=HIDD;
    tab.W[6]=w12;  tab.Th[6]=w12h;              tab.K[6]=HIDD; tab.N[6]=EE;
    int total = 0;
    for (int i = 0; i < 7; i++){
        tab.off[i] = total;
        total += (tab.K[i]/32) * (tab.N[i]/32);
    }
    tab.off[7] = total;
    convWT_all<<<total, 256>>>(tab);
    convA<<<(RFULL*EE + 255)/256, 256>>>(rel_enc, reh, rel, RFULL*EE);

    // 1) LN0
    ln_f16<<<MR, 256>>>(values, ln0_g, ln0_b, xnh, xnl);
    // 2) x = relu(xn @ w_b0 + b_b0)   [128x256, 128 blocks]
    gemm_big_relu<<<dim3(HIDD/256, MR/128), 256, GSMEM2_BYTES>>>(
        xnh, xnl, wb0h, b_b0, xh, xl, MR, HIDD, EE);
    // 3) merged q/ke/kv               [128x256, 96 blocks = 1 wave]
    gemm_qkv_big<<<dim3(6, MR/128), 256, GSMEM2_BYTES>>>(
        xh, xl, wqkvh, bq, bke, bkv,
        p_q, p_ke, qh, ql, keh, kel, kvh, kvl, MR, HIDD);
    // 4) kr_table
    gemm128<0><<<dim3(EE/128, 2), 256, GSMEM_BYTES>>>(
        reh, rel, wkrh, bkr, nullptr, p_krt, RFULL, EE, EE);
    // 5) t1 / bias0
    proj8<<<RFULL, 256>>>(p_krt, wab1, bab1, p_t1);
    proj8<<<MR, 256>>>(p_ke, wab0, bab0, p_b0t);
    // 6) P
    pkernel<<<dim3(MR/128, HH), 128>>>(p_q, p_krt, p_t1, p_P);
    // 7) logits
    logits_mma<<<dim3(36, BB*HH), 128>>>(qh, ql, keh, p_P, p_b0t, p_L);
    // 8) softmax
    softmax_kernel<<<dim3(SS, BB*HH), 128>>>(p_L, Sh, Sl);
    // 9) att + residual
    att_mma<<<dim3(8, BB*HH), 128, ATT_SMEM>>>(Sh, Sl, kvh, values, p_v);
    // 10) LN1
    ln_f16<<<MR, 256>>>(p_v, ln1_g, ln1_b, vnh, vnl);
    // 11) h1 = relu(vn @ w11 + b11)
    gemm_big_relu<<<dim3(HIDD/256, MR/128), 256, GSMEM2_BYTES>>>(
        vnh, vnl, w11h, b11, h1h, h1l, MR, HIDD, EE);
    // 12) out = v + h1 @ w12 + b12
    gemm128<2><<<dim3(EE/128, MR/128), 256, GSMEM_BYTES>>>(
        h1h, h1l, w12h, b12, p_v, out, MR, EE, HIDD);
}

// round 11
// speedup vs baseline: 1.7181x; 1.2774x over previous
#include <cuda_runtime.h>
#include <cuda_fp16.h>
#include <cstdint>
#include <cstddef>

#define BB 4
#define SS 512
#define EE 512
#define HIDD 2048
#define HH 8
#define DD 64
#define RFULL 201
#define RUSE 101
#define MR (BB*SS)   // 2048

// ---------------- fp32 scratch ----------------------------------------------
__device__ __align__(128) float g_q [MR*EE];
__device__ __align__(128) float g_ke[MR*EE];
__device__ __align__(128) float g_krt[RFULL*EE];
__device__ __align__(128) float g_t1[RFULL*HH];
__device__ __align__(128) float g_b0t[MR*HH];
__device__ __align__(128) float g_P[(size_t)MR*HH*RUSE];
__device__ __align__(128) float g_L[(size_t)BB*HH*SS*SS];
__device__ __align__(128) float g_v [MR*EE];

// ---------------- fp16 scratch ----------------------------------------------
__device__ __align__(128) __half g_xnh[MR*EE];
__device__ __align__(128) __half g_xh [MR*HIDD];
__device__ __align__(128) __half g_vnh[MR*EE];
__device__ __align__(128) __half g_h1h[MR*HIDD];
__device__ __align__(128) __half g_reh[RFULL*EE + 64], g_rel_[RFULL*EE + 64];
__device__ __align__(128) __half g_qh [MR*EE], g_ql [MR*EE];
__device__ __align__(128) __half g_keh[MR*EE];
__device__ __align__(128) __half g_kvh[MR*EE];
__device__ __align__(128) __half g_Sh[(size_t)BB*HH*SS*SS];
__device__ __align__(128) __half g_Sl[(size_t)BB*HH*SS*SS];
// weights, transposed to [N][K], single fp16
__device__ __align__(128) __half g_wb0h[HIDD*EE];
__device__ __align__(128) __half g_wqkvh[3*EE*HIDD];
__device__ __align__(128) __half g_wkrh[EE*EE];
__device__ __align__(128) __half g_w11h[HIDD*EE];
__device__ __align__(128) __half g_w12h[EE*HIDD];

// ---------------- PTX helpers -----------------------------------------------
__device__ __forceinline__ uint32_t s2u(const void* p){
    uint32_t a;
    asm("{ .reg .u64 t; cvta.to.shared.u64 t, %1; cvt.u32.u64 %0, t; }" : "=r"(a) : "l"(p));
    return a;
}
__device__ __forceinline__ void cpa16(uint32_t dst, const void* src, uint32_t sz){
    asm volatile("cp.async.cg.shared.global [%0], [%1], 16, %2;" :: "r"(dst), "l"(src), "r"(sz));
}
__device__ __forceinline__ void cpcommit(){ asm volatile("cp.async.commit_group;" ::: "memory"); }
__device__ __forceinline__ void cpwait0(){ asm volatile("cp.async.wait_group 0;" ::: "memory"); }
__device__ __forceinline__ void cpwait1(){ asm volatile("cp.async.wait_group 1;" ::: "memory"); }

__device__ __forceinline__ void ldsm4(uint32_t* r, uint32_t addr){
    asm volatile("ldmatrix.sync.aligned.m8n8.x4.shared.b16 {%0,%1,%2,%3}, [%4];"
        : "=r"(r[0]), "=r"(r[1]), "=r"(r[2]), "=r"(r[3]) : "r"(addr));
}
__device__ __forceinline__ void ldsm4t(uint32_t* r, uint32_t addr){
    asm volatile("ldmatrix.sync.aligned.m8n8.x4.trans.shared.b16 {%0,%1,%2,%3}, [%4];"
        : "=r"(r[0]), "=r"(r[1]), "=r"(r[2]), "=r"(r[3]) : "r"(addr));
}
__device__ __forceinline__ void mma16816(float* d, const uint32_t* a, const uint32_t* b){
    asm volatile("mma.sync.aligned.m16n8k16.row.col.f32.f16.f16.f32 "
        "{%0,%1,%2,%3}, {%4,%5,%6,%7}, {%8,%9}, {%0,%1,%2,%3};"
        : "+f"(d[0]), "+f"(d[1]), "+f"(d[2]), "+f"(d[3])
        : "r"(a[0]), "r"(a[1]), "r"(a[2]), "r"(a[3]), "r"(b[0]), "r"(b[1]));
}
__device__ __forceinline__ uint32_t packh(__half a, __half b){
    return (uint32_t)__half_as_ushort(a) | ((uint32_t)__half_as_ushort(b) << 16);
}

// geometry: k-chunk 64, rows padded to 72 halves (144 B)
#define KC 64
#define KSTRIDE 72
#define ROWB 144
#define TILE_B (128*ROWB)                 // 18432 (128-row tile)
#define STAGE1P (2*TILE_B)                // 36864  (A, B)
#define GSMEM1P (2*STAGE1P)               // 73728
#define STAGE2P (3*TILE_B)                // 55296  (Ah, Al, B)  -- kr only
#define GSMEM2P (2*STAGE2P)               // 110592

#define TILE_A2 (128*ROWB)                // 18432
#define TILE_B2 (256*ROWB)                // 36864
#define STAGEBIG (TILE_A2 + TILE_B2)      // 55296
#define GSMEMBIG (2*STAGEBIG)             // 110592

// attention tiles: 64x64 fp16, stride 72
#define ATILE_B (64*ROWB)                 // 9216
#define ASTAGE_B (3*ATILE_B)              // 27648
#define ATT_SMEM (2*ASTAGE_B)             // 55296

// ---------------- loaders ----------------------------------------------------
// TILES = 2 (A,B) or 3 (Ah,Al,B); 128-row tiles
template<int TILES>
__device__ __forceinline__ void load_chunk128(uint32_t stage, int tid,
    const __half* __restrict__ A0, const __half* __restrict__ A1,
    const __half* __restrict__ Bh,
    int m0, int n0, int k0, int M, int K)
{
    #pragma unroll
    for (int t = 0; t < TILES; t++){
        const __half* g = (t==0)?A0:(t==TILES-1)?Bh:A1;
        int row0 = (t < TILES-1) ? m0 : n0;
        uint32_t tb = stage + t*TILE_B;
        #pragma unroll
        for (int i = 0; i < 4; i++){
            int s = i*256 + tid;
            int r = s >> 3, seg = s & 7;
            int gr = row0 + r;
            uint32_t sz = 16u;
            if (t < TILES-1 && gr >= M){ sz = 0u; gr = M - 1; }
            cpa16(tb + (uint32_t)(r*ROWB + seg*16),
                  g + (size_t)gr*K + k0 + seg*8, sz);
        }
    }
    cpcommit();
}

__device__ __forceinline__ void load_chunk_big(uint32_t stage, int tid,
    const __half* __restrict__ Ah, const __half* __restrict__ Bh,
    int m0, int n0, int k0, int K)
{
    #pragma unroll
    for (int i = 0; i < 4; i++){
        int s = i*256 + tid;
        int r = s >> 3, seg = s & 7;
        cpa16(stage + (uint32_t)(r*ROWB + seg*16),
              Ah + (size_t)(m0 + r)*K + k0 + seg*8, 16u);
    }
    uint32_t tb = stage + TILE_A2;
    #pragma unroll
    for (int i = 0; i < 8; i++){
        int s = i*256 + tid;
        int r = s >> 3, seg = s & 7;
        cpa16(tb + (uint32_t)(r*ROWB + seg*16),
              Bh + (size_t)(n0 + r)*K + k0 + seg*8, 16u);
    }
    cpcommit();
}

// ---------------- 128x128 mainloop (PASSES = 1 or 2) -------------------------
template<int PASSES>
__device__ __forceinline__ void mainloop128(uint32_t sb, int tid, int lane, int warp,
    const __half* A0, const __half* A1, const __half* Bh,
    int m0, int n0, int M, int K, float acc[4][4][4])
{
    const int TILES = PASSES + 1;
    const int STG = TILES*TILE_B;
    int a_row  = (warp >> 2)*64 + (lane & 15);
    int a_col8 = (lane >> 4)*8;
    int b_row  = (warp & 3)*32 + (lane & 7) + ((lane & 16) ? 8 : 0);
    int b_col8 = ((lane & 8) ? 8 : 0);

    const int NC = K / KC;
    uint32_t st0 = sb, st1 = sb + STG;
    load_chunk128<TILES>(st0, tid, A0, A1, Bh, m0, n0, 0, M, K);

    for (int c = 0; c < NC; c++){
        uint32_t cur = (c & 1) ? st1 : st0;
        if (c + 1 < NC)
            load_chunk128<TILES>((c & 1) ? st0 : st1, tid, A0, A1, Bh, m0, n0, (c+1)*KC, M, K);
        if (c + 1 < NC) cpwait1(); else cpwait0();
        __syncthreads();

        uint32_t cA0 = cur, cA1 = cur + TILE_B, cB = cur + (TILES-1)*TILE_B;
        #pragma unroll
        for (int ks = 0; ks < 4; ks++){
            int k0 = ks*16;
            uint32_t a0[4][4], a1[4][4], bh[2][4];
            #pragma unroll
            for (int mt = 0; mt < 4; mt++){
                uint32_t off = (uint32_t)((a_row + mt*16)*KSTRIDE + k0 + a_col8)*2u;
                ldsm4(a0[mt], cA0 + off);
                if (PASSES == 2) ldsm4(a1[mt], cA1 + off);
            }
            #pragma unroll
            for (int p = 0; p < 2; p++){
                uint32_t off = (uint32_t)((b_row + p*16)*KSTRIDE + k0 + b_col8)*2u;
                ldsm4(bh[p], cB + off);
            }
            #pragma unroll
            for (int mt = 0; mt < 4; mt++)
                #pragma unroll
                for (int nt = 0; nt < 4; nt++)
                    mma16816(acc[mt][nt], a0[mt], &bh[nt >> 1][(nt & 1)*2]);
            if (PASSES == 2){
                #pragma unroll
                for (int mt = 0; mt < 4; mt++)
                    #pragma unroll
                    for (int nt = 0; nt < 4; nt++)
                        mma16816(acc[mt][nt], a1[mt], &bh[nt >> 1][(nt & 1)*2]);
            }
        }
        __syncthreads();
    }
}

// EPI: 0 fp32+bias, 2 fp32+bias+res ; PASSES in {1,2}
template<int EPI, int PASSES>
__global__ __launch_bounds__(256, 1)
void gemm128(const __half* A0, const __half* A1, const __half* Bh,
             const float* __restrict__ bias, const float* __restrict__ res,
             float* __restrict__ Cf, int M, int N, int K)
{
    extern __shared__ char smem[];
    uint32_t sb = s2u(smem);
    int tid = threadIdx.x, lane = tid & 31, warp = tid >> 5;
    int m0 = blockIdx.y*128, n0 = blockIdx.x*128;
    float acc[4][4][4];
    #pragma unroll
    for (int a = 0; a < 4; a++)
        #pragma unroll
        for (int b = 0; b < 4; b++)
            #pragma unroll
            for (int c = 0; c < 4; c++) acc[a][b][c] = 0.f;

    mainloop128<PASSES>(sb, tid, lane, warp, A0, A1, Bh, m0, n0, M, K, acc);

    int g = lane >> 2, tig = lane & 3;
    int wm = warp >> 2, wn = warp & 3;
    #pragma unroll
    for (int mt = 0; mt < 4; mt++)
        #pragma unroll
        for (int half = 0; half < 2; half++){
            int row = m0 + wm*64 + mt*16 + g + half*8;
            if (row >= M) continue;
            #pragma unroll
            for (int nt = 0; nt < 4; nt++){
                int col = n0 + wn*32 + nt*8 + tig*2;
                float v0 = acc[mt][nt][half*2 + 0] + bias[col];
                float v1 = acc[mt][nt][half*2 + 1] + bias[col + 1];
                size_t o = (size_t)row*N + col;
                if (EPI == 2){
                    float2 rv = *(const float2*)&res[o];
                    v0 += rv.x; v1 += rv.y;
                }
                *(float2*)&Cf[o] = make_float2(v0, v1);
            }
        }
}

// ---------------- 128x256 mainloop (single pass) -----------------------------
__device__ __forceinline__ void mainloop_big(uint32_t sb, int tid, int lane, int warp,
    const __half* Ah, const __half* Bh,
    int m0, int n0, int K, float acc[4][8][4])
{
    int a_row  = (warp >> 2)*64 + (lane & 15);
    int a_col8 = (lane >> 4)*8;
    int b_rowb = (warp & 3)*64 + (lane & 7) + ((lane & 16) ? 8 : 0);
    int b_col8 = ((lane & 8) ? 8 : 0);

    const int NC = K / KC;
    uint32_t st0 = sb, st1 = sb + STAGEBIG;
    load_chunk_big(st0, tid, Ah, Bh, m0, n0, 0, K);

    for (int c = 0; c < NC; c++){
        uint32_t cur = (c & 1) ? st1 : st0;
        if (c + 1 < NC)
            load_chunk_big((c & 1) ? st0 : st1, tid, Ah, Bh, m0, n0, (c+1)*KC, K);
        if (c + 1 < NC) cpwait1(); else cpwait0();
        __syncthreads();

        uint32_t cA = cur, cB = cur + TILE_A2;
        #pragma unroll
        for (int ks = 0; ks < 4; ks++){
            int k0 = ks*16;
            uint32_t ah[4][4];
            #pragma unroll
            for (int mt = 0; mt < 4; mt++){
                uint32_t off = (uint32_t)((a_row + mt*16)*KSTRIDE + k0 + a_col8)*2u;
                ldsm4(ah[mt], cA + off);
            }
            #pragma unroll
            for (int h2 = 0; h2 < 2; h2++){
                uint32_t bh[2][4];
                #pragma unroll
                for (int p = 0; p < 2; p++){
                    uint32_t off = (uint32_t)((b_rowb + (h2*2 + p)*16)*KSTRIDE + k0 + b_col8)*2u;
                    ldsm4(bh[p], cB + off);
                }
                #pragma unroll
                for (int mt = 0; mt < 4; mt++)
                    #pragma unroll
                    for (int j = 0; j < 4; j++)
                        mma16816(acc[mt][h2*4 + j], ah[mt], &bh[j >> 1][(j & 1)*2]);
            }
        }
        __syncthreads();
    }
}

// relu -> fp16 hi only
__global__ __launch_bounds__(256, 1)
void gemm_big_relu(const __half* Ah, const __half* Bh,
                   const float* __restrict__ bias,
                   __half* __restrict__ Ch, int M, int N, int K)
{
    extern __shared__ char smem[];
    uint32_t sb = s2u(smem);
    int tid = threadIdx.x, lane = tid & 31, warp = tid >> 5;
    int m0 = blockIdx.y*128, n0 = blockIdx.x*256;
    float acc[4][8][4];
    #pragma unroll
    for (int a = 0; a < 4; a++)
        #pragma unroll
        for (int b = 0; b < 8; b++)
            #pragma unroll
            for (int c = 0; c < 4; c++) acc[a][b][c] = 0.f;

    mainloop_big(sb, tid, lane, warp, Ah, Bh, m0, n0, K, acc);

    int g = lane >> 2, tig = lane & 3;
    int wm = warp >> 2, wn = warp & 3;
    #pragma unroll
    for (int mt = 0; mt < 4; mt++)
        #pragma unroll
        for (int half = 0; half < 2; half++){
            int row = m0 + wm*64 + mt*16 + g + half*8;
            #pragma unroll
            for (int nt8 = 0; nt8 < 8; nt8++){
                int col = n0 + wn*64 + nt8*8 + tig*2;
                float v0 = fmaxf(acc[mt][nt8][half*2 + 0] + bias[col],     0.f);
                float v1 = fmaxf(acc[mt][nt8][half*2 + 1] + bias[col + 1], 0.f);
                size_t o = (size_t)row*N + col;
                *(uint32_t*)((char*)Ch + o*2) = packh(__float2half_rn(v0), __float2half_rn(v1));
            }
        }
}

// merged qkv: B = [1536][2048]; z==0 -> q (fp32+hi+lo), z==1 -> ke (fp32+hi), z==2 -> kv (hi)
__global__ __launch_bounds__(256, 1)
void gemm_qkv_big(const __half* Ah, const __half* Bh,
                  const float* b0, const float* b1, const float* b2,
                  float* f0, float* f1,
                  __half* c0h, __half* c0l, __half* c1h, __half* c2h,
                  int M, int K)
{
    extern __shared__ char smem[];
    uint32_t sb = s2u(smem);
    int tid = threadIdx.x, lane = tid & 31, warp = tid >> 5;
    int m0 = blockIdx.y*128, n0 = blockIdx.x*256;
    float acc[4][8][4];
    #pragma unroll
    for (int a = 0; a < 4; a++)
        #pragma unroll
        for (int b = 0; b < 8; b++)
            #pragma unroll
            for (int c = 0; c < 4; c++) acc[a][b][c] = 0.f;

    mainloop_big(sb, tid, lane, warp, Ah, Bh, m0, n0, K, acc);

    int z = n0 >> 9;
    const float* bias = (z==0)?b0:(z==1)?b1:b2;
    float* Cf = (z==0)?f0:(z==1)?f1:nullptr;
    __half* Ch = (z==0)?c0h:(z==1)?c1h:c2h;
    __half* Cl = (z==0)?c0l:nullptr;
    int n0l = n0 & 511;

    int g = lane >> 2, tig = lane & 3;
    int wm = warp >> 2, wn = warp & 3;
    #pragma unroll
    for (int mt = 0; mt < 4; mt++)
        #pragma unroll
        for (int half = 0; half < 2; half++){
            int row = m0 + wm*64 + mt*16 + g + half*8;
            #pragma unroll
            for (int nt8 = 0; nt8 < 8; nt8++){
                int col = n0l + wn*64 + nt8*8 + tig*2;
                float v0 = acc[mt][nt8][half*2 + 0] + bias[col];
                float v1 = acc[mt][nt8][half*2 + 1] + bias[col + 1];
                size_t o = (size_t)row*512 + col;
                if (Cf) *(float2*)&Cf[o] = make_float2(v0, v1);
                __half h0 = __float2half_rn(v0);
                __half h1 = __float2half_rn(v1);
                *(uint32_t*)((char*)Ch + o*2) = packh(h0, h1);
                if (Cl){
                    __half l0 = __float2half_rn(v0 - __half2float(h0));
                    __half l1 = __float2half_rn(v1 - __half2float(h1));
                    *(uint32_t*)((char*)Cl + o*2) = packh(l0, l1);
                }
            }
        }
}

// ---------------- logits via mma: causal 64x64 tiles (2-pass q) --------------
__global__ __launch_bounds__(128) void logits_mma(
    const __half* __restrict__ qh, const __half* __restrict__ ql,
    const __half* __restrict__ keh,
    const float* __restrict__ P, const float* __restrict__ b0t,
    float* __restrict__ L)
{
    __shared__ char lsm[ASTAGE_B];
    uint32_t sb = s2u(lsm);
    int tid = threadIdx.x, lane = tid & 31, warp = tid >> 5;
    int tri = blockIdx.x;
    int it = 0;
    while ((it + 1)*(it + 2)/2 <= tri) it++;
    int jt = tri - it*(it + 1)/2;
    int bh = blockIdx.y, b = bh >> 3, h = bh & 7;
    int i0 = it*64, j0 = jt*64;

    #pragma unroll
    for (int t = 0; t < 3; t++){
        const __half* g = (t==0)?qh:(t==1)?ql:keh;
        int row0 = (t < 2) ? i0 : j0;
        uint32_t tb = sb + t*ATILE_B;
        #pragma unroll
        for (int i = 0; i < 4; i++){
            int s = i*128 + tid;
            int r = s >> 3, seg = s & 7;
            cpa16(tb + (uint32_t)(r*ROWB + seg*16),
                  g + ((size_t)(b*SS + row0 + r))*EE + h*DD + seg*8, 16u);
        }
    }
    cpcommit(); cpwait0();
    __syncthreads();

    int wm = warp >> 1, wn = warp & 1;
    int a_row  = wm*32 + (lane & 15);
    int a_col8 = (lane >> 4)*8;
    int b_row  = wn*32 + (lane & 7) + ((lane & 16) ? 8 : 0);
    int b_col8 = ((lane & 8) ? 8 : 0);

    uint32_t cAh = sb, cAl = sb + ATILE_B, cBh = sb + 2*ATILE_B;
    float acc[2][4][4];
    #pragma unroll
    for (int a = 0; a < 2; a++)
        #pragma unroll
        for (int bb2 = 0; bb2 < 4; bb2++)
            #pragma unroll
            for (int c = 0; c < 4; c++) acc[a][bb2][c] = 0.f;

    #pragma unroll
    for (int ks = 0; ks < 4; ks++){
        int k0 = ks*16;
        uint32_t ah[2][4], al[2][4], bhf[2][4];
        #pragma unroll
        for (int mt = 0; mt < 2; mt++){
            uint32_t off = (uint32_t)((a_row + mt*16)*KSTRIDE + k0 + a_col8)*2u;
            ldsm4(ah[mt], cAh + off);
            ldsm4(al[mt], cAl + off);
        }
        #pragma unroll
        for (int p = 0; p < 2; p++){
            uint32_t off = (uint32_t)((b_row + p*16)*KSTRIDE + k0 + b_col8)*2u;
            ldsm4(bhf[p], cBh + off);
        }
        #pragma unroll
        for (int mt = 0; mt < 2; mt++)
            #pragma unroll
            for (int nt = 0; nt < 4; nt++)
                mma16816(acc[mt][nt], ah[mt], &bhf[nt >> 1][(nt & 1)*2]);
        #pragma unroll
        for (int mt = 0; mt < 2; mt++)
            #pragma unroll
            for (int nt = 0; nt < 4; nt++)
                mma16816(acc[mt][nt], al[mt], &bhf[nt >> 1][(nt & 1)*2]);
    }

    int g = lane >> 2, tig = lane & 3;
    #pragma unroll
    for (int mt = 0; mt < 2; mt++)
        #pragma unroll
        for (int half = 0; half < 2; half++){
            int gi = i0 + wm*32 + mt*16 + g + half*8;
            const float* Pr = P + ((size_t)(b*SS + gi)*HH + h)*RUSE;
            float* Lr = L + ((size_t)bh*SS + gi)*SS;
            #pragma unroll
            for (int nt = 0; nt < 4; nt++){
                int gj = j0 + wn*32 + nt*8 + tig*2;
                #pragma unroll
                for (int e = 0; e < 2; e++){
                    int j = gj + e;
                    if (j > gi) continue;
                    int off = j - gi;
                    if (off < -100) off = -100;
                    Lr[j] = acc[mt][nt][half*2 + e]*0.125f + Pr[off + 100]
                          + b0t[(size_t)(b*SS + j)*HH + h];
                }
            }
        }
}

// ---------------- softmax: fp32 in, fp16 hi/lo out --------------------------
__global__ void softmax_kernel(const float* __restrict__ L,
                               __half* __restrict__ Ph,
                               __half* __restrict__ Pl)
{
    int i = blockIdx.x;
    size_t ro = ((size_t)blockIdx.y*SS + i)*SS;
    const float* row = L + ro;
    int n = i + 1;
    int tid = threadIdx.x;
    float v[4];
    float mx = -1e30f;
    #pragma unroll
    for (int l = 0; l < 4; l++){
        int j = tid + l*128;
        v[l] = (j < n) ? row[j] : -1e30f;
        mx = fmaxf(mx, v[l]);
    }
    #pragma unroll
    for (int o = 16; o > 0; o >>= 1) mx = fmaxf(mx, __shfl_xor_sync(0xffffffffu, mx, o));
    __shared__ float smx[4], ssum[4];
    if ((tid & 31) == 0) smx[tid>>5] = mx;
    __syncthreads();
    mx = fmaxf(fmaxf(smx[0], smx[1]), fmaxf(smx[2], smx[3]));
    float s = 0.f;
    #pragma unroll
    for (int l = 0; l < 4; l++){
        int j = tid + l*128;
        if (j < n){ v[l] = __expf(v[l] - mx); s += v[l]; } else v[l] = 0.f;
    }
    #pragma unroll
    for (int o = 16; o > 0; o >>= 1) s += __shfl_xor_sync(0xffffffffu, s, o);
    if ((tid & 31) == 0) ssum[tid>>5] = s;
    __syncthreads();
    s = ssum[0] + ssum[1] + ssum[2] + ssum[3];
    float inv = 1.f / s;
    #pragma unroll
    for (int l = 0; l < 4; l++){
        int j = tid + l*128;
        float p = (j < n) ? v[l]*inv : 0.f;
        __half h = __float2half_rn(p);
        Ph[ro + j] = h;
        Pl[ro + j] = __float2half_rn(p - __half2float(h));
    }
}

// ---------------- att via mma (2-pass scores) --------------------------------
__device__ __forceinline__ void load_att_chunk(uint32_t stage, int tid,
    const __half* __restrict__ Ph, const __half* __restrict__ Pl,
    const __half* __restrict__ kvh,
    int bh, int b, int h, int i0, int jt)
{
    int j0 = jt*64;
    #pragma unroll
    for (int t = 0; t < 2; t++){
        const __half* g = t ? Pl : Ph;
        uint32_t tb = stage + t*ATILE_B;
        #pragma unroll
        for (int i = 0; i < 4; i++){
            int s = i*128 + tid;
            int r = s >> 3, seg = s & 7;
            cpa16(tb + (uint32_t)(r*ROWB + seg*16),
                  g + ((size_t)bh*SS + i0 + r)*SS + j0 + seg*8, 16u);
        }
    }
    {
        uint32_t tb = stage + 2*ATILE_B;
        #pragma unroll
        for (int i = 0; i < 4; i++){
            int s = i*128 + tid;
            int r = s >> 3, seg = s & 7;
            cpa16(tb + (uint32_t)(r*ROWB + seg*16),
                  kvh + ((size_t)(b*SS + j0 + r))*EE + h*DD + seg*8, 16u);
        }
    }
    cpcommit();
}

__global__ __launch_bounds__(128) void att_mma(
    const __half* __restrict__ Ph, const __half* __restrict__ Pl,
    const __half* __restrict__ kvh,
    const float* __restrict__ vals, float* __restrict__ V)
{
    extern __shared__ char smem[];
    uint32_t sb = s2u(smem);
    int tid = threadIdx.x, lane = tid & 31, warp = tid >> 5;
    int it = blockIdx.x, bh = blockIdx.y, b = bh >> 3, h = bh & 7;
    int i0 = it*64;
    int NCH = it + 1;

    int wm = warp >> 1, wn = warp & 1;
    int a_row  = wm*32 + (lane & 15);
    int a_col8 = (lane >> 4)*8;
    int bt_row = lane & 15;
    int bt_col = wn*32 + ((lane & 16) ? 8 : 0);

    float acc[2][4][4];
    #pragma unroll
    for (int a = 0; a < 2; a++)
        #pragma unroll
        for (int bb2 = 0; bb2 < 4; bb2++)
            #pragma unroll
            for (int c = 0; c < 4; c++) acc[a][bb2][c] = 0.f;

    uint32_t st0 = sb, st1 = sb + ASTAGE_B;
    load_att_chunk(st0, tid, Ph, Pl, kvh, bh, b, h, i0, 0);

    for (int c = 0; c < NCH; c++){
        uint32_t cur = (c & 1) ? st1 : st0;
        if (c + 1 < NCH)
            load_att_chunk((c & 1) ? st0 : st1, tid, Ph, Pl, kvh, bh, b, h, i0, c + 1);
        if (c + 1 < NCH) cpwait1(); else cpwait0();
        __syncthreads();

        uint32_t cSh = cur, cSl = cur + ATILE_B, cKh = cur + 2*ATILE_B;
        #pragma unroll
        for (int ks = 0; ks < 4; ks++){
            int k0 = ks*16;
            uint32_t ah[2][4], al[2][4], bhf[2][4];
            #pragma unroll
            for (int mt = 0; mt < 2; mt++){
                uint32_t off = (uint32_t)((a_row + mt*16)*KSTRIDE + k0 + a_col8)*2u;
                ldsm4(ah[mt], cSh + off);
                ldsm4(al[mt], cSl + off);
            }
            #pragma unroll
            for (int grp = 0; grp < 2; grp++){
                uint32_t off = (uint32_t)((k0 + bt_row)*KSTRIDE + bt_col + grp*16)*2u;
                ldsm4t(bhf[grp], cKh + off);
            }
            #pragma unroll
            for (int mt = 0; mt < 2; mt++)
                #pragma unroll
                for (int nt = 0; nt < 4; nt++)
                    mma16816(acc[mt][nt], ah[mt], &bhf[nt >> 1][(nt & 1)*2]);
            #pragma unroll
            for (int mt = 0; mt < 2; mt++)
                #pragma unroll
                for (int nt = 0; nt < 4; nt++)
                    mma16816(acc[mt][nt], al[mt], &bhf[nt >> 1][(nt & 1)*2]);
        }
        __syncthreads();
    }

    int g = lane >> 2, tig = lane & 3;
    #pragma unroll
    for (int mt = 0; mt < 2; mt++)
        #pragma unroll
        for (int half = 0; half < 2; half++){
            int gi = i0 + wm*32 + mt*16 + g + half*8;
            #pragma unroll
            for (int nt = 0; nt < 4; nt++){
                int gd = wn*32 + nt*8 + tig*2;
                size_t o = ((size_t)(b*SS + gi))*EE + h*DD + gd;
                float2 rv = *(const float2*)&vals[o];
                *(float2*)&V[o] = make_float2(acc[mt][nt][half*2 + 0] + rv.x,
                                              acc[mt][nt][half*2 + 1] + rv.y);
            }
        }
}

// ---------------- fused weight conversion (single fp16) ----------------------
struct WTab {
    const float* W[7];
    __half* Th[7];
    int K[7];
    int N[7];
    int off[8];
};

__global__ void convWT_all(WTab tab)
{
    __shared__ float t[32][33];
    int bid = blockIdx.x;
    int e = 0;
    #pragma unroll
    for (int i = 1; i < 7; i++) if (bid >= tab.off[i]) e = i;
    int local = bid - tab.off[e];
    const float* W = tab.W[e];
    __half* Th = tab.Th[e];
    int K = tab.K[e], N = tab.N[e];
    int ntiles = N >> 5;
    int kt = local / ntiles, ct = local - kt*ntiles;
    int by = kt*32, bx = ct*32;
    int lx = threadIdx.x & 31, ly = threadIdx.x >> 5;
    #pragma unroll
    for (int i = 0; i < 32; i += 8)
        t[ly + i][lx] = W[(size_t)(by + ly + i)*N + bx + lx];
    __syncthreads();
    #pragma unroll
    for (int i = 0; i < 32; i += 8){
        int n = bx + ly + i, k = by + lx;
        Th[(size_t)n*K + k] = __float2half_rn(t[lx][ly + i]);
    }
}

__global__ void convA(const float* __restrict__ X, __half* __restrict__ H,
                      __half* __restrict__ L, int n)
{
    int i = blockIdx.x*256 + threadIdx.x;
    if (i < n){
        float x = X[i];
        __half h = __float2half_rn(x);
        H[i] = h;
        L[i] = __float2half_rn(x - __half2float(h));
    }
}

// ---------------- LayerNorm -> fp16 hi only ---------------------------------
__global__ void ln_h(const float* __restrict__ X, const float* __restrict__ g,
                     const float* __restrict__ bt, __half* __restrict__ Yh)
{
    int row = blockIdx.x;
    int tid = threadIdx.x;
    const float* x = X + (size_t)row*EE;
    float a = x[tid], c = x[tid + 256];
    float s  = a + c;
    float s2 = a*a + c*c;
    #pragma unroll
    for (int o = 16; o > 0; o >>= 1){
        s  += __shfl_xor_sync(0xffffffffu, s,  o);
        s2 += __shfl_xor_sync(0xffffffffu, s2, o);
    }
    __shared__ float sa[8], sbm[8];
    if ((tid & 31) == 0){ sa[tid>>5] = s; sbm[tid>>5] = s2; }
    __syncthreads();
    float ts = 0.f, ts2 = 0.f;
    #pragma unroll
    for (int w = 0; w < 8; w++){ ts += sa[w]; ts2 += sbm[w]; }
    float mean = ts * (1.f/512.f);
    float var  = ts2 * (1.f/512.f) - mean*mean;
    float r = rsqrtf(var + 1e-3f);
    Yh[(size_t)row*EE + tid]       = __float2half_rn((a - mean)*r*g[tid]       + bt[tid]);
    Yh[(size_t)row*EE + tid + 256] = __float2half_rn((c - mean)*r*g[tid + 256] + bt[tid + 256]);
}

// ---------------- tiny N=8 projection ---------------------------------------
__global__ void proj8(const float* __restrict__ X, const float* __restrict__ Wp,
                      const float* __restrict__ bp, float* __restrict__ Y)
{
    int row = blockIdx.x;
    int tid = threadIdx.x;
    int h = tid & 7, seg = tid >> 3;
    const float* x = X + (size_t)row*EE;
    float s = 0.f;
    #pragma unroll
    for (int k = 0; k < 16; k++){
        int kk = seg*16 + k;
        s += x[kk] * Wp[kk*HH + h];
    }
    __shared__ float sm[256];
    sm[tid] = s;
    __syncthreads();
    if (tid < 8){
        float acc = bp[tid];
        #pragma unroll
        for (int sg = 0; sg < 32; sg++) acc += sm[sg*8 + tid];
        Y[(size_t)row*HH + tid] = acc;
    }
}

// ---------------- P[m,h,r] --------------------------------------------------
__global__ __launch_bounds__(128) void pkernel(
    const float* __restrict__ q, const float* __restrict__ krt,
    const float* __restrict__ t1, float* __restrict__ P)
{
    int h = blockIdx.y;
    int m = blockIdx.x * 128 + threadIdx.x;
    float qr[64];
    const float4* qp = (const float4*)(q + (size_t)m*EE + h*DD);
    #pragma unroll
    for (int t = 0; t < 16; t++){
        float4 v = qp[t];
        qr[t*4+0]=v.x; qr[t*4+1]=v.y; qr[t*4+2]=v.z; qr[t*4+3]=v.w;
    }
    float* Pp = P + ((size_t)m*HH + h)*RUSE;
    const float* kbase = krt + h*DD;
    for (int r = 0; r < RUSE; r++){
        const float4* kp = (const float4*)(kbase + (size_t)r*EE);
        float acc = 0.f;
        #pragma unroll
        for (int t = 0; t < 16; t++){
            float4 k4 = __ldg(&kp[t]);
            acc += qr[t*4+0]*k4.x + qr[t*4+1]*k4.y + qr[t*4+2]*k4.z + qr[t*4+3]*k4.w;
        }
        Pp[r] = acc + t1[r*HH + h];
    }
}

// ---------------- launch ----------------------------------------------------
extern "C" void kernel_launch(void* const* d_in, const int* in_sizes, int n_in,
                              void* d_out, int out_size)
{
    const float* values  = (const float*)d_in[0];
    const float* rel_enc = (const float*)d_in[2];
    const float* ln0_g   = (const float*)d_in[3];
    const float* ln0_b   = (const float*)d_in[4];
    const float* w_b0    = (const float*)d_in[5];
    const float* b_b0    = (const float*)d_in[6];
    const float* wq      = (const float*)d_in[7];
    const float* bq      = (const float*)d_in[8];
    const float* wke     = (const float*)d_in[9];
    const float* bke     = (const float*)d_in[10];
    const float* wkv     = (const float*)d_in[11];
    const float* bkv     = (const float*)d_in[12];
    const float* wkr     = (const float*)d_in[13];
    const float* bkr     = (const float*)d_in[14];
    const float* wab0    = (const float*)d_in[15];
    const float* bab0    = (const float*)d_in[16];
    const float* wab1    = (const float*)d_in[17];
    const float* bab1    = (const float*)d_in[18];
    const float* ln1_g   = (const float*)d_in[19];
    const float* ln1_b   = (const float*)d_in[20];
    const float* w11     = (const float*)d_in[21];
    const float* b11     = (const float*)d_in[22];
    const float* w12     = (const float*)d_in[23];
    const float* b12     = (const float*)d_in[24];
    float* out = (float*)d_out;

    float *p_q,*p_ke,*p_krt,*p_t1,*p_b0t,*p_P,*p_L,*p_v;
    cudaGetSymbolAddress((void**)&p_q,   g_q);
    cudaGetSymbolAddress((void**)&p_ke,  g_ke);
    cudaGetSymbolAddress((void**)&p_krt, g_krt);
    cudaGetSymbolAddress((void**)&p_t1,  g_t1);
    cudaGetSymbolAddress((void**)&p_b0t, g_b0t);
    cudaGetSymbolAddress((void**)&p_P,   g_P);
    cudaGetSymbolAddress((void**)&p_L,   g_L);
    cudaGetSymbolAddress((void**)&p_v,   g_v);

    __half *xnh,*xh,*vnh,*h1h,*reh,*rel;
    __half *qh,*ql,*keh,*kvh,*Sh,*Sl;
    __half *wb0h,*wqkvh,*wkrh,*w11h,*w12h;
    cudaGetSymbolAddress((void**)&xnh, g_xnh);
    cudaGetSymbolAddress((void**)&xh,  g_xh);
    cudaGetSymbolAddress((void**)&vnh, g_vnh);
    cudaGetSymbolAddress((void**)&h1h, g_h1h);
    cudaGetSymbolAddress((void**)&reh, g_reh); cudaGetSymbolAddress((void**)&rel, g_rel_);
    cudaGetSymbolAddress((void**)&qh,  g_qh);  cudaGetSymbolAddress((void**)&ql,  g_ql);
    cudaGetSymbolAddress((void**)&keh, g_keh);
    cudaGetSymbolAddress((void**)&kvh, g_kvh);
    cudaGetSymbolAddress((void**)&Sh,  g_Sh);  cudaGetSymbolAddress((void**)&Sl,  g_Sl);
    cudaGetSymbolAddress((void**)&wb0h, g_wb0h);
    cudaGetSymbolAddress((void**)&wqkvh, g_wqkvh);
    cudaGetSymbolAddress((void**)&wkrh, g_wkrh);
    cudaGetSymbolAddress((void**)&w11h, g_w11h);
    cudaGetSymbolAddress((void**)&w12h, g_w12h);

    cudaFuncSetAttribute((const void*)gemm128<0,2>, cudaFuncAttributeMaxDynamicSharedMemorySize, GSMEM2P);
    cudaFuncSetAttribute((const void*)gemm128<2,1>, cudaFuncAttributeMaxDynamicSharedMemorySize, GSMEM1P);
    cudaFuncSetAttribute(gemm_big_relu, cudaFuncAttributeMaxDynamicSharedMemorySize, GSMEMBIG);
    cudaFuncSetAttribute(gemm_qkv_big,  cudaFuncAttributeMaxDynamicSharedMemorySize, GSMEMBIG);
    cudaFuncSetAttribute(att_mma,       cudaFuncAttributeMaxDynamicSharedMemorySize, ATT_SMEM);

    WTab tab;
    tab.W[0]=w_b0; tab.Th[0]=wb0h;              tab.K[0]=EE;   tab.N[0]=HIDD;
    tab.W[1]=wq;   tab.Th[1]=wqkvh;             tab.K[1]=HIDD; tab.N[1]=EE;
    tab.W[2]=wke;  tab.Th[2]=wqkvh + 512*HIDD;  tab.K[2]=HIDD; tab.N[2]=EE;
    tab.W[3]=wkv;  tab.Th[3]=wqkvh + 1024*HIDD; tab.K[3]=HIDD; tab.N[3]=EE;
    tab.W[4]=wkr;  tab.Th[4]=wkrh;              tab.K[4]=EE;   tab.N[4]=EE;
    tab.W[5]=w11;  tab.Th[5]=w11h;              tab.K[5]=EE;   tab.N[5]=HIDD;
    tab.W[6]=w12;  tab.Th[6]=w12h;              tab.K[6]=HIDD; tab.N[6]=EE;
    int total = 0;
    for (int i = 0; i < 7; i++){
        tab.off[i] = total;
        total += (tab.K[i]/32) * (tab.N[i]/32);
    }
    tab.off[7] = total;
    convWT_all<<<total, 256>>>(tab);
    convA<<<(RFULL*EE + 255)/256, 256>>>(rel_enc, reh, rel, RFULL*EE);

    // 1) LN0 -> fp16
    ln_h<<<MR, 256>>>(values, ln0_g, ln0_b, xnh);
    // 2) x = relu(xn @ w_b0 + b_b0)   [1-pass]
    gemm_big_relu<<<dim3(HIDD/256, MR/128), 256, GSMEMBIG>>>(
        xnh, wb0h, b_b0, xh, MR, HIDD, EE);
    // 3) merged q/ke/kv               [1-pass]
    gemm_qkv_big<<<dim3(6, MR/128), 256, GSMEMBIG>>>(
        xh, wqkvh, bq, bke, bkv, p_q, p_ke, qh, ql, keh, kvh, MR, HIDD);
    // 4) kr_table                     [2-pass, error-sensitive, tiny]
    gemm128<0,2><<<dim3(EE/128, 2), 256, GSMEM2P>>>(
        reh, rel, wkrh, bkr, nullptr, p_krt, RFULL, EE, EE);
    // 5) t1 / bias0
    proj8<<<RFULL, 256>>>(p_krt, wab1, bab1, p_t1);
    proj8<<<MR, 256>>>(p_ke, wab0, bab0, p_b0t);
    // 6) P
    pkernel<<<dim3(MR/128, HH), 128>>>(p_q, p_krt, p_t1, p_P);
    // 7) logits (2-pass q)
    logits_mma<<<dim3(36, BB*HH), 128>>>(qh, ql, keh, p_P, p_b0t, p_L);
    // 8) softmax -> fp16 hi/lo
    softmax_kernel<<<dim3(SS, BB*HH), 128>>>(p_L, Sh, Sl);
    // 9) att (2-pass scores) + residual
    att_mma<<<dim3(8, BB*HH), 128, ATT_SMEM>>>(Sh, Sl, kvh, values, p_v);
    // 10) LN1 -> fp16
    ln_h<<<MR, 256>>>(p_v, ln1_g, ln1_b, vnh);
    // 11) h1 = relu(vn @ w11 + b11)   [1-pass]
    gemm_big_relu<<<dim3(HIDD/256, MR/128), 256, GSMEMBIG>>>(
        vnh, w11h, b11, h1h, MR, HIDD, EE);
    // 12) out = v + h1 @ w12 + b12    [1-pass]
    gemm128<2,1><<<dim3(EE/128, MR/128), 256, GSMEM1P>>>(
        h1h, nullptr, w12h, b12, p_v, out, MR, EE, HIDD);
}

// round 13
// speedup vs baseline: 1.7728x; 1.0318x over previous
#include <cuda_runtime.h>
#include <cuda_fp16.h>
#include <cstdint>
#include <cstddef>

#define BB 4
#define SS 512
#define EE 512
#define HIDD 2048
#define HH 8
#define DD 64
#define RFULL 201
#define RUSE 101
#define MR (BB*SS)   // 2048

// ---------------- fp32 scratch ----------------------------------------------
__device__ __align__(128) float g_q [MR*EE];
__device__ __align__(128) float g_ke[MR*EE];
__device__ __align__(128) float g_krt[RFULL*EE];
__device__ __align__(128) float g_t1[RFULL*HH];
__device__ __align__(128) float g_b0t[MR*HH];
__device__ __align__(128) float g_P[(size_t)MR*HH*RUSE];
__device__ __align__(128) float g_v [MR*EE];

// ---------------- fp16 scratch ----------------------------------------------
__device__ __align__(128) __half g_xnh[MR*EE];
__device__ __align__(128) __half g_xh [MR*HIDD];
__device__ __align__(128) __half g_vnh[MR*EE];
__device__ __align__(128) __half g_h1h[MR*HIDD];
__device__ __align__(128) __half g_reh[RFULL*EE + 64], g_rel_[RFULL*EE + 64];
__device__ __align__(128) __half g_qh [MR*EE], g_ql [MR*EE];
__device__ __align__(128) __half g_keh[MR*EE];
__device__ __align__(128) __half g_kvh[MR*EE];
// weights, transposed to [N][K], single fp16
__device__ __align__(128) __half g_wb0h[HIDD*EE];
__device__ __align__(128) __half g_wqkvh[3*EE*HIDD];
__device__ __align__(128) __half g_wkrh[EE*EE];
__device__ __align__(128) __half g_w11h[HIDD*EE];
__device__ __align__(128) __half g_w12h[EE*HIDD];

// ---------------- PTX helpers -----------------------------------------------
__device__ __forceinline__ uint32_t s2u(const void* p){
    uint32_t a;
    asm("{ .reg .u64 t; cvta.to.shared.u64 t, %1; cvt.u32.u64 %0, t; }" : "=r"(a) : "l"(p));
    return a;
}
__device__ __forceinline__ void cpa16(uint32_t dst, const void* src, uint32_t sz){
    asm volatile("cp.async.cg.shared.global [%0], [%1], 16, %2;" :: "r"(dst), "l"(src), "r"(sz));
}
__device__ __forceinline__ void cpcommit(){ asm volatile("cp.async.commit_group;" ::: "memory"); }
__device__ __forceinline__ void cpwait0(){ asm volatile("cp.async.wait_group 0;" ::: "memory"); }
__device__ __forceinline__ void cpwait1(){ asm volatile("cp.async.wait_group 1;" ::: "memory"); }

__device__ __forceinline__ void ldsm4(uint32_t* r, uint32_t addr){
    asm volatile("ldmatrix.sync.aligned.m8n8.x4.shared.b16 {%0,%1,%2,%3}, [%4];"
        : "=r"(r[0]), "=r"(r[1]), "=r"(r[2]), "=r"(r[3]) : "r"(addr));
}
__device__ __forceinline__ void ldsm4t(uint32_t* r, uint32_t addr){
    asm volatile("ldmatrix.sync.aligned.m8n8.x4.trans.shared.b16 {%0,%1,%2,%3}, [%4];"
        : "=r"(r[0]), "=r"(r[1]), "=r"(r[2]), "=r"(r[3]) : "r"(addr));
}
__device__ __forceinline__ void mma16816(float* d, const uint32_t* a, const uint32_t* b){
    asm volatile("mma.sync.aligned.m16n8k16.row.col.f32.f16.f16.f32 "
        "{%0,%1,%2,%3}, {%4,%5,%6,%7}, {%8,%9}, {%0,%1,%2,%3};"
        : "+f"(d[0]), "+f"(d[1]), "+f"(d[2]), "+f"(d[3])
        : "r"(a[0]), "r"(a[1]), "r"(a[2]), "r"(a[3]), "r"(b[0]), "r"(b[1]));
}
__device__ __forceinline__ uint32_t packh(__half a, __half b){
    return (uint32_t)__half_as_ushort(a) | ((uint32_t)__half_as_ushort(b) << 16);
}

// geometry: k-chunk 64, rows padded to 72 halves (144 B)
#define KC 64
#define KSTRIDE 72
#define ROWB 144
#define TILE_B (128*ROWB)                 // 18432
#define STAGE1P (2*TILE_B)
#define GSMEM1P (2*STAGE1P)
#define STAGE2P (3*TILE_B)
#define GSMEM2P (2*STAGE2P)

#define TILE_A2 (128*ROWB)
#define TILE_B2 (256*ROWB)
#define STAGEBIG (TILE_A2 + TILE_B2)
#define GSMEMBIG (2*STAGEBIG)

// flash attention tiles: 64x64 fp16, stride 72
#define ATILE_B (64*ROWB)                 // 9216
#define FA_SMEM (6*ATILE_B)               // 55296: qh, ql, 2 stages x (ke, kv)

// ---------------- loaders ----------------------------------------------------
template<int TILES>
__device__ __forceinline__ void load_chunk128(uint32_t stage, int tid,
    const __half* __restrict__ A0, const __half* __restrict__ A1,
    const __half* __restrict__ Bh,
    int m0, int n0, int k0, int M, int K)
{
    #pragma unroll
    for (int t = 0; t < TILES; t++){
        const __half* gp = (t==0)?A0:(t==TILES-1)?Bh:A1;
        int row0 = (t < TILES-1) ? m0 : n0;
        uint32_t tb = stage + t*TILE_B;
        #pragma unroll
        for (int i = 0; i < 4; i++){
            int s = i*256 + tid;
            int r = s >> 3, seg = s & 7;
            int gr = row0 + r;
            uint32_t sz = 16u;
            if (t < TILES-1 && gr >= M){ sz = 0u; gr = M - 1; }
            cpa16(tb + (uint32_t)(r*ROWB + seg*16),
                  gp + (size_t)gr*K + k0 + seg*8, sz);
        }
    }
    cpcommit();
}

__device__ __forceinline__ void load_chunk_big(uint32_t stage, int tid,
    const __half* __restrict__ Ah, const __half* __restrict__ Bh,
    int m0, int n0, int k0, int K)
{
    #pragma unroll
    for (int i = 0; i < 4; i++){
        int s = i*256 + tid;
        int r = s >> 3, seg = s & 7;
        cpa16(stage + (uint32_t)(r*ROWB + seg*16),
              Ah + (size_t)(m0 + r)*K + k0 + seg*8, 16u);
    }
    uint32_t tb = stage + TILE_A2;
    #pragma unroll
    for (int i = 0; i < 8; i++){
        int s = i*256 + tid;
        int r = s >> 3, seg = s & 7;
        cpa16(tb + (uint32_t)(r*ROWB + seg*16),
              Bh + (size_t)(n0 + r)*K + k0 + seg*8, 16u);
    }
    cpcommit();
}

// ---------------- 128x128 mainloop (PASSES = 1 or 2) -------------------------
template<int PASSES>
__device__ __forceinline__ void mainloop128(uint32_t sb, int tid, int lane, int warp,
    const __half* A0, const __half* A1, const __half* Bh,
    int m0, int n0, int M, int K, float acc[4][4][4])
{
    const int TILES = PASSES + 1;
    const int STG = TILES*TILE_B;
    int a_row  = (warp >> 2)*64 + (lane & 15);
    int a_col8 = (lane >> 4)*8;
    int b_row  = (warp & 3)*32 + (lane & 7) + ((lane & 16) ? 8 : 0);
    int b_col8 = ((lane & 8) ? 8 : 0);

    const int NC = K / KC;
    uint32_t st0 = sb, st1 = sb + STG;
    load_chunk128<TILES>(st0, tid, A0, A1, Bh, m0, n0, 0, M, K);

    for (int c = 0; c < NC; c++){
        uint32_t cur = (c & 1) ? st1 : st0;
        if (c + 1 < NC)
            load_chunk128<TILES>((c & 1) ? st0 : st1, tid, A0, A1, Bh, m0, n0, (c+1)*KC, M, K);
        if (c + 1 < NC) cpwait1(); else cpwait0();
        __syncthreads();

        uint32_t cA0 = cur, cA1 = cur + TILE_B, cB = cur + (TILES-1)*TILE_B;
        #pragma unroll
        for (int ks = 0; ks < 4; ks++){
            int k0 = ks*16;
            uint32_t a0[4][4], a1[4][4], bh[2][4];
            #pragma unroll
            for (int mt = 0; mt < 4; mt++){
                uint32_t off = (uint32_t)((a_row + mt*16)*KSTRIDE + k0 + a_col8)*2u;
                ldsm4(a0[mt], cA0 + off);
                if (PASSES == 2) ldsm4(a1[mt], cA1 + off);
            }
            #pragma unroll
            for (int p = 0; p < 2; p++){
                uint32_t off = (uint32_t)((b_row + p*16)*KSTRIDE + k0 + b_col8)*2u;
                ldsm4(bh[p], cB + off);
            }
            #pragma unroll
            for (int mt = 0; mt < 4; mt++)
                #pragma unroll
                for (int nt = 0; nt < 4; nt++)
                    mma16816(acc[mt][nt], a0[mt], &bh[nt >> 1][(nt & 1)*2]);
            if (PASSES == 2){
                #pragma unroll
                for (int mt = 0; mt < 4; mt++)
                    #pragma unroll
                    for (int nt = 0; nt < 4; nt++)
                        mma16816(acc[mt][nt], a1[mt], &bh[nt >> 1][(nt & 1)*2]);
            }
        }
        __syncthreads();
    }
}

template<int EPI, int PASSES>
__global__ __launch_bounds__(256, 1)
void gemm128(const __half* A0, const __half* A1, const __half* Bh,
             const float* __restrict__ bias, const float* __restrict__ res,
             float* __restrict__ Cf, int M, int N, int K)
{
    extern __shared__ char smem[];
    uint32_t sb = s2u(smem);
    int tid = threadIdx.x, lane = tid & 31, warp = tid >> 5;
    int m0 = blockIdx.y*128, n0 = blockIdx.x*128;
    float acc[4][4][4];
    #pragma unroll
    for (int a = 0; a < 4; a++)
        #pragma unroll
        for (int b = 0; b < 4; b++)
            #pragma unroll
            for (int c = 0; c < 4; c++) acc[a][b][c] = 0.f;

    mainloop128<PASSES>(sb, tid, lane, warp, A0, A1, Bh, m0, n0, M, K, acc);

    int gg = lane >> 2, tig = lane & 3;
    int wm = warp >> 2, wn = warp & 3;
    #pragma unroll
    for (int mt = 0; mt < 4; mt++)
        #pragma unroll
        for (int half = 0; half < 2; half++){
            int row = m0 + wm*64 + mt*16 + gg + half*8;
            if (row >= M) continue;
            #pragma unroll
            for (int nt = 0; nt < 4; nt++){
                int col = n0 + wn*32 + nt*8 + tig*2;
                float v0 = acc[mt][nt][half*2 + 0] + bias[col];
                float v1 = acc[mt][nt][half*2 + 1] + bias[col + 1];
                size_t o = (size_t)row*N + col;
                if (EPI == 2){
                    float2 rv = *(const float2*)&res[o];
                    v0 += rv.x; v1 += rv.y;
                }
                *(float2*)&Cf[o] = make_float2(v0, v1);
            }
        }
}

// ---------------- 128x256 mainloop (single pass) -----------------------------
__device__ __forceinline__ void mainloop_big(uint32_t sb, int tid, int lane, int warp,
    const __half* Ah, const __half* Bh,
    int m0, int n0, int K, float acc[4][8][4])
{
    int a_row  = (warp >> 2)*64 + (lane & 15);
    int a_col8 = (lane >> 4)*8;
    int b_rowb = (warp & 3)*64 + (lane & 7) + ((lane & 16) ? 8 : 0);
    int b_col8 = ((lane & 8) ? 8 : 0);

    const int NC = K / KC;
    uint32_t st0 = sb, st1 = sb + STAGEBIG;
    load_chunk_big(st0, tid, Ah, Bh, m0, n0, 0, K);

    for (int c = 0; c < NC; c++){
        uint32_t cur = (c & 1) ? st1 : st0;
        if (c + 1 < NC)
            load_chunk_big((c & 1) ? st0 : st1, tid, Ah, Bh, m0, n0, (c+1)*KC, K);
        if (c + 1 < NC) cpwait1(); else cpwait0();
        __syncthreads();

        uint32_t cA = cur, cB = cur + TILE_A2;
        #pragma unroll
        for (int ks = 0; ks < 4; ks++){
            int k0 = ks*16;
            uint32_t ah[4][4];
            #pragma unroll
            for (int mt = 0; mt < 4; mt++){
                uint32_t off = (uint32_t)((a_row + mt*16)*KSTRIDE + k0 + a_col8)*2u;
                ldsm4(ah[mt], cA + off);
            }
            #pragma unroll
            for (int h2 = 0; h2 < 2; h2++){
                uint32_t bh[2][4];
                #pragma unroll
                for (int p = 0; p < 2; p++){
                    uint32_t off = (uint32_t)((b_rowb + (h2*2 + p)*16)*KSTRIDE + k0 + b_col8)*2u;
                    ldsm4(bh[p], cB + off);
                }
                #pragma unroll
                for (int mt = 0; mt < 4; mt++)
                    #pragma unroll
                    for (int j = 0; j < 4; j++)
                        mma16816(acc[mt][h2*4 + j], ah[mt], &bh[j >> 1][(j & 1)*2]);
            }
        }
        __syncthreads();
    }
}

__global__ __launch_bounds__(256, 1)
void gemm_big_relu(const __half* Ah, const __half* Bh,
                   const float* __restrict__ bias,
                   __half* __restrict__ Ch, int M, int N, int K)
{
    extern __shared__ char smem[];
    uint32_t sb = s2u(smem);
    int tid = threadIdx.x, lane = tid & 31, warp = tid >> 5;
    int m0 = blockIdx.y*128, n0 = blockIdx.x*256;
    float acc[4][8][4];
    #pragma unroll
    for (int a = 0; a < 4; a++)
        #pragma unroll
        for (int b = 0; b < 8; b++)
            #pragma unroll
            for (int c = 0; c < 4; c++) acc[a][b][c] = 0.f;

    mainloop_big(sb, tid, lane, warp, Ah, Bh, m0, n0, K, acc);

    int gg = lane >> 2, tig = lane & 3;
    int wm = warp >> 2, wn = warp & 3;
    #pragma unroll
    for (int mt = 0; mt < 4; mt++)
        #pragma unroll
        for (int half = 0; half < 2; half++){
            int row = m0 + wm*64 + mt*16 + gg + half*8;
            #pragma unroll
            for (int nt8 = 0; nt8 < 8; nt8++){
                int col = n0 + wn*64 + nt8*8 + tig*2;
                float v0 = fmaxf(acc[mt][nt8][half*2 + 0] + bias[col],     0.f);
                float v1 = fmaxf(acc[mt][nt8][half*2 + 1] + bias[col + 1], 0.f);
                size_t o = (size_t)row*N + col;
                *(uint32_t*)((char*)Ch + o*2) = packh(__float2half_rn(v0), __float2half_rn(v1));
            }
        }
}

// merged qkv
__global__ __launch_bounds__(256, 1)
void gemm_qkv_big(const __half* Ah, const __half* Bh,
                  const float* b0, const float* b1, const float* b2,
                  float* f0, float* f1,
                  __half* c0h, __half* c0l, __half* c1h, __half* c2h,
                  int M, int K)
{
    extern __shared__ char smem[];
    uint32_t sb = s2u(smem);
    int tid = threadIdx.x, lane = tid & 31, warp = tid >> 5;
    int m0 = blockIdx.y*128, n0 = blockIdx.x*256;
    float acc[4][8][4];
    #pragma unroll
    for (int a = 0; a < 4; a++)
        #pragma unroll
        for (int b = 0; b < 8; b++)
            #pragma unroll
            for (int c = 0; c < 4; c++) acc[a][b][c] = 0.f;

    mainloop_big(sb, tid, lane, warp, Ah, Bh, m0, n0, K, acc);

    int z = n0 >> 9;
    const float* bias = (z==0)?b0:(z==1)?b1:b2;
    float* Cf = (z==0)?f0:(z==1)?f1:nullptr;
    __half* Ch = (z==0)?c0h:(z==1)?c1h:c2h;
    __half* Cl = (z==0)?c0l:nullptr;
    int n0l = n0 & 511;

    int gg = lane >> 2, tig = lane & 3;
    int wm = warp >> 2, wn = warp & 3;
    #pragma unroll
    for (int mt = 0; mt < 4; mt++)
        #pragma unroll
        for (int half = 0; half < 2; half++){
            int row = m0 + wm*64 + mt*16 + gg + half*8;
            #pragma unroll
            for (int nt8 = 0; nt8 < 8; nt8++){
                int col = n0l + wn*64 + nt8*8 + tig*2;
                float v0 = acc[mt][nt8][half*2 + 0] + bias[col];
                float v1 = acc[mt][nt8][half*2 + 1] + bias[col + 1];
                size_t o = (size_t)row*512 + col;
                if (Cf) *(float2*)&Cf[o] = make_float2(v0, v1);
                __half h0 = __float2half_rn(v0);
                __half h1 = __float2half_rn(v1);
                *(uint32_t*)((char*)Ch + o*2) = packh(h0, h1);
                if (Cl){
                    __half l0 = __float2half_rn(v0 - __half2float(h0));
                    __half l1 = __float2half_rn(v1 - __half2float(h1));
                    *(uint32_t*)((char*)Cl + o*2) = packh(l0, l1);
                }
            }
        }
}

// ---------------- fused flash attention --------------------------------------
// grid (8 it, 32 bh), block 128 (4 warps; warp w owns rows i0+w*16 .. +15)
__global__ __launch_bounds__(128) void flash_att(
    const __half* __restrict__ qh, const __half* __restrict__ ql,
    const __half* __restrict__ keh, const __half* __restrict__ kvh,
    const float* __restrict__ P, const float* __restrict__ b0t,
    const float* __restrict__ vals, float* __restrict__ V)
{
    extern __shared__ char smem[];
    uint32_t sb = s2u(smem);
    int tid = threadIdx.x, lane = tid & 31, warp = tid >> 5;
    int it = blockIdx.x, bh = blockIdx.y, b = bh >> 3, h = bh & 7;
    int i0 = it*64;
    int NCH = it + 1;

    uint32_t sQH = sb, sQL = sb + ATILE_B;
    uint32_t st0 = sb + 2*ATILE_B;         // [ke, kv]
    uint32_t st1 = st0 + 2*ATILE_B;

    // load q hi/lo + chunk 0 (one group)
    #pragma unroll
    for (int t = 0; t < 2; t++){
        const __half* gp = t ? ql : qh;
        uint32_t tb = t ? sQL : sQH;
        #pragma unroll
        for (int i = 0; i < 4; i++){
            int s = i*128 + tid;
            int r = s >> 3, seg = s & 7;
            cpa16(tb + (uint32_t)(r*ROWB + seg*16),
                  gp + ((size_t)(b*SS + i0 + r))*EE + h*DD + seg*8, 16u);
        }
    }
    #pragma unroll
    for (int t = 0; t < 2; t++){
        const __half* gp = t ? kvh : keh;
        uint32_t tb = st0 + t*ATILE_B;
        #pragma unroll
        for (int i = 0; i < 4; i++){
            int s = i*128 + tid;
            int r = s >> 3, seg = s & 7;
            cpa16(tb + (uint32_t)(r*ROWB + seg*16),
                  gp + ((size_t)(b*SS + r))*EE + h*DD + seg*8, 16u);
        }
    }
    cpcommit();

    int gg = lane >> 2, tig = lane & 3;
    int a_row  = warp*16 + (lane & 15);
    int a_col8 = (lane >> 4)*8;
    int b_rowb = (lane & 7) + ((lane & 16) ? 8 : 0);
    int b_col8 = ((lane & 8) ? 8 : 0);
    int bt_row = lane & 15;
    int bt_colb = ((lane & 16) ? 8 : 0);

    int gi0 = i0 + warp*16 + gg;
    int gi1 = gi0 + 8;
    const float* Pr0 = P + ((size_t)(b*SS + gi0)*HH + h)*RUSE + 100;
    const float* Pr1 = P + ((size_t)(b*SS + gi1)*HH + h)*RUSE + 100;

    float m_st[2] = {-1e30f, -1e30f};
    float l_st[2] = {0.f, 0.f};
    float acc_o[8][4];
    #pragma unroll
    for (int nt = 0; nt < 8; nt++)
        #pragma unroll
        for (int c = 0; c < 4; c++) acc_o[nt][c] = 0.f;

    for (int c = 0; c < NCH; c++){
        uint32_t cur = (c & 1) ? st1 : st0;
        if (c + 1 < NCH){
            uint32_t nxt = (c & 1) ? st0 : st1;
            int j0n = (c + 1)*64;
            #pragma unroll
            for (int t = 0; t < 2; t++){
                const __half* gp = t ? kvh : keh;
                uint32_t tb = nxt + t*ATILE_B;
                #pragma unroll
                for (int i = 0; i < 4; i++){
                    int s = i*128 + tid;
                    int r = s >> 3, seg = s & 7;
                    cpa16(tb + (uint32_t)(r*ROWB + seg*16),
                          gp + ((size_t)(b*SS + j0n + r))*EE + h*DD + seg*8, 16u);
                }
            }
            cpcommit();
        }
        if (c + 1 < NCH) cpwait1(); else cpwait0();
        __syncthreads();

        int j0 = c*64;
        bool diag = (c == it);
        uint32_t cK = cur, cV = cur + ATILE_B;

        // ---- S = q . ke^T  (2-pass) ----
        float s_acc[8][4];
        #pragma unroll
        for (int nt = 0; nt < 8; nt++)
            #pragma unroll
            for (int e = 0; e < 4; e++) s_acc[nt][e] = 0.f;
        #pragma unroll
        for (int ks = 0; ks < 4; ks++){
            int k0 = ks*16;
            uint32_t aq[4], aql[4], bf[4][4];
            uint32_t offA = (uint32_t)(a_row*KSTRIDE + k0 + a_col8)*2u;
            ldsm4(aq,  sQH + offA);
            ldsm4(aql, sQL + offA);
            #pragma unroll
            for (int p = 0; p < 4; p++){
                uint32_t off = (uint32_t)((p*16 + b_rowb)*KSTRIDE + k0 + b_col8)*2u;
                ldsm4(bf[p], cK + off);
            }
            #pragma unroll
            for (int nt = 0; nt < 8; nt++)
                mma16816(s_acc[nt], aq, &bf[nt >> 1][(nt & 1)*2]);
            #pragma unroll
            for (int nt = 0; nt < 8; nt++)
                mma16816(s_acc[nt], aql, &bf[nt >> 1][(nt & 1)*2]);
        }

        // ---- bias + mask + online softmax ----
        float rowmax[2] = {-1e30f, -1e30f};
        #pragma unroll
        for (int nt = 0; nt < 8; nt++){
            #pragma unroll
            for (int e = 0; e < 2; e++){
                int j = j0 + nt*8 + tig*2 + e;
                float bv = b0t[(size_t)(b*SS + j)*HH + h];
                #pragma unroll
                for (int hh = 0; hh < 2; hh++){
                    int gi = hh ? gi1 : gi0;
                    int ci = hh*2 + e;
                    float val;
                    if (diag && j > gi){
                        val = -1e30f;
                    } else {
                        int off = j - gi;
                        if (off < -100) off = -100;
                        val = s_acc[nt][ci]*0.125f + (hh ? Pr1 : Pr0)[off] + bv;
                    }
                    s_acc[nt][ci] = val;
                    rowmax[hh] = fmaxf(rowmax[hh], val);
                }
            }
        }
        #pragma unroll
        for (int hh = 0; hh < 2; hh++){
            rowmax[hh] = fmaxf(rowmax[hh], __shfl_xor_sync(0xffffffffu, rowmax[hh], 1));
            rowmax[hh] = fmaxf(rowmax[hh], __shfl_xor_sync(0xffffffffu, rowmax[hh], 2));
        }
        float mnew[2], scale[2], rsum[2] = {0.f, 0.f};
        #pragma unroll
        for (int hh = 0; hh < 2; hh++){
            mnew[hh]  = fmaxf(m_st[hh], rowmax[hh]);
            scale[hh] = __expf(m_st[hh] - mnew[hh]);
            m_st[hh]  = mnew[hh];
        }
        #pragma unroll
        for (int nt = 0; nt < 8; nt++)
            #pragma unroll
            for (int ci = 0; ci < 4; ci++){
                int hh = ci >> 1;
                float p = __expf(s_acc[nt][ci] - mnew[hh]);
                s_acc[nt][ci] = p;
                rsum[hh] += p;
            }
        #pragma unroll
        for (int hh = 0; hh < 2; hh++){
            rsum[hh] += __shfl_xor_sync(0xffffffffu, rsum[hh], 1);
            rsum[hh] += __shfl_xor_sync(0xffffffffu, rsum[hh], 2);
            l_st[hh] = l_st[hh]*scale[hh] + rsum[hh];
        }
        #pragma unroll
        for (int nt = 0; nt < 8; nt++)
            #pragma unroll
            for (int ci = 0; ci < 4; ci++)
                acc_o[nt][ci] *= scale[ci >> 1];

        // ---- pack p (hi + lo) into A fragments ----
        // A-frag for k-chunk ks2 (j cols k0..k0+15):
        //   reg 0 = c0c1 of nt=2*ks2 (row gi0, k low8)
        //   reg 1 = c2c3 of nt=2*ks2 (row gi1, k low8)
        //   reg 2 = c0c1 of nt=2*ks2+1 (row gi0, k high8)
        //   reg 3 = c2c3 of nt=2*ks2+1 (row gi1, k high8)
        uint32_t pa[4][4], pl[4][4];
        #pragma unroll
        for (int ks2 = 0; ks2 < 4; ks2++){
            #pragma unroll
            for (int half8 = 0; half8 < 2; half8++){
                int nt = ks2*2 + half8;
                __half h0 = __float2half_rn(s_acc[nt][0]);
                __half h1 = __float2half_rn(s_acc[nt][1]);
                __half h2 = __float2half_rn(s_acc[nt][2]);
                __half h3 = __float2half_rn(s_acc[nt][3]);
                pa[ks2][0 + half8*2] = packh(h0, h1);
                pa[ks2][1 + half8*2] = packh(h2, h3);
                __half l0 = __float2half_rn(s_acc[nt][0] - __half2float(h0));
                __half l1 = __float2half_rn(s_acc[nt][1] - __half2float(h1));
                __half l2 = __float2half_rn(s_acc[nt][2] - __half2float(h2));
                __half l3 = __float2half_rn(s_acc[nt][3] - __half2float(h3));
                pl[ks2][0 + half8*2] = packh(l0, l1);
                pl[ks2][1 + half8*2] = packh(l2, l3);
            }
        }

        // ---- O += P . V  (2-pass) ----
        #pragma unroll
        for (int ks2 = 0; ks2 < 4; ks2++){
            int k0 = ks2*16;
            uint32_t bv[4][4];
            #pragma unroll
            for (int grp = 0; grp < 4; grp++){
                uint32_t off = (uint32_t)((k0 + bt_row)*KSTRIDE + grp*16 + bt_colb)*2u;
                ldsm4t(bv[grp], cV + off);
            }
            #pragma unroll
            for (int nt = 0; nt < 8; nt++)
                mma16816(acc_o[nt], pa[ks2], &bv[nt >> 1][(nt & 1)*2]);
            #pragma unroll
            for (int nt = 0; nt < 8; nt++)
                mma16816(acc_o[nt], pl[ks2], &bv[nt >> 1][(nt & 1)*2]);
        }
        __syncthreads();
    }

    // ---- finalize: O / l + residual ----
    float inv[2] = {1.f / l_st[0], 1.f / l_st[1]};
    #pragma unroll
    for (int hh = 0; hh < 2; hh++){
        int gi = hh ? gi1 : gi0;
        #pragma unroll
        for (int nt = 0; nt < 8; nt++){
            int d = nt*8 + tig*2;
            size_t o = ((size_t)(b*SS + gi))*EE + h*DD + d;
            float2 rv = *(const float2*)&vals[o];
            *(float2*)&V[o] = make_float2(acc_o[nt][hh*2 + 0]*inv[hh] + rv.x,
                                          acc_o[nt][hh*2 + 1]*inv[hh] + rv.y);
        }
    }
}

// ---------------- fused weight conversion ------------------------------------
struct WTab {
    const float* W[7];
    __half* Th[7];
    int K[7];
    int N[7];
    int off[8];
};

__global__ void convWT_all(WTab tab)
{
    __shared__ float t[32][33];
    int bid = blockIdx.x;
    int e = 0;
    #pragma unroll
    for (int i = 1; i < 7; i++) if (bid >= tab.off[i]) e = i;
    int local = bid - tab.off[e];
    const float* W = tab.W[e];
    __half* Th = tab.Th[e];
    int K = tab.K[e], N = tab.N[e];
    int ntiles = N >> 5;
    int kt = local / ntiles, ct = local - kt*ntiles;
    int by = kt*32, bx = ct*32;
    int lx = threadIdx.x & 31, ly = threadIdx.x >> 5;
    #pragma unroll
    for (int i = 0; i < 32; i += 8)
        t[ly + i][lx] = W[(size_t)(by + ly + i)*N + bx + lx];
    __syncthreads();
    #pragma unroll
    for (int i = 0; i < 32; i += 8){
        int n = bx + ly + i, k = by + lx;
        Th[(size_t)n*K + k] = __float2half_rn(t[lx][ly + i]);
    }
}

__global__ void convA(const float* __restrict__ X, __half* __restrict__ H,
                      __half* __restrict__ L, int n)
{
    int i = blockIdx.x*256 + threadIdx.x;
    if (i < n){
        float x = X[i];
        __half h = __float2half_rn(x);
        H[i] = h;
        L[i] = __float2half_rn(x - __half2float(h));
    }
}

// ---------------- LayerNorm -> fp16 hi only ---------------------------------
__global__ void ln_h(const float* __restrict__ X, const float* __restrict__ g,
                     const float* __restrict__ bt, __half* __restrict__ Yh)
{
    int row = blockIdx.x;
    int tid = threadIdx.x;
    const float* x = X + (size_t)row*EE;
    float a = x[tid], c = x[tid + 256];
    float s  = a + c;
    float s2 = a*a + c*c;
    #pragma unroll
    for (int o = 16; o > 0; o >>= 1){
        s  += __shfl_xor_sync(0xffffffffu, s,  o);
        s2 += __shfl_xor_sync(0xffffffffu, s2, o);
    }
    __shared__ float sa[8], sbm[8];
    if ((tid & 31) == 0){ sa[tid>>5] = s; sbm[tid>>5] = s2; }
    __syncthreads();
    float ts = 0.f, ts2 = 0.f;
    #pragma unroll
    for (int w = 0; w < 8; w++){ ts += sa[w]; ts2 += sbm[w]; }
    float mean = ts * (1.f/512.f);
    float var  = ts2 * (1.f/512.f) - mean*mean;
    float r = rsqrtf(var + 1e-3f);
    Yh[(size_t)row*EE + tid]       = __float2half_rn((a - mean)*r*g[tid]       + bt[tid]);
    Yh[(size_t)row*EE + tid + 256] = __float2half_rn((c - mean)*r*g[tid + 256] + bt[tid + 256]);
}

// ---------------- tiny N=8 projection ---------------------------------------
__global__ void proj8(const float* __restrict__ X, const float* __restrict__ Wp,
                      const float* __restrict__ bp, float* __restrict__ Y)
{
    int row = blockIdx.x;
    int tid = threadIdx.x;
    int h = tid & 7, seg = tid >> 3;
    const float* x = X + (size_t)row*EE;
    float s = 0.f;
    #pragma unroll
    for (int k = 0; k < 16; k++){
        int kk = seg*16 + k;
        s += x[kk] * Wp[kk*HH + h];
    }
    __shared__ float sm[256];
    sm[tid] = s;
    __syncthreads();
    if (tid < 8){
        float acc = bp[tid];
        #pragma unroll
        for (int sg = 0; sg < 32; sg++) acc += sm[sg*8 + tid];
        Y[(size_t)row*HH + tid] = acc;
    }
}

// ---------------- P[m,h,r] --------------------------------------------------
__global__ __launch_bounds__(128) void pkernel(
    const float* __restrict__ q, const float* __restrict__ krt,
    const float* __restrict__ t1, float* __restrict__ P)
{
    int h = blockIdx.y;
    int m = blockIdx.x * 128 + threadIdx.x;
    float qr[64];
    const float4* qp = (const float4*)(q + (size_t)m*EE + h*DD);
    #pragma unroll
    for (int t = 0; t < 16; t++){
        float4 v = qp[t];
        qr[t*4+0]=v.x; qr[t*4+1]=v.y; qr[t*4+2]=v.z; qr[t*4+3]=v.w;
    }
    float* Pp = P + ((size_t)m*HH + h)*RUSE;
    const float* kbase = krt + h*DD;
    for (int r = 0; r < RUSE; r++){
        const float4* kp = (const float4*)(kbase + (size_t)r*EE);
        float acc = 0.f;
        #pragma unroll
        for (int t = 0; t < 16; t++){
            float4 k4 = __ldg(&kp[t]);
            acc += qr[t*4+0]*k4.x + qr[t*4+1]*k4.y + qr[t*4+2]*k4.z + qr[t*4+3]*k4.w;
        }
        Pp[r] = acc + t1[r*HH + h];
    }
}

// ---------------- launch ----------------------------------------------------
extern "C" void kernel_launch(void* const* d_in, const int* in_sizes, int n_in,
                              void* d_out, int out_size)
{
    const float* values  = (const float*)d_in[0];
    const float* rel_enc = (const float*)d_in[2];
    const float* ln0_g   = (const float*)d_in[3];
    const float* ln0_b   = (const float*)d_in[4];
    const float* w_b0    = (const float*)d_in[5];
    const float* b_b0    = (const float*)d_in[6];
    const float* wq      = (const float*)d_in[7];
    const float* bq      = (const float*)d_in[8];
    const float* wke     = (const float*)d_in[9];
    const float* bke     = (const float*)d_in[10];
    const float* wkv     = (const float*)d_in[11];
    const float* bkv     = (const float*)d_in[12];
    const float* wkr     = (const float*)d_in[13];
    const float* bkr     = (const float*)d_in[14];
    const float* wab0    = (const float*)d_in[15];
    const float* bab0    = (const float*)d_in[16];
    const float* wab1    = (const float*)d_in[17];
    const float* bab1    = (const float*)d_in[18];
    const float* ln1_g   = (const float*)d_in[19];
    const float* ln1_b   = (const float*)d_in[20];
    const float* w11     = (const float*)d_in[21];
    const float* b11     = (const float*)d_in[22];
    const float* w12     = (const float*)d_in[23];
    const float* b12     = (const float*)d_in[24];
    float* out = (float*)d_out;

    float *p_q,*p_ke,*p_krt,*p_t1,*p_b0t,*p_P,*p_v;
    cudaGetSymbolAddress((void**)&p_q,   g_q);
    cudaGetSymbolAddress((void**)&p_ke,  g_ke);
    cudaGetSymbolAddress((void**)&p_krt, g_krt);
    cudaGetSymbolAddress((void**)&p_t1,  g_t1);
    cudaGetSymbolAddress((void**)&p_b0t, g_b0t);
    cudaGetSymbolAddress((void**)&p_P,   g_P);
    cudaGetSymbolAddress((void**)&p_v,   g_v);

    __half *xnh,*xh,*vnh,*h1h,*reh,*rel;
    __half *qh,*ql,*keh,*kvh;
    __half *wb0h,*wqkvh,*wkrh,*w11h,*w12h;
    cudaGetSymbolAddress((void**)&xnh, g_xnh);
    cudaGetSymbolAddress((void**)&xh,  g_xh);
    cudaGetSymbolAddress((void**)&vnh, g_vnh);
    cudaGetSymbolAddress((void**)&h1h, g_h1h);
    cudaGetSymbolAddress((void**)&reh, g_reh); cudaGetSymbolAddress((void**)&rel, g_rel_);
    cudaGetSymbolAddress((void**)&qh,  g_qh);  cudaGetSymbolAddress((void**)&ql,  g_ql);
    cudaGetSymbolAddress((void**)&keh, g_keh);
    cudaGetSymbolAddress((void**)&kvh, g_kvh);
    cudaGetSymbolAddress((void**)&wb0h, g_wb0h);
    cudaGetSymbolAddress((void**)&wqkvh, g_wqkvh);
    cudaGetSymbolAddress((void**)&wkrh, g_wkrh);
    cudaGetSymbolAddress((void**)&w11h, g_w11h);
    cudaGetSymbolAddress((void**)&w12h, g_w12h);

    cudaFuncSetAttribute((const void*)gemm128<0,2>, cudaFuncAttributeMaxDynamicSharedMemorySize, GSMEM2P);
    cudaFuncSetAttribute((const void*)gemm128<2,1>, cudaFuncAttributeMaxDynamicSharedMemorySize, GSMEM1P);
    cudaFuncSetAttribute(gemm_big_relu, cudaFuncAttributeMaxDynamicSharedMemorySize, GSMEMBIG);
    cudaFuncSetAttribute(gemm_qkv_big,  cudaFuncAttributeMaxDynamicSharedMemorySize, GSMEMBIG);
    cudaFuncSetAttribute(flash_att,     cudaFuncAttributeMaxDynamicSharedMemorySize, FA_SMEM);

    WTab tab;
    tab.W[0]=w_b0; tab.Th[0]=wb0h;              tab.K[0]=EE;   tab.N[0]=HIDD;
    tab.W[1]=wq;   tab.Th[1]=wqkvh;             tab.K[1]=HIDD; tab.N[1]=EE;
    tab.W[2]=wke;  tab.Th[2]=wqkvh + 512*HIDD;  tab.K[2]=HIDD; tab.N[2]=EE;
    tab.W[3]=wkv;  tab.Th[3]=wqkvh + 1024*HIDD; tab.K[3]=HIDD; tab.N[3]=EE;
    tab.W[4]=wkr;  tab.Th[4]=wkrh;              tab.K[4]=EE;   tab.N[4]=EE;
    tab.W[5]=w11;  tab.Th[5]=w11h;              tab.K[5]=EE;   tab.N[5]=HIDD;
    tab.W[6]=w12;  tab.Th[6]=w12h;              tab.K[6]=HIDD; tab.N[6]=EE;
    int total = 0;
    for (int i = 0; i < 7; i++){
        tab.off[i] = total;
        total += (tab.K[i]/32) * (tab.N[i]/32);
    }
    tab.off[7] = total;
    convWT_all<<<total, 256>>>(tab);
    convA<<<(RFULL*EE + 255)/256, 256>>>(rel_enc, reh, rel, RFULL*EE);

    // 1) LN0 -> fp16
    ln_h<<<MR, 256>>>(values, ln0_g, ln0_b, xnh);
    // 2) x = relu(xn @ w_b0 + b_b0)
    gemm_big_relu<<<dim3(HIDD/256, MR/128), 256, GSMEMBIG>>>(
        xnh, wb0h, b_b0, xh, MR, HIDD, EE);
    // 3) merged q/ke/kv
    gemm_qkv_big<<<dim3(6, MR/128), 256, GSMEMBIG>>>(
        xh, wqkvh, bq, bke, bkv, p_q, p_ke, qh, ql, keh, kvh, MR, HIDD);
    // 4) kr_table (2-pass)
    gemm128<0,2><<<dim3(EE/128, 2), 256, GSMEM2P>>>(
        reh, rel, wkrh, bkr, nullptr, p_krt, RFULL, EE, EE);
    // 5) t1 / bias0
    proj8<<<RFULL, 256>>>(p_krt, wab1, bab1, p_t1);
    proj8<<<MR, 256>>>(p_ke, wab0, bab0, p_b0t);
    // 6) P
    pkernel<<<dim3(MR/128, HH), 128>>>(p_q, p_krt, p_t1, p_P);
    // 7) fused flash attention -> v
    flash_att<<<dim3(8, BB*HH), 128, FA_SMEM>>>(
        qh, ql, keh, kvh, p_P, p_b0t, values, p_v);
    // 8) LN1 -> fp16
    ln_h<<<MR, 256>>>(p_v, ln1_g, ln1_b, vnh);
    // 9) h1 = relu(vn @ w11 + b11)
    gemm_big_relu<<<dim3(HIDD/256, MR/128), 256, GSMEMBIG>>>(
        vnh, w11h, b11, h1h, MR, HIDD, EE);
    // 10) out = v + h1 @ w12 + b12
    gemm128<2,1><<<dim3(EE/128, MR/128), 256, GSMEM1P>>>(
        h1h, nullptr, w12h, b12, p_v, out, MR, EE, HIDD);
}

// round 14
// speedup vs baseline: 1.7969x; 1.0136x over previous
#include <cuda_runtime.h>
#include <cuda_fp16.h>
#include <cstdint>
#include <cstddef>

#define BB 4
#define SS 512
#define EE 512
#define HIDD 2048
#define HH 8
#define DD 64
#define RFULL 201
#define RUSE 101
#define MR (BB*SS)   // 2048

// ---------------- fp32 scratch ----------------------------------------------
__device__ __align__(128) float g_q [MR*EE];
__device__ __align__(128) float g_ke[MR*EE];
__device__ __align__(128) float g_krt[RFULL*EE];
__device__ __align__(128) float g_t1[RFULL*HH];
__device__ __align__(128) float g_b0t[MR*HH];
__device__ __align__(128) float g_P[(size_t)MR*HH*RUSE];
__device__ __align__(128) float g_v [MR*EE];

// ---------------- fp16 scratch ----------------------------------------------
__device__ __align__(128) __half g_xnh[MR*EE];
__device__ __align__(128) __half g_xh [MR*HIDD];
__device__ __align__(128) __half g_vnh[MR*EE];
__device__ __align__(128) __half g_h1h[MR*HIDD];
__device__ __align__(128) __half g_reh[RFULL*EE + 64], g_rel_[RFULL*EE + 64];
__device__ __align__(128) __half g_qh [MR*EE], g_ql [MR*EE];
__device__ __align__(128) __half g_keh[MR*EE];
__device__ __align__(128) __half g_kvh[MR*EE];
// weights, transposed to [N][K], single fp16
__device__ __align__(128) __half g_wb0h[HIDD*EE];
__device__ __align__(128) __half g_wqkvh[3*EE*HIDD];
__device__ __align__(128) __half g_wkrh[EE*EE];
__device__ __align__(128) __half g_w11h[HIDD*EE];
__device__ __align__(128) __half g_w12h[EE*HIDD];

// ---------------- PTX helpers -----------------------------------------------
__device__ __forceinline__ uint32_t s2u(const void* p){
    uint32_t a;
    asm("{ .reg .u64 t; cvta.to.shared.u64 t, %1; cvt.u32.u64 %0, t; }" : "=r"(a) : "l"(p));
    return a;
}
__device__ __forceinline__ void cpa16(uint32_t dst, const void* src, uint32_t sz){
    asm volatile("cp.async.cg.shared.global [%0], [%1], 16, %2;" :: "r"(dst), "l"(src), "r"(sz));
}
__device__ __forceinline__ void cpcommit(){ asm volatile("cp.async.commit_group;" ::: "memory"); }
__device__ __forceinline__ void cpwait0(){ asm volatile("cp.async.wait_group 0;" ::: "memory"); }
__device__ __forceinline__ void cpwait1(){ asm volatile("cp.async.wait_group 1;" ::: "memory"); }

__device__ __forceinline__ void ldsm4(uint32_t* r, uint32_t addr){
    asm volatile("ldmatrix.sync.aligned.m8n8.x4.shared.b16 {%0,%1,%2,%3}, [%4];"
        : "=r"(r[0]), "=r"(r[1]), "=r"(r[2]), "=r"(r[3]) : "r"(addr));
}
__device__ __forceinline__ void ldsm4t(uint32_t* r, uint32_t addr){
    asm volatile("ldmatrix.sync.aligned.m8n8.x4.trans.shared.b16 {%0,%1,%2,%3}, [%4];"
        : "=r"(r[0]), "=r"(r[1]), "=r"(r[2]), "=r"(r[3]) : "r"(addr));
}
__device__ __forceinline__ void mma16816(float* d, const uint32_t* a, const uint32_t* b){
    asm volatile("mma.sync.aligned.m16n8k16.row.col.f32.f16.f16.f32 "
        "{%0,%1,%2,%3}, {%4,%5,%6,%7}, {%8,%9}, {%0,%1,%2,%3};"
        : "+f"(d[0]), "+f"(d[1]), "+f"(d[2]), "+f"(d[3])
        : "r"(a[0]), "r"(a[1]), "r"(a[2]), "r"(a[3]), "r"(b[0]), "r"(b[1]));
}
__device__ __forceinline__ uint32_t packh(__half a, __half b){
    return (uint32_t)__half_as_ushort(a) | ((uint32_t)__half_as_ushort(b) << 16);
}

// geometry: k-chunk 64, rows padded to 72 halves (144 B)
#define KC 64
#define KSTRIDE 72
#define ROWB 144
#define TILE_B (128*ROWB)                 // 18432
#define STAGE1P (2*TILE_B)
#define GSMEM1P (2*STAGE1P)
#define STAGE2P (3*TILE_B)
#define GSMEM2P (2*STAGE2P)

#define TILE_A2 (128*ROWB)
#define TILE_B2 (256*ROWB)
#define STAGEBIG (TILE_A2 + TILE_B2)
#define GSMEMBIG (2*STAGEBIG)

// flash attention: q tile 128x64, kv tiles 64x64, stride 72
#define QTILE_B (128*ROWB)                // 18432
#define ATILE_B (64*ROWB)                 // 9216
#define FA_SMEM (2*QTILE_B + 4*ATILE_B)   // 73728

// ---------------- loaders ----------------------------------------------------
template<int TILES>
__device__ __forceinline__ void load_chunk128(uint32_t stage, int tid,
    const __half* __restrict__ A0, const __half* __restrict__ A1,
    const __half* __restrict__ Bh,
    int m0, int n0, int k0, int M, int K)
{
    #pragma unroll
    for (int t = 0; t < TILES; t++){
        const __half* gp = (t==0)?A0:(t==TILES-1)?Bh:A1;
        int row0 = (t < TILES-1) ? m0 : n0;
        uint32_t tb = stage + t*TILE_B;
        #pragma unroll
        for (int i = 0; i < 4; i++){
            int s = i*256 + tid;
            int r = s >> 3, seg = s & 7;
            int gr = row0 + r;
            uint32_t sz = 16u;
            if (t < TILES-1 && gr >= M){ sz = 0u; gr = M - 1; }
            cpa16(tb + (uint32_t)(r*ROWB + seg*16),
                  gp + (size_t)gr*K + k0 + seg*8, sz);
        }
    }
    cpcommit();
}

__device__ __forceinline__ void load_chunk_big(uint32_t stage, int tid,
    const __half* __restrict__ Ah, const __half* __restrict__ Bh,
    int m0, int n0, int k0, int K)
{
    #pragma unroll
    for (int i = 0; i < 4; i++){
        int s = i*256 + tid;
        int r = s >> 3, seg = s & 7;
        cpa16(stage + (uint32_t)(r*ROWB + seg*16),
              Ah + (size_t)(m0 + r)*K + k0 + seg*8, 16u);
    }
    uint32_t tb = stage + TILE_A2;
    #pragma unroll
    for (int i = 0; i < 8; i++){
        int s = i*256 + tid;
        int r = s >> 3, seg = s & 7;
        cpa16(tb + (uint32_t)(r*ROWB + seg*16),
              Bh + (size_t)(n0 + r)*K + k0 + seg*8, 16u);
    }
    cpcommit();
}

// ---------------- 128x128 mainloop (PASSES = 1 or 2) -------------------------
template<int PASSES>
__device__ __forceinline__ void mainloop128(uint32_t sb, int tid, int lane, int warp,
    const __half* A0, const __half* A1, const __half* Bh,
    int m0, int n0, int M, int K, float acc[4][4][4])
{
    const int TILES = PASSES + 1;
    const int STG = TILES*TILE_B;
    int a_row  = (warp >> 2)*64 + (lane & 15);
    int a_col8 = (lane >> 4)*8;
    int b_row  = (warp & 3)*32 + (lane & 7) + ((lane & 16) ? 8 : 0);
    int b_col8 = ((lane & 8) ? 8 : 0);

    const int NC = K / KC;
    uint32_t st0 = sb, st1 = sb + STG;
    load_chunk128<TILES>(st0, tid, A0, A1, Bh, m0, n0, 0, M, K);

    for (int c = 0; c < NC; c++){
        uint32_t cur = (c & 1) ? st1 : st0;
        if (c + 1 < NC)
            load_chunk128<TILES>((c & 1) ? st0 : st1, tid, A0, A1, Bh, m0, n0, (c+1)*KC, M, K);
        if (c + 1 < NC) cpwait1(); else cpwait0();
        __syncthreads();

        uint32_t cA0 = cur, cA1 = cur + TILE_B, cB = cur + (TILES-1)*TILE_B;
        #pragma unroll
        for (int ks = 0; ks < 4; ks++){
            int k0 = ks*16;
            uint32_t a0[4][4], a1[4][4], bh[2][4];
            #pragma unroll
            for (int mt = 0; mt < 4; mt++){
                uint32_t off = (uint32_t)((a_row + mt*16)*KSTRIDE + k0 + a_col8)*2u;
                ldsm4(a0[mt], cA0 + off);
                if (PASSES == 2) ldsm4(a1[mt], cA1 + off);
            }
            #pragma unroll
            for (int p = 0; p < 2; p++){
                uint32_t off = (uint32_t)((b_row + p*16)*KSTRIDE + k0 + b_col8)*2u;
                ldsm4(bh[p], cB + off);
            }
            #pragma unroll
            for (int mt = 0; mt < 4; mt++)
                #pragma unroll
                for (int nt = 0; nt < 4; nt++)
                    mma16816(acc[mt][nt], a0[mt], &bh[nt >> 1][(nt & 1)*2]);
            if (PASSES == 2){
                #pragma unroll
                for (int mt = 0; mt < 4; mt++)
                    #pragma unroll
                    for (int nt = 0; nt < 4; nt++)
                        mma16816(acc[mt][nt], a1[mt], &bh[nt >> 1][(nt & 1)*2]);
            }
        }
        __syncthreads();
    }
}

template<int EPI, int PASSES>
__global__ __launch_bounds__(256, 1)
void gemm128(const __half* A0, const __half* A1, const __half* Bh,
             const float* __restrict__ bias, const float* __restrict__ res,
             float* __restrict__ Cf, int M, int N, int K)
{
    extern __shared__ char smem[];
    uint32_t sb = s2u(smem);
    int tid = threadIdx.x, lane = tid & 31, warp = tid >> 5;
    int m0 = blockIdx.y*128, n0 = blockIdx.x*128;
    float acc[4][4][4];
    #pragma unroll
    for (int a = 0; a < 4; a++)
        #pragma unroll
        for (int b = 0; b < 4; b++)
            #pragma unroll
            for (int c = 0; c < 4; c++) acc[a][b][c] = 0.f;

    mainloop128<PASSES>(sb, tid, lane, warp, A0, A1, Bh, m0, n0, M, K, acc);

    int gg = lane >> 2, tig = lane & 3;
    int wm = warp >> 2, wn = warp & 3;
    #pragma unroll
    for (int mt = 0; mt < 4; mt++)
        #pragma unroll
        for (int half = 0; half < 2; half++){
            int row = m0 + wm*64 + mt*16 + gg + half*8;
            if (row >= M) continue;
            #pragma unroll
            for (int nt = 0; nt < 4; nt++){
                int col = n0 + wn*32 + nt*8 + tig*2;
                float v0 = acc[mt][nt][half*2 + 0] + bias[col];
                float v1 = acc[mt][nt][half*2 + 1] + bias[col + 1];
                size_t o = (size_t)row*N + col;
                if (EPI == 2){
                    float2 rv = *(const float2*)&res[o];
                    v0 += rv.x; v1 += rv.y;
                }
                *(float2*)&Cf[o] = make_float2(v0, v1);
            }
        }
}

// ---------------- 128x256 mainloop (single pass) -----------------------------
__device__ __forceinline__ void mainloop_big(uint32_t sb, int tid, int lane, int warp,
    const __half* Ah, const __half* Bh,
    int m0, int n0, int K, float acc[4][8][4])
{
    int a_row  = (warp >> 2)*64 + (lane & 15);
    int a_col8 = (lane >> 4)*8;
    int b_rowb = (warp & 3)*64 + (lane & 7) + ((lane & 16) ? 8 : 0);
    int b_col8 = ((lane & 8) ? 8 : 0);

    const int NC = K / KC;
    uint32_t st0 = sb, st1 = sb + STAGEBIG;
    load_chunk_big(st0, tid, Ah, Bh, m0, n0, 0, K);

    for (int c = 0; c < NC; c++){
        uint32_t cur = (c & 1) ? st1 : st0;
        if (c + 1 < NC)
            load_chunk_big((c & 1) ? st0 : st1, tid, Ah, Bh, m0, n0, (c+1)*KC, K);
        if (c + 1 < NC) cpwait1(); else cpwait0();
        __syncthreads();

        uint32_t cA = cur, cB = cur + TILE_A2;
        #pragma unroll
        for (int ks = 0; ks < 4; ks++){
            int k0 = ks*16;
            uint32_t ah[4][4];
            #pragma unroll
            for (int mt = 0; mt < 4; mt++){
                uint32_t off = (uint32_t)((a_row + mt*16)*KSTRIDE + k0 + a_col8)*2u;
                ldsm4(ah[mt], cA + off);
            }
            #pragma unroll
            for (int h2 = 0; h2 < 2; h2++){
                uint32_t bh[2][4];
                #pragma unroll
                for (int p = 0; p < 2; p++){
                    uint32_t off = (uint32_t)((b_rowb + (h2*2 + p)*16)*KSTRIDE + k0 + b_col8)*2u;
                    ldsm4(bh[p], cB + off);
                }
                #pragma unroll
                for (int mt = 0; mt < 4; mt++)
                    #pragma unroll
                    for (int j = 0; j < 4; j++)
                        mma16816(acc[mt][h2*4 + j], ah[mt], &bh[j >> 1][(j & 1)*2]);
            }
        }
        __syncthreads();
    }
}

__global__ __launch_bounds__(256, 1)
void gemm_big_relu(const __half* Ah, const __half* Bh,
                   const float* __restrict__ bias,
                   __half* __restrict__ Ch, int M, int N, int K)
{
    extern __shared__ char smem[];
    uint32_t sb = s2u(smem);
    int tid = threadIdx.x, lane = tid & 31, warp = tid >> 5;
    int m0 = blockIdx.y*128, n0 = blockIdx.x*256;
    float acc[4][8][4];
    #pragma unroll
    for (int a = 0; a < 4; a++)
        #pragma unroll
        for (int b = 0; b < 8; b++)
            #pragma unroll
            for (int c = 0; c < 4; c++) acc[a][b][c] = 0.f;

    mainloop_big(sb, tid, lane, warp, Ah, Bh, m0, n0, K, acc);

    int gg = lane >> 2, tig = lane & 3;
    int wm = warp >> 2, wn = warp & 3;
    #pragma unroll
    for (int mt = 0; mt < 4; mt++)
        #pragma unroll
        for (int half = 0; half < 2; half++){
            int row = m0 + wm*64 + mt*16 + gg + half*8;
            #pragma unroll
            for (int nt8 = 0; nt8 < 8; nt8++){
                int col = n0 + wn*64 + nt8*8 + tig*2;
                float v0 = fmaxf(acc[mt][nt8][half*2 + 0] + bias[col],     0.f);
                float v1 = fmaxf(acc[mt][nt8][half*2 + 1] + bias[col + 1], 0.f);
                size_t o = (size_t)row*N + col;
                *(uint32_t*)((char*)Ch + o*2) = packh(__float2half_rn(v0), __float2half_rn(v1));
            }
        }
}

// merged qkv
__global__ __launch_bounds__(256, 1)
void gemm_qkv_big(const __half* Ah, const __half* Bh,
                  const float* b0, const float* b1, const float* b2,
                  float* f0, float* f1,
                  __half* c0h, __half* c0l, __half* c1h, __half* c2h,
                  int M, int K)
{
    extern __shared__ char smem[];
    uint32_t sb = s2u(smem);
    int tid = threadIdx.x, lane = tid & 31, warp = tid >> 5;
    int m0 = blockIdx.y*128, n0 = blockIdx.x*256;
    float acc[4][8][4];
    #pragma unroll
    for (int a = 0; a < 4; a++)
        #pragma unroll
        for (int b = 0; b < 8; b++)
            #pragma unroll
            for (int c = 0; c < 4; c++) acc[a][b][c] = 0.f;

    mainloop_big(sb, tid, lane, warp, Ah, Bh, m0, n0, K, acc);

    int z = n0 >> 9;
    const float* bias = (z==0)?b0:(z==1)?b1:b2;
    float* Cf = (z==0)?f0:(z==1)?f1:nullptr;
    __half* Ch = (z==0)?c0h:(z==1)?c1h:c2h;
    __half* Cl = (z==0)?c0l:nullptr;
    int n0l = n0 & 511;

    int gg = lane >> 2, tig = lane & 3;
    int wm = warp >> 2, wn = warp & 3;
    #pragma unroll
    for (int mt = 0; mt < 4; mt++)
        #pragma unroll
        for (int half = 0; half < 2; half++){
            int row = m0 + wm*64 + mt*16 + gg + half*8;
            #pragma unroll
            for (int nt8 = 0; nt8 < 8; nt8++){
                int col = n0l + wn*64 + nt8*8 + tig*2;
                float v0 = acc[mt][nt8][half*2 + 0] + bias[col];
                float v1 = acc[mt][nt8][half*2 + 1] + bias[col + 1];
                size_t o = (size_t)row*512 + col;
                if (Cf) *(float2*)&Cf[o] = make_float2(v0, v1);
                __half h0 = __float2half_rn(v0);
                __half h1 = __float2half_rn(v1);
                *(uint32_t*)((char*)Ch + o*2) = packh(h0, h1);
                if (Cl){
                    __half l0 = __float2half_rn(v0 - __half2float(h0));
                    __half l1 = __float2half_rn(v1 - __half2float(h1));
                    *(uint32_t*)((char*)Cl + o*2) = packh(l0, l1);
                }
            }
        }
}

// ---------------- fused flash attention: 128-row q tiles ---------------------
// grid (4 it, 32 bh), block 256 (8 warps; warp w owns rows i0+w*16..+15)
__global__ __launch_bounds__(256) void flash_att(
    const __half* __restrict__ qh, const __half* __restrict__ ql,
    const __half* __restrict__ keh, const __half* __restrict__ kvh,
    const float* __restrict__ P, const float* __restrict__ b0t,
    const float* __restrict__ vals, float* __restrict__ V)
{
    extern __shared__ char smem[];
    uint32_t sb = s2u(smem);
    int tid = threadIdx.x, lane = tid & 31, warp = tid >> 5;
    int it = blockIdx.x, bh = blockIdx.y, b = bh >> 3, h = bh & 7;
    int i0 = it*128;
    int NCH = 2*it + 2;

    uint32_t sQH = sb, sQL = sb + QTILE_B;
    uint32_t st0 = sb + 2*QTILE_B;         // [ke, kv]
    uint32_t st1 = st0 + 2*ATILE_B;

    // load q hi/lo (128 rows) + chunk 0 (one cp.async group)
    #pragma unroll
    for (int t = 0; t < 2; t++){
        const __half* gp = t ? ql : qh;
        uint32_t tb = t ? sQL : sQH;
        #pragma unroll
        for (int i = 0; i < 4; i++){
            int s = i*256 + tid;
            int r = s >> 3, seg = s & 7;
            cpa16(tb + (uint32_t)(r*ROWB + seg*16),
                  gp + ((size_t)(b*SS + i0 + r))*EE + h*DD + seg*8, 16u);
        }
    }
    #pragma unroll
    for (int t = 0; t < 2; t++){
        const __half* gp = t ? kvh : keh;
        uint32_t tb = st0 + t*ATILE_B;
        #pragma unroll
        for (int i = 0; i < 2; i++){
            int s = i*256 + tid;
            int r = s >> 3, seg = s & 7;
            cpa16(tb + (uint32_t)(r*ROWB + seg*16),
                  gp + ((size_t)(b*SS + r))*EE + h*DD + seg*8, 16u);
        }
    }
    cpcommit();

    int gg = lane >> 2, tig = lane & 3;
    int a_row  = warp*16 + (lane & 15);
    int a_col8 = (lane >> 4)*8;
    int b_rowb = (lane & 7) + ((lane & 16) ? 8 : 0);
    int b_col8 = ((lane & 8) ? 8 : 0);
    int bt_row = lane & 15;
    int bt_colb = ((lane & 16) ? 8 : 0);

    int gi0 = i0 + warp*16 + gg;
    int gi1 = gi0 + 8;
    const float* Pr0 = P + ((size_t)(b*SS + gi0)*HH + h)*RUSE + 100;
    const float* Pr1 = P + ((size_t)(b*SS + gi1)*HH + h)*RUSE + 100;

    float m_st[2] = {-1e30f, -1e30f};
    float l_st[2] = {0.f, 0.f};
    float acc_o[8][4];
    #pragma unroll
    for (int nt = 0; nt < 8; nt++)
        #pragma unroll
        for (int c = 0; c < 4; c++) acc_o[nt][c] = 0.f;

    for (int c = 0; c < NCH; c++){
        uint32_t cur = (c & 1) ? st1 : st0;
        if (c + 1 < NCH){
            uint32_t nxt = (c & 1) ? st0 : st1;
            int j0n = (c + 1)*64;
            #pragma unroll
            for (int t = 0; t < 2; t++){
                const __half* gp = t ? kvh : keh;
                uint32_t tb = nxt + t*ATILE_B;
                #pragma unroll
                for (int i = 0; i < 2; i++){
                    int s = i*256 + tid;
                    int r = s >> 3, seg = s & 7;
                    cpa16(tb + (uint32_t)(r*ROWB + seg*16),
                          gp + ((size_t)(b*SS + j0n + r))*EE + h*DD + seg*8, 16u);
                }
            }
            cpcommit();
        }
        if (c + 1 < NCH) cpwait1(); else cpwait0();
        __syncthreads();

        int j0 = c*64;
        uint32_t cK = cur, cV = cur + ATILE_B;

        // ---- S = q . ke^T  (2-pass) ----
        float s_acc[8][4];
        #pragma unroll
        for (int nt = 0; nt < 8; nt++)
            #pragma unroll
            for (int e = 0; e < 4; e++) s_acc[nt][e] = 0.f;
        #pragma unroll
        for (int ks = 0; ks < 4; ks++){
            int k0 = ks*16;
            uint32_t aq[4], aql[4], bf[4][4];
            uint32_t offA = (uint32_t)(a_row*KSTRIDE + k0 + a_col8)*2u;
            ldsm4(aq,  sQH + offA);
            ldsm4(aql, sQL + offA);
            #pragma unroll
            for (int p = 0; p < 4; p++){
                uint32_t off = (uint32_t)((p*16 + b_rowb)*KSTRIDE + k0 + b_col8)*2u;
                ldsm4(bf[p], cK + off);
            }
            #pragma unroll
            for (int nt = 0; nt < 8; nt++)
                mma16816(s_acc[nt], aq, &bf[nt >> 1][(nt & 1)*2]);
            #pragma unroll
            for (int nt = 0; nt < 8; nt++)
                mma16816(s_acc[nt], aql, &bf[nt >> 1][(nt & 1)*2]);
        }

        // ---- bias + causal mask + online softmax ----
        float rowmax[2] = {-1e30f, -1e30f};
        #pragma unroll
        for (int nt = 0; nt < 8; nt++){
            #pragma unroll
            for (int e = 0; e < 2; e++){
                int j = j0 + nt*8 + tig*2 + e;
                float bv = b0t[(size_t)(b*SS + j)*HH + h];
                #pragma unroll
                for (int hh = 0; hh < 2; hh++){
                    int gi = hh ? gi1 : gi0;
                    int ci = hh*2 + e;
                    float val;
                    if (j > gi){
                        val = -1e30f;
                    } else {
                        int off = j - gi;
                        if (off < -100) off = -100;
                        val = s_acc[nt][ci]*0.125f + (hh ? Pr1 : Pr0)[off] + bv;
                    }
                    s_acc[nt][ci] = val;
                    rowmax[hh] = fmaxf(rowmax[hh], val);
                }
            }
        }
        #pragma unroll
        for (int hh = 0; hh < 2; hh++){
            rowmax[hh] = fmaxf(rowmax[hh], __shfl_xor_sync(0xffffffffu, rowmax[hh], 1));
            rowmax[hh] = fmaxf(rowmax[hh], __shfl_xor_sync(0xffffffffu, rowmax[hh], 2));
        }
        float mnew[2], scale[2], rsum[2] = {0.f, 0.f};
        #pragma unroll
        for (int hh = 0; hh < 2; hh++){
            mnew[hh]  = fmaxf(m_st[hh], rowmax[hh]);
            scale[hh] = __expf(m_st[hh] - mnew[hh]);
            m_st[hh]  = mnew[hh];
        }
        #pragma unroll
        for (int nt = 0; nt < 8; nt++)
            #pragma unroll
            for (int ci = 0; ci < 4; ci++){
                int hh = ci >> 1;
                float p = __expf(s_acc[nt][ci] - mnew[hh]);
                s_acc[nt][ci] = p;
                rsum[hh] += p;
            }
        #pragma unroll
        for (int hh = 0; hh < 2; hh++){
            rsum[hh] += __shfl_xor_sync(0xffffffffu, rsum[hh], 1);
            rsum[hh] += __shfl_xor_sync(0xffffffffu, rsum[hh], 2);
            l_st[hh] = l_st[hh]*scale[hh] + rsum[hh];
        }
        #pragma unroll
        for (int nt = 0; nt < 8; nt++)
            #pragma unroll
            for (int ci = 0; ci < 4; ci++)
                acc_o[nt][ci] *= scale[ci >> 1];

        // ---- pack p (hi + lo) into A fragments ----
        uint32_t pa[4][4], pl[4][4];
        #pragma unroll
        for (int ks2 = 0; ks2 < 4; ks2++){
            #pragma unroll
            for (int half8 = 0; half8 < 2; half8++){
                int nt = ks2*2 + half8;
                __half h0 = __float2half_rn(s_acc[nt][0]);
                __half h1 = __float2half_rn(s_acc[nt][1]);
                __half h2 = __float2half_rn(s_acc[nt][2]);
                __half h3 = __float2half_rn(s_acc[nt][3]);
                pa[ks2][0 + half8*2] = packh(h0, h1);
                pa[ks2][1 + half8*2] = packh(h2, h3);
                __half l0 = __float2half_rn(s_acc[nt][0] - __half2float(h0));
                __half l1 = __float2half_rn(s_acc[nt][1] - __half2float(h1));
                __half l2 = __float2half_rn(s_acc[nt][2] - __half2float(h2));
                __half l3 = __float2half_rn(s_acc[nt][3] - __half2float(h3));
                pl[ks2][0 + half8*2] = packh(l0, l1);
                pl[ks2][1 + half8*2] = packh(l2, l3);
            }
        }

        // ---- O += P . V  (2-pass) ----
        #pragma unroll
        for (int ks2 = 0; ks2 < 4; ks2++){
            int k0 = ks2*16;
            uint32_t bv[4][4];
            #pragma unroll
            for (int grp = 0; grp < 4; grp++){
                uint32_t off = (uint32_t)((k0 + bt_row)*KSTRIDE + grp*16 + bt_colb)*2u;
                ldsm4t(bv[grp], cV + off);
            }
            #pragma unroll
            for (int nt = 0; nt < 8; nt++)
                mma16816(acc_o[nt], pa[ks2], &bv[nt >> 1][(nt & 1)*2]);
            #pragma unroll
            for (int nt = 0; nt < 8; nt++)
                mma16816(acc_o[nt], pl[ks2], &bv[nt >> 1][(nt & 1)*2]);
        }
        __syncthreads();
    }

    // ---- finalize: O / l + residual ----
    float inv[2] = {1.f / l_st[0], 1.f / l_st[1]};
    #pragma unroll
    for (int hh = 0; hh < 2; hh++){
        int gi = hh ? gi1 : gi0;
        #pragma unroll
        for (int nt = 0; nt < 8; nt++){
            int d = nt*8 + tig*2;
            size_t o = ((size_t)(b*SS + gi))*EE + h*DD + d;
            float2 rv = *(const float2*)&vals[o];
            *(float2*)&V[o] = make_float2(acc_o[nt][hh*2 + 0]*inv[hh] + rv.x,
                                          acc_o[nt][hh*2 + 1]*inv[hh] + rv.y);
        }
    }
}

// ---------------- fused weight conversion ------------------------------------
struct WTab {
    const float* W[7];
    __half* Th[7];
    int K[7];
    int N[7];
    int off[8];
};

__global__ void convWT_all(WTab tab)
{
    __shared__ float t[32][33];
    int bid = blockIdx.x;
    int e = 0;
    #pragma unroll
    for (int i = 1; i < 7; i++) if (bid >= tab.off[i]) e = i;
    int local = bid - tab.off[e];
    const float* W = tab.W[e];
    __half* Th = tab.Th[e];
    int K = tab.K[e], N = tab.N[e];
    int ntiles = N >> 5;
    int kt = local / ntiles, ct = local - kt*ntiles;
    int by = kt*32, bx = ct*32;
    int lx = threadIdx.x & 31, ly = threadIdx.x >> 5;
    #pragma unroll
    for (int i = 0; i < 32; i += 8)
        t[ly + i][lx] = W[(size_t)(by + ly + i)*N + bx + lx];
    __syncthreads();
    #pragma unroll
    for (int i = 0; i < 32; i += 8){
        int n = bx + ly + i, k = by + lx;
        Th[(size_t)n*K + k] = __float2half_rn(t[lx][ly + i]);
    }
}

__global__ void convA(const float* __restrict__ X, __half* __restrict__ H,
                      __half* __restrict__ L, int n)
{
    int i = blockIdx.x*256 + threadIdx.x;
    if (i < n){
        float x = X[i];
        __half h = __float2half_rn(x);
        H[i] = h;
        L[i] = __float2half_rn(x - __half2float(h));
    }
}

// ---------------- LayerNorm -> fp16 hi only ---------------------------------
__global__ void ln_h(const float* __restrict__ X, const float* __restrict__ g,
                     const float* __restrict__ bt, __half* __restrict__ Yh)
{
    int row = blockIdx.x;
    int tid = threadIdx.x;
    const float* x = X + (size_t)row*EE;
    float a = x[tid], c = x[tid + 256];
    float s  = a + c;
    float s2 = a*a + c*c;
    #pragma unroll
    for (int o = 16; o > 0; o >>= 1){
        s  += __shfl_xor_sync(0xffffffffu, s,  o);
        s2 += __shfl_xor_sync(0xffffffffu, s2, o);
    }
    __shared__ float sa[8], sbm[8];
    if ((tid & 31) == 0){ sa[tid>>5] = s; sbm[tid>>5] = s2; }
    __syncthreads();
    float ts = 0.f, ts2 = 0.f;
    #pragma unroll
    for (int w = 0; w < 8; w++){ ts += sa[w]; ts2 += sbm[w]; }
    float mean = ts * (1.f/512.f);
    float var  = ts2 * (1.f/512.f) - mean*mean;
    float r = rsqrtf(var + 1e-3f);
    Yh[(size_t)row*EE + tid]       = __float2half_rn((a - mean)*r*g[tid]       + bt[tid]);
    Yh[(size_t)row*EE + tid + 256] = __float2half_rn((c - mean)*r*g[tid + 256] + bt[tid + 256]);
}

// ---------------- fused dual N=8 projection ----------------------------------
__global__ void proj8_dual(
    const float* __restrict__ X0, const float* __restrict__ W0,
    const float* __restrict__ bp0, float* __restrict__ Y0, int n0,
    const float* __restrict__ X1, const float* __restrict__ W1,
    const float* __restrict__ bp1, float* __restrict__ Y1)
{
    int row = blockIdx.x;
    const float *X, *Wp, *bp;
    float* Y;
    int r;
    if (row < n0){ X = X0; Wp = W0; bp = bp0; Y = Y0; r = row; }
    else         { X = X1; Wp = W1; bp = bp1; Y = Y1; r = row - n0; }
    int tid = threadIdx.x;
    int h = tid & 7, seg = tid >> 3;
    const float* x = X + (size_t)r*EE;
    float s = 0.f;
    #pragma unroll
    for (int k = 0; k < 16; k++){
        int kk = seg*16 + k;
        s += x[kk] * Wp[kk*HH + h];
    }
    __shared__ float sm[256];
    sm[tid] = s;
    __syncthreads();
    if (tid < 8){
        float acc = bp[tid];
        #pragma unroll
        for (int sg = 0; sg < 32; sg++) acc += sm[sg*8 + tid];
        Y[(size_t)r*HH + tid] = acc;
    }
}

// ---------------- P[m,h,r] --------------------------------------------------
__global__ __launch_bounds__(128) void pkernel(
    const float* __restrict__ q, const float* __restrict__ krt,
    const float* __restrict__ t1, float* __restrict__ P)
{
    int h = blockIdx.y;
    int m = blockIdx.x * 128 + threadIdx.x;
    float qr[64];
    const float4* qp = (const float4*)(q + (size_t)m*EE + h*DD);
    #pragma unroll
    for (int t = 0; t < 16; t++){
        float4 v = qp[t];
        qr[t*4+0]=v.x; qr[t*4+1]=v.y; qr[t*4+2]=v.z; qr[t*4+3]=v.w;
    }
    float* Pp = P + ((size_t)m*HH + h)*RUSE;
    const float* kbase = krt + h*DD;
    for (int r = 0; r < RUSE; r++){
        const float4* kp = (const float4*)(kbase + (size_t)r*EE);
        float acc = 0.f;
        #pragma unroll
        for (int t = 0; t < 16; t++){
            float4 k4 = __ldg(&kp[t]);
            acc += qr[t*4+0]*k4.x + qr[t*4+1]*k4.y + qr[t*4+2]*k4.z + qr[t*4+3]*k4.w;
        }
        Pp[r] = acc + t1[r*HH + h];
    }
}

// ---------------- launch ----------------------------------------------------
extern "C" void kernel_launch(void* const* d_in, const int* in_sizes, int n_in,
                              void* d_out, int out_size)
{
    const float* values  = (const float*)d_in[0];
    const float* rel_enc = (const float*)d_in[2];
    const float* ln0_g   = (const float*)d_in[3];
    const float* ln0_b   = (const float*)d_in[4];
    const float* w_b0    = (const float*)d_in[5];
    const float* b_b0    = (const float*)d_in[6];
    const float* wq      = (const float*)d_in[7];
    const float* bq      = (const float*)d_in[8];
    const float* wke     = (const float*)d_in[9];
    const float* bke     = (const float*)d_in[10];
    const float* wkv     = (const float*)d_in[11];
    const float* bkv     = (const float*)d_in[12];
    const float* wkr     = (const float*)d_in[13];
    const float* bkr     = (const float*)d_in[14];
    const float* wab0    = (const float*)d_in[15];
    const float* bab0    = (const float*)d_in[16];
    const float* wab1    = (const float*)d_in[17];
    const float* bab1    = (const float*)d_in[18];
    const float* ln1_g   = (const float*)d_in[19];
    const float* ln1_b   = (const float*)d_in[20];
    const float* w11     = (const float*)d_in[21];
    const float* b11     = (const float*)d_in[22];
    const float* w12     = (const float*)d_in[23];
    const float* b12     = (const float*)d_in[24];
    float* out = (float*)d_out;

    float *p_q,*p_ke,*p_krt,*p_t1,*p_b0t,*p_P,*p_v;
    cudaGetSymbolAddress((void**)&p_q,   g_q);
    cudaGetSymbolAddress((void**)&p_ke,  g_ke);
    cudaGetSymbolAddress((void**)&p_krt, g_krt);
    cudaGetSymbolAddress((void**)&p_t1,  g_t1);
    cudaGetSymbolAddress((void**)&p_b0t, g_b0t);
    cudaGetSymbolAddress((void**)&p_P,   g_P);
    cudaGetSymbolAddress((void**)&p_v,   g_v);

    __half *xnh,*xh,*vnh,*h1h,*reh,*rel;
    __half *qh,*ql,*keh,*kvh;
    __half *wb0h,*wqkvh,*wkrh,*w11h,*w12h;
    cudaGetSymbolAddress((void**)&xnh, g_xnh);
    cudaGetSymbolAddress((void**)&xh,  g_xh);
    cudaGetSymbolAddress((void**)&vnh, g_vnh);
    cudaGetSymbolAddress((void**)&h1h, g_h1h);
    cudaGetSymbolAddress((void**)&reh, g_reh); cudaGetSymbolAddress((void**)&rel, g_rel_);
    cudaGetSymbolAddress((void**)&qh,  g_qh);  cudaGetSymbolAddress((void**)&ql,  g_ql);
    cudaGetSymbolAddress((void**)&keh, g_keh);
    cudaGetSymbolAddress((void**)&kvh, g_kvh);
    cudaGetSymbolAddress((void**)&wb0h, g_wb0h);
    cudaGetSymbolAddress((void**)&wqkvh, g_wqkvh);
    cudaGetSymbolAddress((void**)&wkrh, g_wkrh);
    cudaGetSymbolAddress((void**)&w11h, g_w11h);
    cudaGetSymbolAddress((void**)&w12h, g_w12h);

    cudaFuncSetAttribute((const void*)gemm128<0,2>, cudaFuncAttributeMaxDynamicSharedMemorySize, GSMEM2P);
    cudaFuncSetAttribute((const void*)gemm128<2,1>, cudaFuncAttributeMaxDynamicSharedMemorySize, GSMEM1P);
    cudaFuncSetAttribute(gemm_big_relu, cudaFuncAttributeMaxDynamicSharedMemorySize, GSMEMBIG);
    cudaFuncSetAttribute(gemm_qkv_big,  cudaFuncAttributeMaxDynamicSharedMemorySize, GSMEMBIG);
    cudaFuncSetAttribute(flash_att,     cudaFuncAttributeMaxDynamicSharedMemorySize, FA_SMEM);

    WTab tab;
    tab.W[0]=w_b0; tab.Th[0]=wb0h;              tab.K[0]=EE;   tab.N[0]=HIDD;
    tab.W[1]=wq;   tab.Th[1]=wqkvh;             tab.K[1]=HIDD; tab.N[1]=EE;
    tab.W[2]=wke;  tab.Th[2]=wqkvh + 512*HIDD;  tab.K[2]=HIDD; tab.N[2]=EE;
    tab.W[3]=wkv;  tab.Th[3]=wqkvh + 1024*HIDD; tab.K[3]=HIDD; tab.N[3]=EE;
    tab.W[4]=wkr;  tab.Th[4]=wkrh;              tab.K[4]=EE;   tab.N[4]=EE;
    tab.W[5]=w11;  tab.Th[5]=w11h;              tab.K[5]=EE;   tab.N[5]=HIDD;
    tab.W[6]=w12;  tab.Th[6]=w12h;              tab.K[6]=HIDD; tab.N[6]=EE;
    int total = 0;
    for (int i = 0; i < 7; i++){
        tab.off[i] = total;
        total += (tab.K[i]/32) * (tab.N[i]/32);
    }
    tab.off[7] = total;
    convWT_all<<<total, 256>>>(tab);
    convA<<<(RFULL*EE + 255)/256, 256>>>(rel_enc, reh, rel, RFULL*EE);

    // 1) LN0 -> fp16
    ln_h<<<MR, 256>>>(values, ln0_g, ln0_b, xnh);
    // 2) x = relu(xn @ w_b0 + b_b0)
    gemm_big_relu<<<dim3(HIDD/256, MR/128), 256, GSMEMBIG>>>(
        xnh, wb0h, b_b0, xh, MR, HIDD, EE);
    // 3) merged q/ke/kv
    gemm_qkv_big<<<dim3(6, MR/128), 256, GSMEMBIG>>>(
        xh, wqkvh, bq, bke, bkv, p_q, p_ke, qh, ql, keh, kvh, MR, HIDD);
    // 4) kr_table (2-pass)
    gemm128<0,2><<<dim3(EE/128, 2), 256, GSMEM2P>>>(
        reh, rel, wkrh, bkr, nullptr, p_krt, RFULL, EE, EE);
    // 5) bias0 + t1 (fused)
    proj8_dual<<<MR + RFULL, 256>>>(p_ke, wab0, bab0, p_b0t, MR,
                                    p_krt, wab1, bab1, p_t1);
    // 6) P
    pkernel<<<dim3(MR/128, HH), 128>>>(p_q, p_krt, p_t1, p_P);
    // 7) fused flash attention (128-row q tiles) -> v
    flash_att<<<dim3(4, BB*HH), 256, FA_SMEM>>>(
        qh, ql, keh, kvh, p_P, p_b0t, values, p_v);
    // 8) LN1 -> fp16
    ln_h<<<MR, 256>>>(p_v, ln1_g, ln1_b, vnh);
    // 9) h1 = relu(vn @ w11 + b11)
    gemm_big_relu<<<dim3(HIDD/256, MR/128), 256, GSMEMBIG>>>(
        vnh, w11h, b11, h1h, MR, HIDD, EE);
    // 10) out = v + h1 @ w12 + b12
    gemm128<2,1><<<dim3(EE/128, MR/128), 256, GSMEM1P>>>(
        h1h, nullptr, w12h, b12, p_v, out, MR, EE, HIDD);
}

// round 15
// speedup vs baseline: 1.8809x; 1.0468x over previous
#include <cuda_runtime.h>
#include <cuda_fp16.h>
#include <cstdint>
#include <cstddef>

#define BB 4
#define SS 512
#define EE 512
#define HIDD 2048
#define HH 8
#define DD 64
#define RFULL 201
#define RUSE 101
#define MR (BB*SS)   // 2048

// ---------------- fp32 scratch ----------------------------------------------
__device__ __align__(128) float g_q [MR*EE];
__device__ __align__(128) float g_ke[MR*EE];
__device__ __align__(128) float g_krt[RFULL*EE];
__device__ __align__(128) float g_t1[RFULL*HH];
__device__ __align__(128) float g_b0t[MR*HH];
__device__ __align__(128) float g_P[(size_t)MR*HH*RUSE];
__device__ __align__(128) float g_v [MR*EE];

// ---------------- fp16 scratch ----------------------------------------------
__device__ __align__(128) __half g_xnh[MR*EE];
__device__ __align__(128) __half g_xh [MR*HIDD];
__device__ __align__(128) __half g_vnh[MR*EE];
__device__ __align__(128) __half g_h1h[MR*HIDD];
__device__ __align__(128) __half g_reh[RFULL*EE + 64], g_rel_[RFULL*EE + 64];
__device__ __align__(128) __half g_qh [MR*EE], g_ql [MR*EE];
__device__ __align__(128) __half g_keh[MR*EE];
__device__ __align__(128) __half g_kvh[MR*EE];
// weights, transposed to [N][K], single fp16
__device__ __align__(128) __half g_wb0h[HIDD*EE];
__device__ __align__(128) __half g_wqkvh[3*EE*HIDD];
__device__ __align__(128) __half g_wkrh[EE*EE];
__device__ __align__(128) __half g_w11h[HIDD*EE];
__device__ __align__(128) __half g_w12h[EE*HIDD];

// ---------------- PTX helpers -----------------------------------------------
__device__ __forceinline__ uint32_t s2u(const void* p){
    uint32_t a;
    asm("{ .reg .u64 t; cvta.to.shared.u64 t, %1; cvt.u32.u64 %0, t; }" : "=r"(a) : "l"(p));
    return a;
}
__device__ __forceinline__ void cpa16(uint32_t dst, const void* src, uint32_t sz){
    asm volatile("cp.async.cg.shared.global [%0], [%1], 16, %2;" :: "r"(dst), "l"(src), "r"(sz));
}
__device__ __forceinline__ void cpcommit(){ asm volatile("cp.async.commit_group;" ::: "memory"); }
__device__ __forceinline__ void cpwait0(){ asm volatile("cp.async.wait_group 0;" ::: "memory"); }
__device__ __forceinline__ void cpwait1(){ asm volatile("cp.async.wait_group 1;" ::: "memory"); }

__device__ __forceinline__ void ldsm4(uint32_t* r, uint32_t addr){
    asm volatile("ldmatrix.sync.aligned.m8n8.x4.shared.b16 {%0,%1,%2,%3}, [%4];"
        : "=r"(r[0]), "=r"(r[1]), "=r"(r[2]), "=r"(r[3]) : "r"(addr));
}
__device__ __forceinline__ void ldsm4t(uint32_t* r, uint32_t addr){
    asm volatile("ldmatrix.sync.aligned.m8n8.x4.trans.shared.b16 {%0,%1,%2,%3}, [%4];"
        : "=r"(r[0]), "=r"(r[1]), "=r"(r[2]), "=r"(r[3]) : "r"(addr));
}
__device__ __forceinline__ void mma16816(float* d, const uint32_t* a, const uint32_t* b){
    asm volatile("mma.sync.aligned.m16n8k16.row.col.f32.f16.f16.f32 "
        "{%0,%1,%2,%3}, {%4,%5,%6,%7}, {%8,%9}, {%0,%1,%2,%3};"
        : "+f"(d[0]), "+f"(d[1]), "+f"(d[2]), "+f"(d[3])
        : "r"(a[0]), "r"(a[1]), "r"(a[2]), "r"(a[3]), "r"(b[0]), "r"(b[1]));
}
__device__ __forceinline__ uint32_t packh(__half a, __half b){
    return (uint32_t)__half_as_ushort(a) | ((uint32_t)__half_as_ushort(b) << 16);
}

// geometry: k-chunk 64, rows padded to 72 halves (144 B)
#define KC 64
#define KSTRIDE 72
#define ROWB 144
#define TILE_B (128*ROWB)                 // 18432
#define STAGE1P (2*TILE_B)                // 36864  (A, B) 128x128 1-pass
#define GSMEM1P (2*STAGE1P)               // 73728  -> 2 CTAs/SM
#define STAGE2P (3*TILE_B)                // 55296  (Ah, Al, B) kr only
#define GSMEM2P (2*STAGE2P)               // 110592

#define TILE_A64 (64*ROWB)                // 9216
#define STAGE64 (TILE_A64 + TILE_B)       // 27648
#define GSMEM64 (2*STAGE64)               // 55296

// flash attention: q tile 128x64, kv tiles 64x64
#define QTILE_B (128*ROWB)                // 18432
#define ATILE_B (64*ROWB)                 // 9216
#define FA_SMEM (2*QTILE_B + 4*ATILE_B)   // 73728

// ---------------- loaders ----------------------------------------------------
template<int TILES>
__device__ __forceinline__ void load_chunk128(uint32_t stage, int tid,
    const __half* __restrict__ A0, const __half* __restrict__ A1,
    const __half* __restrict__ Bh,
    int m0, int n0, int k0, int M, int K)
{
    #pragma unroll
    for (int t = 0; t < TILES; t++){
        const __half* gp = (t==0)?A0:(t==TILES-1)?Bh:A1;
        int row0 = (t < TILES-1) ? m0 : n0;
        uint32_t tb = stage + t*TILE_B;
        #pragma unroll
        for (int i = 0; i < 4; i++){
            int s = i*256 + tid;
            int r = s >> 3, seg = s & 7;
            int gr = row0 + r;
            uint32_t sz = 16u;
            if (t < TILES-1 && gr >= M){ sz = 0u; gr = M - 1; }
            cpa16(tb + (uint32_t)(r*ROWB + seg*16),
                  gp + (size_t)gr*K + k0 + seg*8, sz);
        }
    }
    cpcommit();
}

__device__ __forceinline__ void load_chunk64(uint32_t stage, int tid,
    const __half* __restrict__ A, const __half* __restrict__ B,
    int m0, int n0, int k0, int K)
{
    #pragma unroll
    for (int i = 0; i < 2; i++){
        int s = i*256 + tid;
        int r = s >> 3, seg = s & 7;
        cpa16(stage + (uint32_t)(r*ROWB + seg*16),
              A + (size_t)(m0 + r)*K + k0 + seg*8, 16u);
    }
    uint32_t tb = stage + TILE_A64;
    #pragma unroll
    for (int i = 0; i < 4; i++){
        int s = i*256 + tid;
        int r = s >> 3, seg = s & 7;
        cpa16(tb + (uint32_t)(r*ROWB + seg*16),
              B + (size_t)(n0 + r)*K + k0 + seg*8, 16u);
    }
    cpcommit();
}

// ---------------- 128x128 mainloop (PASSES = 1 or 2) -------------------------
template<int PASSES>
__device__ __forceinline__ void mainloop128(uint32_t sb, int tid, int lane, int warp,
    const __half* A0, const __half* A1, const __half* Bh,
    int m0, int n0, int M, int K, float acc[4][4][4])
{
    const int TILES = PASSES + 1;
    const int STG = TILES*TILE_B;
    int a_row  = (warp >> 2)*64 + (lane & 15);
    int a_col8 = (lane >> 4)*8;
    int b_row  = (warp & 3)*32 + (lane & 7) + ((lane & 16) ? 8 : 0);
    int b_col8 = ((lane & 8) ? 8 : 0);

    const int NC = K / KC;
    uint32_t st0 = sb, st1 = sb + STG;
    load_chunk128<TILES>(st0, tid, A0, A1, Bh, m0, n0, 0, M, K);

    for (int c = 0; c < NC; c++){
        uint32_t cur = (c & 1) ? st1 : st0;
        if (c + 1 < NC)
            load_chunk128<TILES>((c & 1) ? st0 : st1, tid, A0, A1, Bh, m0, n0, (c+1)*KC, M, K);
        if (c + 1 < NC) cpwait1(); else cpwait0();
        __syncthreads();

        uint32_t cA0 = cur, cA1 = cur + TILE_B, cB = cur + (TILES-1)*TILE_B;
        #pragma unroll
        for (int ks = 0; ks < 4; ks++){
            int k0 = ks*16;
            uint32_t a0[4][4], a1[4][4], bh[2][4];
            #pragma unroll
            for (int mt = 0; mt < 4; mt++){
                uint32_t off = (uint32_t)((a_row + mt*16)*KSTRIDE + k0 + a_col8)*2u;
                ldsm4(a0[mt], cA0 + off);
                if (PASSES == 2) ldsm4(a1[mt], cA1 + off);
            }
            #pragma unroll
            for (int p = 0; p < 2; p++){
                uint32_t off = (uint32_t)((b_row + p*16)*KSTRIDE + k0 + b_col8)*2u;
                ldsm4(bh[p], cB + off);
            }
            #pragma unroll
            for (int mt = 0; mt < 4; mt++)
                #pragma unroll
                for (int nt = 0; nt < 4; nt++)
                    mma16816(acc[mt][nt], a0[mt], &bh[nt >> 1][(nt & 1)*2]);
            if (PASSES == 2){
                #pragma unroll
                for (int mt = 0; mt < 4; mt++)
                    #pragma unroll
                    for (int nt = 0; nt < 4; nt++)
                        mma16816(acc[mt][nt], a1[mt], &bh[nt >> 1][(nt & 1)*2]);
            }
        }
        __syncthreads();
    }
}

// EPI: 0 fp32+bias, 1 relu->fp16, 2 fp32+bias+res ; PASSES 1 or 2
template<int EPI, int PASSES>
__global__ __launch_bounds__(256, 2)
void gemm128(const __half* A0, const __half* A1, const __half* Bh,
             const float* __restrict__ bias, const float* __restrict__ res,
             float* __restrict__ Cf, __half* __restrict__ Ch,
             int M, int N, int K)
{
    extern __shared__ char smem[];
    uint32_t sb = s2u(smem);
    int tid = threadIdx.x, lane = tid & 31, warp = tid >> 5;
    int m0 = blockIdx.y*128, n0 = blockIdx.x*128;
    float acc[4][4][4];
    #pragma unroll
    for (int a = 0; a < 4; a++)
        #pragma unroll
        for (int b = 0; b < 4; b++)
            #pragma unroll
            for (int c = 0; c < 4; c++) acc[a][b][c] = 0.f;

    mainloop128<PASSES>(sb, tid, lane, warp, A0, A1, Bh, m0, n0, M, K, acc);

    int gg = lane >> 2, tig = lane & 3;
    int wm = warp >> 2, wn = warp & 3;
    #pragma unroll
    for (int mt = 0; mt < 4; mt++)
        #pragma unroll
        for (int half = 0; half < 2; half++){
            int row = m0 + wm*64 + mt*16 + gg + half*8;
            if (row >= M) continue;
            #pragma unroll
            for (int nt = 0; nt < 4; nt++){
                int col = n0 + wn*32 + nt*8 + tig*2;
                float v0 = acc[mt][nt][half*2 + 0] + bias[col];
                float v1 = acc[mt][nt][half*2 + 1] + bias[col + 1];
                size_t o = (size_t)row*N + col;
                if (EPI == 1){
                    v0 = fmaxf(v0, 0.f); v1 = fmaxf(v1, 0.f);
                    *(uint32_t*)((char*)Ch + o*2) = packh(__float2half_rn(v0), __float2half_rn(v1));
                } else {
                    if (EPI == 2){
                        float2 rv = *(const float2*)&res[o];
                        v0 += rv.x; v1 += rv.y;
                    }
                    *(float2*)&Cf[o] = make_float2(v0, v1);
                }
            }
        }
}

// merged qkv on 128x128 tiles: N=1536, z = blockIdx.x>>2
__global__ __launch_bounds__(256, 2)
void gemm_qkv128(const __half* Ah, const __half* Bh,
                 const float* b0, const float* b1, const float* b2,
                 float* f0, float* f1,
                 __half* c0h, __half* c0l, __half* c1h, __half* c2h,
                 int M, int K)
{
    extern __shared__ char smem[];
    uint32_t sb = s2u(smem);
    int tid = threadIdx.x, lane = tid & 31, warp = tid >> 5;
    int m0 = blockIdx.y*128, n0 = blockIdx.x*128;
    float acc[4][4][4];
    #pragma unroll
    for (int a = 0; a < 4; a++)
        #pragma unroll
        for (int b = 0; b < 4; b++)
            #pragma unroll
            for (int c = 0; c < 4; c++) acc[a][b][c] = 0.f;

    mainloop128<1>(sb, tid, lane, warp, Ah, nullptr, Bh, m0, n0, M, K, acc);

    int z = blockIdx.x >> 2;
    const float* bias = (z==0)?b0:(z==1)?b1:b2;
    float* Cf = (z==0)?f0:(z==1)?f1:nullptr;
    __half* Ch = (z==0)?c0h:(z==1)?c1h:c2h;
    __half* Cl = (z==0)?c0l:nullptr;
    int n0l = (blockIdx.x & 3)*128;

    int gg = lane >> 2, tig = lane & 3;
    int wm = warp >> 2, wn = warp & 3;
    #pragma unroll
    for (int mt = 0; mt < 4; mt++)
        #pragma unroll
        for (int half = 0; half < 2; half++){
            int row = m0 + wm*64 + mt*16 + gg + half*8;
            #pragma unroll
            for (int nt = 0; nt < 4; nt++){
                int col = n0l + wn*32 + nt*8 + tig*2;
                float v0 = acc[mt][nt][half*2 + 0] + bias[col];
                float v1 = acc[mt][nt][half*2 + 1] + bias[col + 1];
                size_t o = (size_t)row*512 + col;
                if (Cf) *(float2*)&Cf[o] = make_float2(v0, v1);
                __half h0 = __float2half_rn(v0);
                __half h1 = __float2half_rn(v1);
                *(uint32_t*)((char*)Ch + o*2) = packh(h0, h1);
                if (Cl){
                    __half l0 = __float2half_rn(v0 - __half2float(h0));
                    __half l1 = __float2half_rn(v1 - __half2float(h1));
                    *(uint32_t*)((char*)Cl + o*2) = packh(l0, l1);
                }
            }
        }
}

// ---------------- 64x128 GEMM (FFN2): out = A@B^T + bias + res ---------------
__global__ __launch_bounds__(256, 2)
void gemm64_res(const __half* __restrict__ A, const __half* __restrict__ B,
                const float* __restrict__ bias, const float* __restrict__ res,
                float* __restrict__ Cf, int M, int N, int K)
{
    extern __shared__ char smem[];
    uint32_t sb = s2u(smem);
    int tid = threadIdx.x, lane = tid & 31, warp = tid >> 5;
    int m0 = blockIdx.y*64, n0 = blockIdx.x*128;

    int a_row  = (warp >> 2)*32 + (lane & 15);
    int a_col8 = (lane >> 4)*8;
    int b_row  = (warp & 3)*32 + (lane & 7) + ((lane & 16) ? 8 : 0);
    int b_col8 = ((lane & 8) ? 8 : 0);

    float acc[2][4][4];
    #pragma unroll
    for (int a = 0; a < 2; a++)
        #pragma unroll
        for (int b = 0; b < 4; b++)
            #pragma unroll
            for (int c = 0; c < 4; c++) acc[a][b][c] = 0.f;

    const int NC = K / KC;
    uint32_t st0 = sb, st1 = sb + STAGE64;
    load_chunk64(st0, tid, A, B, m0, n0, 0, K);

    for (int c = 0; c < NC; c++){
        uint32_t cur = (c & 1) ? st1 : st0;
        if (c + 1 < NC)
            load_chunk64((c & 1) ? st0 : st1, tid, A, B, m0, n0, (c+1)*KC, K);
        if (c + 1 < NC) cpwait1(); else cpwait0();
        __syncthreads();

        uint32_t cA = cur, cB = cur + TILE_A64;
        #pragma unroll
        for (int ks = 0; ks < 4; ks++){
            int k0 = ks*16;
            uint32_t af[2][4], bh[2][4];
            #pragma unroll
            for (int mt = 0; mt < 2; mt++){
                uint32_t off = (uint32_t)((a_row + mt*16)*KSTRIDE + k0 + a_col8)*2u;
                ldsm4(af[mt], cA + off);
            }
            #pragma unroll
            for (int p = 0; p < 2; p++){
                uint32_t off = (uint32_t)((b_row + p*16)*KSTRIDE + k0 + b_col8)*2u;
                ldsm4(bh[p], cB + off);
            }
            #pragma unroll
            for (int mt = 0; mt < 2; mt++)
                #pragma unroll
                for (int nt = 0; nt < 4; nt++)
                    mma16816(acc[mt][nt], af[mt], &bh[nt >> 1][(nt & 1)*2]);
        }
        __syncthreads();
    }

    int gg = lane >> 2, tig = lane & 3;
    int wm = warp >> 2, wn = warp & 3;
    #pragma unroll
    for (int mt = 0; mt < 2; mt++)
        #pragma unroll
        for (int half = 0; half < 2; half++){
            int row = m0 + wm*32 + mt*16 + gg + half*8;
            #pragma unroll
            for (int nt = 0; nt < 4; nt++){
                int col = n0 + wn*32 + nt*8 + tig*2;
                float v0 = acc[mt][nt][half*2 + 0] + bias[col];
                float v1 = acc[mt][nt][half*2 + 1] + bias[col + 1];
                size_t o = (size_t)row*N + col;
                float2 rv = *(const float2*)&res[o];
                *(float2*)&Cf[o] = make_float2(v0 + rv.x, v1 + rv.y);
            }
        }
}

// ---------------- fused flash attention: 128-row q tiles ---------------------
__global__ __launch_bounds__(256) void flash_att(
    const __half* __restrict__ qh, const __half* __restrict__ ql,
    const __half* __restrict__ keh, const __half* __restrict__ kvh,
    const float* __restrict__ P, const float* __restrict__ b0t,
    const float* __restrict__ vals, float* __restrict__ V)
{
    extern __shared__ char smem[];
    uint32_t sb = s2u(smem);
    int tid = threadIdx.x, lane = tid & 31, warp = tid >> 5;
    int it = blockIdx.x, bh = blockIdx.y, b = bh >> 3, h = bh & 7;
    int i0 = it*128;
    int NCH = 2*it + 2;

    uint32_t sQH = sb, sQL = sb + QTILE_B;
    uint32_t st0 = sb + 2*QTILE_B;
    uint32_t st1 = st0 + 2*ATILE_B;

    #pragma unroll
    for (int t = 0; t < 2; t++){
        const __half* gp = t ? ql : qh;
        uint32_t tb = t ? sQL : sQH;
        #pragma unroll
        for (int i = 0; i < 4; i++){
            int s = i*256 + tid;
            int r = s >> 3, seg = s & 7;
            cpa16(tb + (uint32_t)(r*ROWB + seg*16),
                  gp + ((size_t)(b*SS + i0 + r))*EE + h*DD + seg*8, 16u);
        }
    }
    #pragma unroll
    for (int t = 0; t < 2; t++){
        const __half* gp = t ? kvh : keh;
        uint32_t tb = st0 + t*ATILE_B;
        #pragma unroll
        for (int i = 0; i < 2; i++){
            int s = i*256 + tid;
            int r = s >> 3, seg = s & 7;
            cpa16(tb + (uint32_t)(r*ROWB + seg*16),
                  gp + ((size_t)(b*SS + r))*EE + h*DD + seg*8, 16u);
        }
    }
    cpcommit();

    int gg = lane >> 2, tig = lane & 3;
    int a_row  = warp*16 + (lane & 15);
    int a_col8 = (lane >> 4)*8;
    int b_rowb = (lane & 7) + ((lane & 16) ? 8 : 0);
    int b_col8 = ((lane & 8) ? 8 : 0);
    int bt_row = lane & 15;
    int bt_colb = ((lane & 16) ? 8 : 0);

    int gi0 = i0 + warp*16 + gg;
    int gi1 = gi0 + 8;
    const float* Pr0 = P + ((size_t)(b*SS + gi0)*HH + h)*RUSE + 100;
    const float* Pr1 = P + ((size_t)(b*SS + gi1)*HH + h)*RUSE + 100;

    float m_st[2] = {-1e30f, -1e30f};
    float l_st[2] = {0.f, 0.f};
    float acc_o[8][4];
    #pragma unroll
    for (int nt = 0; nt < 8; nt++)
        #pragma unroll
        for (int c = 0; c < 4; c++) acc_o[nt][c] = 0.f;

    for (int c = 0; c < NCH; c++){
        uint32_t cur = (c & 1) ? st1 : st0;
        if (c + 1 < NCH){
            uint32_t nxt = (c & 1) ? st0 : st1;
            int j0n = (c + 1)*64;
            #pragma unroll
            for (int t = 0; t < 2; t++){
                const __half* gp = t ? kvh : keh;
                uint32_t tb = nxt + t*ATILE_B;
                #pragma unroll
                for (int i = 0; i < 2; i++){
                    int s = i*256 + tid;
                    int r = s >> 3, seg = s & 7;
                    cpa16(tb + (uint32_t)(r*ROWB + seg*16),
                          gp + ((size_t)(b*SS + j0n + r))*EE + h*DD + seg*8, 16u);
                }
            }
            cpcommit();
        }
        if (c + 1 < NCH) cpwait1(); else cpwait0();
        __syncthreads();

        int j0 = c*64;
        uint32_t cK = cur, cV = cur + ATILE_B;

        float s_acc[8][4];
        #pragma unroll
        for (int nt = 0; nt < 8; nt++)
            #pragma unroll
            for (int e = 0; e < 4; e++) s_acc[nt][e] = 0.f;
        #pragma unroll
        for (int ks = 0; ks < 4; ks++){
            int k0 = ks*16;
            uint32_t aq[4], aql[4], bf[4][4];
            uint32_t offA = (uint32_t)(a_row*KSTRIDE + k0 + a_col8)*2u;
            ldsm4(aq,  sQH + offA);
            ldsm4(aql, sQL + offA);
            #pragma unroll
            for (int p = 0; p < 4; p++){
                uint32_t off = (uint32_t)((p*16 + b_rowb)*KSTRIDE + k0 + b_col8)*2u;
                ldsm4(bf[p], cK + off);
            }
            #pragma unroll
            for (int nt = 0; nt < 8; nt++)
                mma16816(s_acc[nt], aq, &bf[nt >> 1][(nt & 1)*2]);
            #pragma unroll
            for (int nt = 0; nt < 8; nt++)
                mma16816(s_acc[nt], aql, &bf[nt >> 1][(nt & 1)*2]);
        }

        float rowmax[2] = {-1e30f, -1e30f};
        #pragma unroll
        for (int nt = 0; nt < 8; nt++){
            #pragma unroll
            for (int e = 0; e < 2; e++){
                int j = j0 + nt*8 + tig*2 + e;
                float bv = b0t[(size_t)(b*SS + j)*HH + h];
                #pragma unroll
                for (int hh = 0; hh < 2; hh++){
                    int gi = hh ? gi1 : gi0;
                    int ci = hh*2 + e;
                    float val;
                    if (j > gi){
                        val = -1e30f;
                    } else {
                        int off = j - gi;
                        if (off < -100) off = -100;
                        val = s_acc[nt][ci]*0.125f + (hh ? Pr1 : Pr0)[off] + bv;
                    }
                    s_acc[nt][ci] = val;
                    rowmax[hh] = fmaxf(rowmax[hh], val);
                }
            }
        }
        #pragma unroll
        for (int hh = 0; hh < 2; hh++){
            rowmax[hh] = fmaxf(rowmax[hh], __shfl_xor_sync(0xffffffffu, rowmax[hh], 1));
            rowmax[hh] = fmaxf(rowmax[hh], __shfl_xor_sync(0xffffffffu, rowmax[hh], 2));
        }
        float mnew[2], scale[2], rsum[2] = {0.f, 0.f};
        #pragma unroll
        for (int hh = 0; hh < 2; hh++){
            mnew[hh]  = fmaxf(m_st[hh], rowmax[hh]);
            scale[hh] = __expf(m_st[hh] - mnew[hh]);
            m_st[hh]  = mnew[hh];
        }
        #pragma unroll
        for (int nt = 0; nt < 8; nt++)
            #pragma unroll
            for (int ci = 0; ci < 4; ci++){
                int hh = ci >> 1;
                float p = __expf(s_acc[nt][ci] - mnew[hh]);
                s_acc[nt][ci] = p;
                rsum[hh] += p;
            }
        #pragma unroll
        for (int hh = 0; hh < 2; hh++){
            rsum[hh] += __shfl_xor_sync(0xffffffffu, rsum[hh], 1);
            rsum[hh] += __shfl_xor_sync(0xffffffffu, rsum[hh], 2);
            l_st[hh] = l_st[hh]*scale[hh] + rsum[hh];
        }
        #pragma unroll
        for (int nt = 0; nt < 8; nt++)
            #pragma unroll
            for (int ci = 0; ci < 4; ci++)
                acc_o[nt][ci] *= scale[ci >> 1];

        uint32_t pa[4][4], pl[4][4];
        #pragma unroll
        for (int ks2 = 0; ks2 < 4; ks2++){
            #pragma unroll
            for (int half8 = 0; half8 < 2; half8++){
                int nt = ks2*2 + half8;
                __half h0 = __float2half_rn(s_acc[nt][0]);
                __half h1 = __float2half_rn(s_acc[nt][1]);
                __half h2 = __float2half_rn(s_acc[nt][2]);
                __half h3 = __float2half_rn(s_acc[nt][3]);
                pa[ks2][0 + half8*2] = packh(h0, h1);
                pa[ks2][1 + half8*2] = packh(h2, h3);
                __half l0 = __float2half_rn(s_acc[nt][0] - __half2float(h0));
                __half l1 = __float2half_rn(s_acc[nt][1] - __half2float(h1));
                __half l2 = __float2half_rn(s_acc[nt][2] - __half2float(h2));
                __half l3 = __float2half_rn(s_acc[nt][3] - __half2float(h3));
                pl[ks2][0 + half8*2] = packh(l0, l1);
                pl[ks2][1 + half8*2] = packh(l2, l3);
            }
        }

        #pragma unroll
        for (int ks2 = 0; ks2 < 4; ks2++){
            int k0 = ks2*16;
            uint32_t bv[4][4];
            #pragma unroll
            for (int grp = 0; grp < 4; grp++){
                uint32_t off = (uint32_t)((k0 + bt_row)*KSTRIDE + grp*16 + bt_colb)*2u;
                ldsm4t(bv[grp], cV + off);
            }
            #pragma unroll
            for (int nt = 0; nt < 8; nt++)
                mma16816(acc_o[nt], pa[ks2], &bv[nt >> 1][(nt & 1)*2]);
            #pragma unroll
            for (int nt = 0; nt < 8; nt++)
                mma16816(acc_o[nt], pl[ks2], &bv[nt >> 1][(nt & 1)*2]);
        }
        __syncthreads();
    }

    float inv[2] = {1.f / l_st[0], 1.f / l_st[1]};
    #pragma unroll
    for (int hh = 0; hh < 2; hh++){
        int gi = hh ? gi1 : gi0;
        #pragma unroll
        for (int nt = 0; nt < 8; nt++){
            int d = nt*8 + tig*2;
            size_t o = ((size_t)(b*SS + gi))*EE + h*DD + d;
            float2 rv = *(const float2*)&vals[o];
            *(float2*)&V[o] = make_float2(acc_o[nt][hh*2 + 0]*inv[hh] + rv.x,
                                          acc_o[nt][hh*2 + 1]*inv[hh] + rv.y);
        }
    }
}

// ---------------- fused weight conversion ------------------------------------
struct WTab {
    const float* W[7];
    __half* Th[7];
    int K[7];
    int N[7];
    int off[8];
};

__global__ void convWT_all(WTab tab)
{
    __shared__ float t[32][33];
    int bid = blockIdx.x;
    int e = 0;
    #pragma unroll
    for (int i = 1; i < 7; i++) if (bid >= tab.off[i]) e = i;
    int local = bid - tab.off[e];
    const float* W = tab.W[e];
    __half* Th = tab.Th[e];
    int K = tab.K[e], N = tab.N[e];
    int ntiles = N >> 5;
    int kt = local / ntiles, ct = local - kt*ntiles;
    int by = kt*32, bx = ct*32;
    int lx = threadIdx.x & 31, ly = threadIdx.x >> 5;
    #pragma unroll
    for (int i = 0; i < 32; i += 8)
        t[ly + i][lx] = W[(size_t)(by + ly + i)*N + bx + lx];
    __syncthreads();
    #pragma unroll
    for (int i = 0; i < 32; i += 8){
        int n = bx + ly + i, k = by + lx;
        Th[(size_t)n*K + k] = __float2half_rn(t[lx][ly + i]);
    }
}

__global__ void convA(const float* __restrict__ X, __half* __restrict__ H,
                      __half* __restrict__ L, int n)
{
    int i = blockIdx.x*256 + threadIdx.x;
    if (i < n){
        float x = X[i];
        __half h = __float2half_rn(x);
        H[i] = h;
        L[i] = __float2half_rn(x - __half2float(h));
    }
}

// ---------------- LayerNorm -> fp16 hi only ---------------------------------
__global__ void ln_h(const float* __restrict__ X, const float* __restrict__ g,
                     const float* __restrict__ bt, __half* __restrict__ Yh)
{
    int row = blockIdx.x;
    int tid = threadIdx.x;
    const float* x = X + (size_t)row*EE;
    float a = x[tid], c = x[tid + 256];
    float s  = a + c;
    float s2 = a*a + c*c;
    #pragma unroll
    for (int o = 16; o > 0; o >>= 1){
        s  += __shfl_xor_sync(0xffffffffu, s,  o);
        s2 += __shfl_xor_sync(0xffffffffu, s2, o);
    }
    __shared__ float sa[8], sbm[8];
    if ((tid & 31) == 0){ sa[tid>>5] = s; sbm[tid>>5] = s2; }
    __syncthreads();
    float ts = 0.f, ts2 = 0.f;
    #pragma unroll
    for (int w = 0; w < 8; w++){ ts += sa[w]; ts2 += sbm[w]; }
    float mean = ts * (1.f/512.f);
    float var  = ts2 * (1.f/512.f) - mean*mean;
    float r = rsqrtf(var + 1e-3f);
    Yh[(size_t)row*EE + tid]       = __float2half_rn((a - mean)*r*g[tid]       + bt[tid]);
    Yh[(size_t)row*EE + tid + 256] = __float2half_rn((c - mean)*r*g[tid + 256] + bt[tid + 256]);
}

// ---------------- fused dual N=8 projection ----------------------------------
__global__ void proj8_dual(
    const float* __restrict__ X0, const float* __restrict__ W0,
    const float* __restrict__ bp0, float* __restrict__ Y0, int n0,
    const float* __restrict__ X1, const float* __restrict__ W1,
    const float* __restrict__ bp1, float* __restrict__ Y1)
{
    int row = blockIdx.x;
    const float *X, *Wp, *bp;
    float* Y;
    int r;
    if (row < n0){ X = X0; Wp = W0; bp = bp0; Y = Y0; r = row; }
    else         { X = X1; Wp = W1; bp = bp1; Y = Y1; r = row - n0; }
    int tid = threadIdx.x;
    int h = tid & 7, seg = tid >> 3;
    const float* x = X + (size_t)r*EE;
    float s = 0.f;
    #pragma unroll
    for (int k = 0; k < 16; k++){
        int kk = seg*16 + k;
        s += x[kk] * Wp[kk*HH + h];
    }
    __shared__ float sm[256];
    sm[tid] = s;
    __syncthreads();
    if (tid < 8){
        float acc = bp[tid];
        #pragma unroll
        for (int sg = 0; sg < 32; sg++) acc += sm[sg*8 + tid];
        Y[(size_t)r*HH + tid] = acc;
    }
}

// ---------------- P[m,h,r] --------------------------------------------------
__global__ __launch_bounds__(128) void pkernel(
    const float* __restrict__ q, const float* __restrict__ krt,
    const float* __restrict__ t1, float* __restrict__ P)
{
    int h = blockIdx.y;
    int m = blockIdx.x * 128 + threadIdx.x;
    float qr[64];
    const float4* qp = (const float4*)(q + (size_t)m*EE + h*DD);
    #pragma unroll
    for (int t = 0; t < 16; t++){
        float4 v = qp[t];
        qr[t*4+0]=v.x; qr[t*4+1]=v.y; qr[t*4+2]=v.z; qr[t*4+3]=v.w;
    }
    float* Pp = P + ((size_t)m*HH + h)*RUSE;
    const float* kbase = krt + h*DD;
    for (int r = 0; r < RUSE; r++){
        const float4* kp = (const float4*)(kbase + (size_t)r*EE);
        float acc = 0.f;
        #pragma unroll
        for (int t = 0; t < 16; t++){
            float4 k4 = __ldg(&kp[t]);
            acc += qr[t*4+0]*k4.x + qr[t*4+1]*k4.y + qr[t*4+2]*k4.z + qr[t*4+3]*k4.w;
        }
        Pp[r] = acc + t1[r*HH + h];
    }
}

// ---------------- launch ----------------------------------------------------
extern "C" void kernel_launch(void* const* d_in, const int* in_sizes, int n_in,
                              void* d_out, int out_size)
{
    const float* values  = (const float*)d_in[0];
    const float* rel_enc = (const float*)d_in[2];
    const float* ln0_g   = (const float*)d_in[3];
    const float* ln0_b   = (const float*)d_in[4];
    const float* w_b0    = (const float*)d_in[5];
    const float* b_b0    = (const float*)d_in[6];
    const float* wq      = (const float*)d_in[7];
    const float* bq      = (const float*)d_in[8];
    const float* wke     = (const float*)d_in[9];
    const float* bke     = (const float*)d_in[10];
    const float* wkv     = (const float*)d_in[11];
    const float* bkv     = (const float*)d_in[12];
    const float* wkr     = (const float*)d_in[13];
    const float* bkr     = (const float*)d_in[14];
    const float* wab0    = (const float*)d_in[15];
    const float* bab0    = (const float*)d_in[16];
    const float* wab1    = (const float*)d_in[17];
    const float* bab1    = (const float*)d_in[18];
    const float* ln1_g   = (const float*)d_in[19];
    const float* ln1_b   = (const float*)d_in[20];
    const float* w11     = (const float*)d_in[21];
    const float* b11     = (const float*)d_in[22];
    const float* w12     = (const float*)d_in[23];
    const float* b12     = (const float*)d_in[24];
    float* out = (float*)d_out;

    float *p_q,*p_ke,*p_krt,*p_t1,*p_b0t,*p_P,*p_v;
    cudaGetSymbolAddress((void**)&p_q,   g_q);
    cudaGetSymbolAddress((void**)&p_ke,  g_ke);
    cudaGetSymbolAddress((void**)&p_krt, g_krt);
    cudaGetSymbolAddress((void**)&p_t1,  g_t1);
    cudaGetSymbolAddress((void**)&p_b0t, g_b0t);
    cudaGetSymbolAddress((void**)&p_P,   g_P);
    cudaGetSymbolAddress((void**)&p_v,   g_v);

    __half *xnh,*xh,*vnh,*h1h,*reh,*rel;
    __half *qh,*ql,*keh,*kvh;
    __half *wb0h,*wqkvh,*wkrh,*w11h,*w12h;
    cudaGetSymbolAddress((void**)&xnh, g_xnh);
    cudaGetSymbolAddress((void**)&xh,  g_xh);
    cudaGetSymbolAddress((void**)&vnh, g_vnh);
    cudaGetSymbolAddress((void**)&h1h, g_h1h);
    cudaGetSymbolAddress((void**)&reh, g_reh); cudaGetSymbolAddress((void**)&rel, g_rel_);
    cudaGetSymbolAddress((void**)&qh,  g_qh);  cudaGetSymbolAddress((void**)&ql,  g_ql);
    cudaGetSymbolAddress((void**)&keh, g_keh);
    cudaGetSymbolAddress((void**)&kvh, g_kvh);
    cudaGetSymbolAddress((void**)&wb0h, g_wb0h);
    cudaGetSymbolAddress((void**)&wqkvh, g_wqkvh);
    cudaGetSymbolAddress((void**)&wkrh, g_wkrh);
    cudaGetSymbolAddress((void**)&w11h, g_w11h);
    cudaGetSymbolAddress((void**)&w12h, g_w12h);

    cudaFuncSetAttribute((const void*)gemm128<0,2>, cudaFuncAttributeMaxDynamicSharedMemorySize, GSMEM2P);
    cudaFuncSetAttribute((const void*)gemm128<1,1>, cudaFuncAttributeMaxDynamicSharedMemorySize, GSMEM1P);
    cudaFuncSetAttribute(gemm_qkv128, cudaFuncAttributeMaxDynamicSharedMemorySize, GSMEM1P);
    cudaFuncSetAttribute(gemm64_res,  cudaFuncAttributeMaxDynamicSharedMemorySize, GSMEM64);
    cudaFuncSetAttribute(flash_att,   cudaFuncAttributeMaxDynamicSharedMemorySize, FA_SMEM);

    WTab tab;
    tab.W[0]=w_b0; tab.Th[0]=wb0h;              tab.K[0]=EE;   tab.N[0]=HIDD;
    tab.W[1]=wq;   tab.Th[1]=wqkvh;             tab.K[1]=HIDD; tab.N[1]=EE;
    tab.W[2]=wke;  tab.Th[2]=wqkvh + 512*HIDD;  tab.K[2]=HIDD; tab.N[2]=EE;
    tab.W[3]=wkv;  tab.Th[3]=wqkvh + 1024*HIDD; tab.K[3]=HIDD; tab.N[3]=EE;
    tab.W[4]=wkr;  tab.Th[4]=wkrh;              tab.K[4]=EE;   tab.N[4]=EE;
    tab.W[5]=w11;  tab.Th[5]=w11h;              tab.K[5]=EE;   tab.N[5]=HIDD;
    tab.W[6]=w12;  tab.Th[6]=w12h;              tab.K[6]=HIDD; tab.N[6]=EE;
    int total = 0;
    for (int i = 0; i < 7; i++){
        tab.off[i] = total;
        total += (tab.K[i]/32) * (tab.N[i]/32);
    }
    tab.off[7] = total;
    convWT_all<<<total, 256>>>(tab);
    convA<<<(RFULL*EE + 255)/256, 256>>>(rel_enc, reh, rel, RFULL*EE);

    // 1) LN0 -> fp16
    ln_h<<<MR, 256>>>(values, ln0_g, ln0_b, xnh);
    // 2) x = relu(xn @ w_b0 + b_b0)  [128x128, 256 blocks, occ 2]
    gemm128<1,1><<<dim3(HIDD/128, MR/128), 256, GSMEM1P>>>(
        xnh, nullptr, wb0h, b_b0, nullptr, nullptr, xh, MR, HIDD, EE);
    // 3) merged q/ke/kv              [128x128, 192 blocks, occ 2]
    gemm_qkv128<<<dim3(12, MR/128), 256, GSMEM1P>>>(
        xh, wqkvh, bq, bke, bkv, p_q, p_ke, qh, ql, keh, kvh, MR, HIDD);
    // 4) kr_table (2-pass)
    gemm128<0,2><<<dim3(EE/128, 2), 256, GSMEM2P>>>(
        reh, rel, wkrh, bkr, nullptr, p_krt, nullptr, RFULL, EE, EE);
    // 5) bias0 + t1 (fused)
    proj8_dual<<<MR + RFULL, 256>>>(p_ke, wab0, bab0, p_b0t, MR,
                                    p_krt, wab1, bab1, p_t1);
    // 6) P
    pkernel<<<dim3(MR/128, HH), 128>>>(p_q, p_krt, p_t1, p_P);
    // 7) fused flash attention -> v
    flash_att<<<dim3(4, BB*HH), 256, FA_SMEM>>>(
        qh, ql, keh, kvh, p_P, p_b0t, values, p_v);
    // 8) LN1 -> fp16
    ln_h<<<MR, 256>>>(p_v, ln1_g, ln1_b, vnh);
    // 9) h1 = relu(vn @ w11 + b11)   [128x128, 256 blocks]
    gemm128<1,1><<<dim3(HIDD/128, MR/128), 256, GSMEM1P>>>(
        vnh, nullptr, w11h, b11, nullptr, nullptr, h1h, MR, HIDD, EE);
    // 10) out = v + h1 @ w12 + b12   [64x128, 128 blocks]
    gemm64_res<<<dim3(EE/128, MR/64), 256, GSMEM64>>>(
        h1h, w12h, b12, p_v, out, MR, EE, HIDD);
}